// round 7
// baseline (speedup 1.0000x reference)
#include <cuda_runtime.h>
#include <stdint.h>
#include <math.h>

#define B_ 2
#define S_ 2048
#define E_ 1024
#define H_ 16
#define D_ 64
#define BH_ (B_*H_)

__device__ float g_Q[(size_t)BH_ * S_ * D_];
__device__ float g_K[(size_t)BH_ * S_ * D_];
__device__ float g_V[(size_t)BH_ * S_ * D_];
__device__ float g_C[(size_t)BH_ * S_ * D_];

// ---------------- tf32 helpers ----------------
__device__ __forceinline__ uint32_t f2tf(float x) {
    uint32_t r;
    asm("cvt.rna.tf32.f32 %0, %1;" : "=r"(r) : "f"(x));
    return r;
}
__device__ __forceinline__ void split_tf(float x, uint32_t& hi, uint32_t& lo) {
    hi = f2tf(x);
    lo = f2tf(x - __uint_as_float(hi));
}
__device__ __forceinline__ void mma8(float* c,
                                     uint32_t a0, uint32_t a1, uint32_t a2, uint32_t a3,
                                     uint32_t b0, uint32_t b1) {
    asm volatile(
        "mma.sync.aligned.m16n8k8.row.col.f32.tf32.tf32.f32 "
        "{%0,%1,%2,%3}, {%4,%5,%6,%7}, {%8,%9}, {%0,%1,%2,%3};\n"
        : "+f"(c[0]), "+f"(c[1]), "+f"(c[2]), "+f"(c[3])
        : "r"(a0), "r"(a1), "r"(a2), "r"(a3), "r"(b0), "r"(b1));
}

// fast exp on FMA pipe; args <= 0
__device__ __forceinline__ float fast_exp(float x) {
    float t = x * 1.44269504089f;
    t = fmaxf(t, -100.0f);
    float rm = t + 12582912.0f;
    int ib = __float_as_int(rm) - 0x4B400000;
    float f = t - (rm - 12582912.0f);
    float p = 0.0013333558f;
    p = fmaf(p, f, 0.0096181291f);
    p = fmaf(p, f, 0.0555041087f);
    p = fmaf(p, f, 0.2402265069f);
    p = fmaf(p, f, 0.6931471806f);
    p = fmaf(p, f, 1.0f);
    return __int_as_float(__float_as_int(p) + (ib << 23));
}

// ---------------------------------------------------------------------------
// tf32 GEMM: C[128 x 64-tile] = A[128 x 1024] * W[1024 x 64-tile] + bias
// PASSES=3: split hi/lo (hh + lh + hl). PASSES=1: plain tf32.
// MODE 0/1/2: projection -> writes g_Q / g_K / g_V (device globals resolved
//             IN DEVICE CODE — cannot be passed from host).
// MODE 3:     output projection — gathers A from g_C, writes Out (= d_out).
// 256 thr, 8 warps (4m x 2n, warp m32 x n32). K-chunk 32, double-buffered.
// SMEM: A 64KB @0 ; B 32KB @65536. Total 96KB -> 2 CTAs/SM.
// ---------------------------------------------------------------------------
#define GEMM_SMEM 98304

template<int PASSES, int MODE>
__global__ __launch_bounds__(256) void gemm_tf(
    const float* __restrict__ X, const float* __restrict__ W,
    const float* __restrict__ bias, float* __restrict__ Out)
{
    extern __shared__ char smc[];
    uint2* As2 = (uint2*)smc;
    uint2* Bs2 = (uint2*)(smc + 65536);
    const uint4* As4 = (const uint4*)smc;
    const uint4* Bs4 = (const uint4*)(smc + 65536);

    const int tid = threadIdx.x;
    const int lane = tid & 31;
    const int warp = tid >> 5;
    const int g = lane >> 2;
    const int tg = lane & 3;
    const int wm = (warp >> 1) * 32;
    const int wn = (warp & 1) * 32;

    const float* Arow = nullptr;
    const float* Wt;
    const float* bi;
    float* Ot;
    int wld, outld, bcta = 0, sbase = 0;

    if (MODE == 3) {
        int m0 = blockIdx.x * 128;
        int n0 = blockIdx.y * 64;
        bcta = m0 >> 11;            // batch (2048 rows per batch)
        sbase = m0 & (S_ - 1);
        Wt = W + n0;  wld = E_;
        bi = bias + n0;
        Ot = Out + (size_t)m0 * E_ + n0;  outld = E_;
    } else {
        float* G = (MODE == 0) ? g_Q : (MODE == 1) ? g_K : g_V;   // device-side
        int bh = blockIdx.y;
        int b = bh >> 4, h = bh & 15;
        int s0 = blockIdx.x * 128;
        Arow = X + ((size_t)b * S_ + s0) * E_;
        Wt = W + (size_t)h * E_ * D_;  wld = D_;
        bi = bias + h * D_;
        Ot = G + ((size_t)bh * S_ + s0) * D_;  outld = D_;
    }

    float acc[2][4][4];
#pragma unroll
    for (int mf = 0; mf < 2; mf++)
#pragma unroll
        for (int nf = 0; nf < 4; nf++)
#pragma unroll
            for (int c = 0; c < 4; c++) acc[mf][nf][c] = 0.f;

    float4 ar[4], br[2];

    auto ldg = [&](int k0) {
#pragma unroll
        for (int it = 0; it < 4; it++) {
            int slot = tid + it * 256;
            int row = slot >> 3;
            int c4 = (slot & 7) * 4;
            if (MODE == 3) {
                int e = k0 + c4;
                int h = e >> 6, dd = e & 63;
                ar[it] = *(const float4*)(g_C +
                    (((size_t)(bcta * H_ + h) * S_ + sbase + row) * D_ + dd));
            } else {
                ar[it] = *(const float4*)(Arow + (size_t)row * E_ + k0 + c4);
            }
        }
#pragma unroll
        for (int it = 0; it < 2; it++) {
            int slot = tid + it * 256;
            int kr = slot >> 4;
            int c4 = (slot & 15) * 4;
            br[it] = *(const float4*)(Wt + (size_t)(k0 + kr) * wld + c4);
        }
    };
    auto sts = [&](int buf) {
        const int b4 = buf * 4;
#pragma unroll
        for (int it = 0; it < 4; it++) {
            int slot = tid + it * 256;
            int row = slot >> 3;
            int c4 = (slot & 7) * 4;
            const float* fe = (const float*)&ar[it];
#pragma unroll
            for (int j = 0; j < 4; j++) {
                int c = c4 + j;
                int k8 = c >> 3, w = (c >> 2) & 1, jj = c & 3;
                uint32_t hi, lo;
                if (PASSES == 3) split_tf(fe[j], hi, lo);
                else { hi = f2tf(fe[j]); lo = 0u; }
                As2[(((b4 + k8) << 7) + row) * 8 + jj * 2 + w] = make_uint2(hi, lo);
            }
        }
#pragma unroll
        for (int it = 0; it < 2; it++) {
            int slot = tid + it * 256;
            int kr = slot >> 4;
            int c4 = (slot & 15) * 4;
            int k8 = kr >> 3, w = (kr >> 2) & 1, jj = kr & 3;
            const float* fe = (const float*)&br[it];
#pragma unroll
            for (int j = 0; j < 4; j++) {
                uint32_t hi, lo;
                if (PASSES == 3) split_tf(fe[j], hi, lo);
                else { hi = f2tf(fe[j]); lo = 0u; }
                Bs2[(((b4 + k8) << 6) + (c4 + j)) * 8 + jj * 2 + w] = make_uint2(hi, lo);
            }
        }
    };

    ldg(0);
    sts(0);
    __syncthreads();

    for (int ch = 0; ch < 32; ch++) {
        const int buf = ch & 1;
        if (ch < 31) ldg((ch + 1) * 32);

#pragma unroll
        for (int k8 = 0; k8 < 4; k8++) {
            const int ab = ((buf * 4 + k8) << 7);
            const int bb = ((buf * 4 + k8) << 6);
            uint4 A0 = As4[(ab + wm + g) * 4 + tg];
            uint4 A1 = As4[(ab + wm + g + 8) * 4 + tg];
            uint4 A2 = As4[(ab + wm + 16 + g) * 4 + tg];
            uint4 A3 = As4[(ab + wm + 16 + g + 8) * 4 + tg];
            uint4 Bv[4];
#pragma unroll
            for (int nf = 0; nf < 4; nf++)
                Bv[nf] = Bs4[(bb + wn + nf * 8 + g) * 4 + tg];
#pragma unroll
            for (int nf = 0; nf < 4; nf++) {
                mma8(acc[0][nf], A0.x, A1.x, A0.z, A1.z, Bv[nf].x, Bv[nf].z);
                mma8(acc[1][nf], A2.x, A3.x, A2.z, A3.z, Bv[nf].x, Bv[nf].z);
                if (PASSES == 3) {
                    mma8(acc[0][nf], A0.y, A1.y, A0.w, A1.w, Bv[nf].x, Bv[nf].z);
                    mma8(acc[1][nf], A2.y, A3.y, A2.w, A3.w, Bv[nf].x, Bv[nf].z);
                    mma8(acc[0][nf], A0.x, A1.x, A0.z, A1.z, Bv[nf].y, Bv[nf].w);
                    mma8(acc[1][nf], A2.x, A3.x, A2.z, A3.z, Bv[nf].y, Bv[nf].w);
                }
            }
        }
        if (ch < 31) sts(buf ^ 1);
        __syncthreads();
    }

    // epilogue: + bias
#pragma unroll
    for (int mf = 0; mf < 2; mf++) {
#pragma unroll
        for (int nf = 0; nf < 4; nf++) {
            int col = wn + nf * 8 + 2 * tg;
            float bx = bi[col], by = bi[col + 1];
            int r0 = wm + mf * 16 + g;
            *(float2*)(Ot + (size_t)r0 * outld + col) =
                make_float2(acc[mf][nf][0] + bx, acc[mf][nf][1] + by);
            *(float2*)(Ot + (size_t)(r0 + 8) * outld + col) =
                make_float2(acc[mf][nf][2] + bx, acc[mf][nf][3] + by);
        }
    }
}

// ---------------------------------------------------------------------------
// Flash attention: tf32x3 QK + tf32x1 PV on mma.sync (unchanged, round 5).
// ---------------------------------------------------------------------------
#define ATT_SMEM 147456
#define KOFF 65536
#define VOFF 98304
#define POFF 114688

__global__ __launch_bounds__(256) void attn_kernel()
{
    extern __shared__ char smc[];
    uint32_t* Qw = (uint32_t*)smc;
    uint32_t* Kw = (uint32_t*)(smc + KOFF);
    uint32_t* Vw = (uint32_t*)(smc + VOFF);
    uint32_t* Pw = (uint32_t*)(smc + POFF);
    const uint4* Qu = (const uint4*)smc;
    const uint4* Ku = (const uint4*)(smc + KOFF);
    const uint2* Vu = (const uint2*)(smc + VOFF);
    const uint2* Pu = (const uint2*)(smc + POFF);

    const int tid = threadIdx.x;
    const int lane = tid & 31;
    const int warp = tid >> 5;
    const int g = lane >> 2;
    const int tg = lane & 3;
    const int rbase = warp * 16;
    const int bh = blockIdx.y;
    const int q0 = blockIdx.x * 128;

    const float* Qg = g_Q + ((size_t)bh * S_ + q0) * D_;
    const float* Kg = g_K + (size_t)bh * S_ * D_;
    const float* Vg = g_V + (size_t)bh * S_ * D_;

#pragma unroll
    for (int it = 0; it < 8; it++) {
        int slot = tid + it * 256;
        int row = slot >> 4;
        int c4 = (slot & 15) * 4;
        float4 f = *(const float4*)(Qg + (size_t)row * D_ + c4);
        const float* fe = (const float*)&f;
#pragma unroll
        for (int j = 0; j < 4; j++) {
            int c = c4 + j;
            int k8 = c >> 3, w = (c >> 2) & 1, jj = c & 3;
            uint32_t hi, lo;
            split_tf(fe[j] * 0.125f, hi, lo);
            int idx = ((((k8 << 7) + row) * 4 + jj) << 2) + w;
            Qw[idx] = hi; Qw[idx + 2] = lo;
        }
    }

    float m0 = -1e30f, m1 = -1e30f, l0 = 0.f, l1 = 0.f;
    float oacc[8][4];
#pragma unroll
    for (int nf = 0; nf < 8; nf++)
#pragma unroll
        for (int c = 0; c < 4; c++) oacc[nf][c] = 0.f;

    float4 kf[4], vf[4];
#pragma unroll
    for (int it = 0; it < 4; it++) {
        int slot = tid + it * 256;
        int row = slot >> 4;
        int c4 = (slot & 15) * 4;
        kf[it] = *(const float4*)(Kg + (size_t)row * D_ + c4);
        vf[it] = *(const float4*)(Vg + (size_t)row * D_ + c4);
    }

    for (int kb = 0; kb < 32; kb++) {
#pragma unroll
        for (int it = 0; it < 4; it++) {
            int slot = tid + it * 256;
            int row = slot >> 4;
            int c4 = (slot & 15) * 4;
            const float* ke = (const float*)&kf[it];
            const float* ve = (const float*)&vf[it];
#pragma unroll
            for (int j = 0; j < 4; j++) {
                int c = c4 + j;
                int k8 = c >> 3, w = (c >> 2) & 1, jj = c & 3;
                uint32_t hi, lo;
                split_tf(ke[j], hi, lo);
                int idx = ((((k8 << 6) + row) * 4 + jj) << 2) + w;
                Kw[idx] = hi; Kw[idx + 2] = lo;
            }
            {
                int kk8 = row >> 3, vtg = row & 3, half = (row >> 2) & 1;
#pragma unroll
                for (int j = 0; j < 4; j++) {
                    int d = c4 + j;
                    int idx = ((((kk8 << 6) + d) * 4 + vtg) << 1) + half;
                    Vw[idx] = f2tf(ve[j]);
                }
            }
        }
        __syncthreads();

        if (kb < 31) {
#pragma unroll
            for (int it = 0; it < 4; it++) {
                int slot = tid + it * 256;
                int row = slot >> 4;
                int c4 = (slot & 15) * 4;
                kf[it] = *(const float4*)(Kg + ((size_t)(kb + 1) * 64 + row) * D_ + c4);
                vf[it] = *(const float4*)(Vg + ((size_t)(kb + 1) * 64 + row) * D_ + c4);
            }
        }

        float sacc[8][4];
#pragma unroll
        for (int nf = 0; nf < 8; nf++)
#pragma unroll
            for (int c = 0; c < 4; c++) sacc[nf][c] = 0.f;

#pragma unroll 2
        for (int k8 = 0; k8 < 8; k8++) {
            uint4 A0 = Qu[((k8 << 7) + rbase + g) * 4 + tg];
            uint4 A1 = Qu[((k8 << 7) + rbase + g + 8) * 4 + tg];
#pragma unroll
            for (int nf = 0; nf < 8; nf++) {
                uint4 Bv = Ku[((k8 << 6) + nf * 8 + g) * 4 + tg];
                mma8(sacc[nf], A0.x, A1.x, A0.y, A1.y, Bv.x, Bv.y);
                mma8(sacc[nf], A0.z, A1.z, A0.w, A1.w, Bv.x, Bv.y);
                mma8(sacc[nf], A0.x, A1.x, A0.y, A1.y, Bv.z, Bv.w);
            }
        }

        float mx0 = -1e30f, mx1 = -1e30f;
#pragma unroll
        for (int nf = 0; nf < 8; nf++) {
            mx0 = fmaxf(mx0, fmaxf(sacc[nf][0], sacc[nf][1]));
            mx1 = fmaxf(mx1, fmaxf(sacc[nf][2], sacc[nf][3]));
        }
        mx0 = fmaxf(mx0, __shfl_xor_sync(0xffffffffu, mx0, 1));
        mx0 = fmaxf(mx0, __shfl_xor_sync(0xffffffffu, mx0, 2));
        mx1 = fmaxf(mx1, __shfl_xor_sync(0xffffffffu, mx1, 1));
        mx1 = fmaxf(mx1, __shfl_xor_sync(0xffffffffu, mx1, 2));
        float mn0 = fmaxf(m0, mx0), mn1 = fmaxf(m1, mx1);
        float corr0 = fast_exp(m0 - mn0), corr1 = fast_exp(m1 - mn1);
        m0 = mn0; m1 = mn1;

        const int rA = rbase + g, rB = rA + 8;
        float sum0 = 0.f, sum1 = 0.f;
#pragma unroll
        for (int nf = 0; nf < 8; nf++) {
            float p0 = fast_exp(sacc[nf][0] - mn0);
            float p1 = fast_exp(sacc[nf][1] - mn0);
            float p2 = fast_exp(sacc[nf][2] - mn1);
            float p3 = fast_exp(sacc[nf][3] - mn1);
            sum0 += p0 + p1; sum1 += p2 + p3;
            int cA = 2 * tg, cB = 2 * tg + 1;
            int iA0 = ((((nf << 7) + rA) * 4 + (cA & 3)) << 1) + (cA >> 2);
            int iB0 = ((((nf << 7) + rA) * 4 + (cB & 3)) << 1) + (cB >> 2);
            int iA1 = ((((nf << 7) + rB) * 4 + (cA & 3)) << 1) + (cA >> 2);
            int iB1 = ((((nf << 7) + rB) * 4 + (cB & 3)) << 1) + (cB >> 2);
            Pw[iA0] = f2tf(p0); Pw[iB0] = f2tf(p1);
            Pw[iA1] = f2tf(p2); Pw[iB1] = f2tf(p3);
            oacc[nf][0] *= corr0; oacc[nf][1] *= corr0;
            oacc[nf][2] *= corr1; oacc[nf][3] *= corr1;
        }
        sum0 += __shfl_xor_sync(0xffffffffu, sum0, 1);
        sum0 += __shfl_xor_sync(0xffffffffu, sum0, 2);
        sum1 += __shfl_xor_sync(0xffffffffu, sum1, 1);
        sum1 += __shfl_xor_sync(0xffffffffu, sum1, 2);
        l0 = l0 * corr0 + sum0;
        l1 = l1 * corr1 + sum1;

        __syncwarp();

#pragma unroll 2
        for (int kk8 = 0; kk8 < 8; kk8++) {
            uint2 P0 = Pu[((kk8 << 7) + rbase + g) * 4 + tg];
            uint2 P1 = Pu[((kk8 << 7) + rbase + g + 8) * 4 + tg];
#pragma unroll
            for (int nf = 0; nf < 8; nf++) {
                uint2 Bv = Vu[((kk8 << 6) + nf * 8 + g) * 4 + tg];
                mma8(oacc[nf], P0.x, P1.x, P0.y, P1.y, Bv.x, Bv.y);
            }
        }
        __syncthreads();
    }

    float inv0 = 1.f / l0, inv1 = 1.f / l1;
    float* Cg = g_C + ((size_t)bh * S_ + q0) * D_;
    const int rA = rbase + g, rB = rA + 8;
#pragma unroll
    for (int nf = 0; nf < 8; nf++) {
        int col = nf * 8 + 2 * tg;
        *(float2*)(Cg + (size_t)rA * D_ + col) =
            make_float2(oacc[nf][0] * inv0, oacc[nf][1] * inv0);
        *(float2*)(Cg + (size_t)rB * D_ + col) =
            make_float2(oacc[nf][2] * inv1, oacc[nf][3] * inv1);
    }
}

// ---------------------------------------------------------------------------
extern "C" void kernel_launch(void* const* d_in, const int* in_sizes, int n_in,
                              void* d_out, int out_size)
{
    const float* q  = (const float*)d_in[0];
    const float* k  = (const float*)d_in[1];
    const float* v  = (const float*)d_in[2];
    const float* Wq = (const float*)d_in[3];
    const float* Wk = (const float*)d_in[4];
    const float* Wv = (const float*)d_in[5];
    const float* bq = (const float*)d_in[6];
    const float* bk = (const float*)d_in[7];
    const float* bv = (const float*)d_in[8];
    const float* Wo = (const float*)d_in[9];
    const float* bo = (const float*)d_in[10];
    float* out = (float*)d_out;

    cudaFuncSetAttribute(gemm_tf<3, 0>, cudaFuncAttributeMaxDynamicSharedMemorySize, GEMM_SMEM);
    cudaFuncSetAttribute(gemm_tf<3, 1>, cudaFuncAttributeMaxDynamicSharedMemorySize, GEMM_SMEM);
    cudaFuncSetAttribute(gemm_tf<1, 2>, cudaFuncAttributeMaxDynamicSharedMemorySize, GEMM_SMEM);
    cudaFuncSetAttribute(gemm_tf<1, 3>, cudaFuncAttributeMaxDynamicSharedMemorySize, GEMM_SMEM);
    cudaFuncSetAttribute(attn_kernel, cudaFuncAttributeMaxDynamicSharedMemorySize, ATT_SMEM);

    gemm_tf<3, 0><<<dim3(S_ / 128, BH_), 256, GEMM_SMEM>>>(q, Wq, bq, nullptr);
    gemm_tf<3, 1><<<dim3(S_ / 128, BH_), 256, GEMM_SMEM>>>(k, Wk, bk, nullptr);
    gemm_tf<1, 2><<<dim3(S_ / 128, BH_), 256, GEMM_SMEM>>>(v, Wv, bv, nullptr);
    attn_kernel<<<dim3(S_ / 128, BH_), 256, ATT_SMEM>>>();
    gemm_tf<1, 3><<<dim3((B_ * S_) / 128, E_ / 64), 256, GEMM_SMEM>>>(nullptr, Wo, bo, out);
}

// round 8
// speedup vs baseline: 1.1761x; 1.1761x over previous
#include <cuda_runtime.h>
#include <stdint.h>
#include <math.h>

#define B_ 2
#define S_ 2048
#define E_ 1024
#define H_ 16
#define D_ 64
#define BH_ (B_*H_)

__device__ float g_Q[(size_t)BH_ * S_ * D_];
__device__ float g_K[(size_t)BH_ * S_ * D_];
__device__ float g_V[(size_t)BH_ * S_ * D_];
__device__ float g_C[(size_t)BH_ * S_ * D_];

// ---------------- tf32 helpers ----------------
__device__ __forceinline__ uint32_t f2tf(float x) {
    uint32_t r;
    asm("cvt.rna.tf32.f32 %0, %1;" : "=r"(r) : "f"(x));
    return r;
}
__device__ __forceinline__ void split_tf(float x, uint32_t& hi, uint32_t& lo) {
    hi = f2tf(x);
    lo = f2tf(x - __uint_as_float(hi));
}
__device__ __forceinline__ void mma8(float* c,
                                     uint32_t a0, uint32_t a1, uint32_t a2, uint32_t a3,
                                     uint32_t b0, uint32_t b1) {
    asm volatile(
        "mma.sync.aligned.m16n8k8.row.col.f32.tf32.tf32.f32 "
        "{%0,%1,%2,%3}, {%4,%5,%6,%7}, {%8,%9}, {%0,%1,%2,%3};\n"
        : "+f"(c[0]), "+f"(c[1]), "+f"(c[2]), "+f"(c[3])
        : "r"(a0), "r"(a1), "r"(a2), "r"(a3), "r"(b0), "r"(b1));
}

// fast exp on FMA pipe; args <= 0
__device__ __forceinline__ float fast_exp(float x) {
    float t = x * 1.44269504089f;
    t = fmaxf(t, -100.0f);
    float rm = t + 12582912.0f;
    int ib = __float_as_int(rm) - 0x4B400000;
    float f = t - (rm - 12582912.0f);
    float p = 0.0013333558f;
    p = fmaf(p, f, 0.0096181291f);
    p = fmaf(p, f, 0.0555041087f);
    p = fmaf(p, f, 0.2402265069f);
    p = fmaf(p, f, 0.6931471806f);
    p = fmaf(p, f, 1.0f);
    return __int_as_float(__float_as_int(p) + (ib << 23));
}

// ---------------------------------------------------------------------------
// QKV projection (FFMA — round-5 known good: 592us for all three)
// ---------------------------------------------------------------------------
__global__ __launch_bounds__(256) void proj_kernel(
    const float* __restrict__ q, const float* __restrict__ k, const float* __restrict__ v,
    const float* __restrict__ Wq, const float* __restrict__ Wk, const float* __restrict__ Wv,
    const float* __restrict__ bq, const float* __restrict__ bk, const float* __restrict__ bv)
{
    __shared__ float As[16][132];
    __shared__ float Bs[16][64];

    const int z = blockIdx.z;
    const float* X    = (z == 0) ? q  : (z == 1) ? k  : v;
    const float* W    = (z == 0) ? Wq : (z == 1) ? Wk : Wv;
    const float* bias = (z == 0) ? bq : (z == 1) ? bk : bv;
    float* Out        = (z == 0) ? g_Q : (z == 1) ? g_K : g_V;

    const int bh = blockIdx.y;
    const int b = bh >> 4;
    const int h = bh & 15;
    const int s0 = blockIdx.x * 128;
    const int tid = threadIdx.x;
    const int ng = tid & 15;
    const int mg = tid >> 4;

    const float* Xb = X + ((size_t)b * S_ + s0) * E_;
    const float* Wh = W + (size_t)h * E_ * D_;

    float acc[8][4];
#pragma unroll
    for (int i = 0; i < 8; i++)
#pragma unroll
        for (int j = 0; j < 4; j++) acc[i][j] = 0.f;

    for (int k0 = 0; k0 < E_; k0 += 16) {
#pragma unroll
        for (int it = 0; it < 2; it++) {
            int i = tid + it * 256;
            int row = i >> 2;
            int c4 = (i & 3) * 4;
            float4 f = *(const float4*)(Xb + (size_t)row * E_ + k0 + c4);
            As[c4 + 0][row] = f.x; As[c4 + 1][row] = f.y;
            As[c4 + 2][row] = f.z; As[c4 + 3][row] = f.w;
        }
        {
            int r = tid >> 4, c4 = (tid & 15) * 4;
            *(float4*)&Bs[r][c4] = *(const float4*)(Wh + (size_t)(k0 + r) * D_ + c4);
        }
        __syncthreads();
#pragma unroll
        for (int kk = 0; kk < 16; kk++) {
            float4 a0 = *(float4*)&As[kk][mg * 8];
            float4 a1 = *(float4*)&As[kk][mg * 8 + 4];
            float4 b4 = *(float4*)&Bs[kk][ng * 4];
            float a[8] = {a0.x, a0.y, a0.z, a0.w, a1.x, a1.y, a1.z, a1.w};
            float bb[4] = {b4.x, b4.y, b4.z, b4.w};
#pragma unroll
            for (int i = 0; i < 8; i++)
#pragma unroll
                for (int j = 0; j < 4; j++) acc[i][j] += a[i] * bb[j];
        }
        __syncthreads();
    }

    float4 bias4 = *(const float4*)(bias + h * D_ + ng * 4);
    float* Ob = Out + ((size_t)bh * S_ + s0 + mg * 8) * D_ + ng * 4;
#pragma unroll
    for (int i = 0; i < 8; i++) {
        float4 r;
        r.x = acc[i][0] + bias4.x; r.y = acc[i][1] + bias4.y;
        r.z = acc[i][2] + bias4.z; r.w = acc[i][3] + bias4.w;
        *(float4*)(Ob + (size_t)i * D_) = r;
    }
}

// ---------------------------------------------------------------------------
// Flash attention: tf32x3 QK + tf32x1 PV, BM=64, 128 thr / 4 warps,
// 96KB smem -> 2 CTAs/SM (softmax of one CTA overlaps MMA of the other).
// SMEM: Qw 32KB @0 | Kw 32KB @32768 | Vw 16KB @65536 | Pw 16KB @81920.
// grid = (S/64, BH)
// ---------------------------------------------------------------------------
#define ATT_SMEM 98304
#define A_KOFF 32768
#define A_VOFF 65536
#define A_POFF 81920

__global__ __launch_bounds__(128) void attn_kernel()
{
    extern __shared__ char smc[];
    uint32_t* Qw = (uint32_t*)smc;
    uint32_t* Kw = (uint32_t*)(smc + A_KOFF);
    uint32_t* Vw = (uint32_t*)(smc + A_VOFF);
    uint32_t* Pw = (uint32_t*)(smc + A_POFF);
    const uint4* Qu = (const uint4*)smc;
    const uint4* Ku = (const uint4*)(smc + A_KOFF);
    const uint2* Vu = (const uint2*)(smc + A_VOFF);
    const uint2* Pu = (const uint2*)(smc + A_POFF);

    const int tid = threadIdx.x;
    const int lane = tid & 31;
    const int warp = tid >> 5;
    const int g = lane >> 2;
    const int tg = lane & 3;
    const int rbase = warp * 16;          // 4 warps cover 64 q-rows
    const int bh = blockIdx.y;
    const int q0 = blockIdx.x * 64;

    const float* Qg = g_Q + ((size_t)bh * S_ + q0) * D_;
    const float* Kg = g_K + (size_t)bh * S_ * D_;
    const float* Vg = g_V + (size_t)bh * S_ * D_;

    // ---- Q load + scale + split (once): 64 rows x 16 float4 = 1024 slots ----
#pragma unroll
    for (int it = 0; it < 8; it++) {
        int slot = tid + it * 128;
        int row = slot >> 4;
        int c4 = (slot & 15) * 4;
        float4 f = *(const float4*)(Qg + (size_t)row * D_ + c4);
        const float* fe = (const float*)&f;
#pragma unroll
        for (int j = 0; j < 4; j++) {
            int c = c4 + j;
            int k8 = c >> 3, w = (c >> 2) & 1, jj = c & 3;
            uint32_t hi, lo;
            split_tf(fe[j] * 0.125f, hi, lo);
            int idx = ((((k8 << 6) + row) * 4 + jj) << 2) + w;
            Qw[idx] = hi; Qw[idx + 2] = lo;
        }
    }

    float m0 = -1e30f, m1 = -1e30f, l0 = 0.f, l1 = 0.f;
    float oacc[8][4];
#pragma unroll
    for (int nf = 0; nf < 8; nf++)
#pragma unroll
        for (int c = 0; c < 4; c++) oacc[nf][c] = 0.f;

    for (int kb = 0; kb < 32; kb++) {
        // ---- K (split hi/lo) + V (single tf32) tile: 1024 slots ----
#pragma unroll
        for (int it = 0; it < 8; it++) {
            int slot = tid + it * 128;
            int row = slot >> 4;            // key 0..63
            int c4 = (slot & 15) * 4;
            float4 kf = *(const float4*)(Kg + ((size_t)kb * 64 + row) * D_ + c4);
            float4 vf = *(const float4*)(Vg + ((size_t)kb * 64 + row) * D_ + c4);
            const float* ke = (const float*)&kf;
            const float* ve = (const float*)&vf;
#pragma unroll
            for (int j = 0; j < 4; j++) {
                int c = c4 + j;
                int k8 = c >> 3, w = (c >> 2) & 1, jj = c & 3;
                uint32_t hi, lo;
                split_tf(ke[j], hi, lo);
                int idx = ((((k8 << 6) + row) * 4 + jj) << 2) + w;
                Kw[idx] = hi; Kw[idx + 2] = lo;
            }
            {
                int kk8 = row >> 3, vtg = row & 3, half = (row >> 2) & 1;
#pragma unroll
                for (int j = 0; j < 4; j++) {
                    int d = c4 + j;
                    int idx = ((((kk8 << 6) + d) * 4 + vtg) << 1) + half;
                    Vw[idx] = f2tf(ve[j]);
                }
            }
        }
        __syncthreads();

        // ---- S = (Q/8) K^T  (3-pass tf32) ----
        float sacc[8][4];
#pragma unroll
        for (int nf = 0; nf < 8; nf++)
#pragma unroll
            for (int c = 0; c < 4; c++) sacc[nf][c] = 0.f;

#pragma unroll 2
        for (int k8 = 0; k8 < 8; k8++) {
            uint4 A0 = Qu[((k8 << 6) + rbase + g) * 4 + tg];
            uint4 A1 = Qu[((k8 << 6) + rbase + g + 8) * 4 + tg];
#pragma unroll
            for (int nf = 0; nf < 8; nf++) {
                uint4 Bv = Ku[((k8 << 6) + nf * 8 + g) * 4 + tg];
                mma8(sacc[nf], A0.x, A1.x, A0.y, A1.y, Bv.x, Bv.y);
                mma8(sacc[nf], A0.z, A1.z, A0.w, A1.w, Bv.x, Bv.y);
                mma8(sacc[nf], A0.x, A1.x, A0.y, A1.y, Bv.z, Bv.w);
            }
        }

        // ---- online softmax (rows rbase+g and rbase+g+8) ----
        float mx0 = -1e30f, mx1 = -1e30f;
#pragma unroll
        for (int nf = 0; nf < 8; nf++) {
            mx0 = fmaxf(mx0, fmaxf(sacc[nf][0], sacc[nf][1]));
            mx1 = fmaxf(mx1, fmaxf(sacc[nf][2], sacc[nf][3]));
        }
        mx0 = fmaxf(mx0, __shfl_xor_sync(0xffffffffu, mx0, 1));
        mx0 = fmaxf(mx0, __shfl_xor_sync(0xffffffffu, mx0, 2));
        mx1 = fmaxf(mx1, __shfl_xor_sync(0xffffffffu, mx1, 1));
        mx1 = fmaxf(mx1, __shfl_xor_sync(0xffffffffu, mx1, 2));
        float mn0 = fmaxf(m0, mx0), mn1 = fmaxf(m1, mx1);
        float corr0 = fast_exp(m0 - mn0), corr1 = fast_exp(m1 - mn1);
        m0 = mn0; m1 = mn1;

        const int rA = rbase + g, rB = rA + 8;
        float sum0 = 0.f, sum1 = 0.f;
#pragma unroll
        for (int nf = 0; nf < 8; nf++) {
            float p0 = fast_exp(sacc[nf][0] - mn0);
            float p1 = fast_exp(sacc[nf][1] - mn0);
            float p2 = fast_exp(sacc[nf][2] - mn1);
            float p3 = fast_exp(sacc[nf][3] - mn1);
            sum0 += p0 + p1; sum1 += p2 + p3;
            int cA = 2 * tg, cB = 2 * tg + 1;
            int iA0 = ((((nf << 6) + rA) * 4 + (cA & 3)) << 1) + (cA >> 2);
            int iB0 = ((((nf << 6) + rA) * 4 + (cB & 3)) << 1) + (cB >> 2);
            int iA1 = ((((nf << 6) + rB) * 4 + (cA & 3)) << 1) + (cA >> 2);
            int iB1 = ((((nf << 6) + rB) * 4 + (cB & 3)) << 1) + (cB >> 2);
            Pw[iA0] = f2tf(p0); Pw[iB0] = f2tf(p1);
            Pw[iA1] = f2tf(p2); Pw[iB1] = f2tf(p3);
            oacc[nf][0] *= corr0; oacc[nf][1] *= corr0;
            oacc[nf][2] *= corr1; oacc[nf][3] *= corr1;
        }
        sum0 += __shfl_xor_sync(0xffffffffu, sum0, 1);
        sum0 += __shfl_xor_sync(0xffffffffu, sum0, 2);
        sum1 += __shfl_xor_sync(0xffffffffu, sum1, 1);
        sum1 += __shfl_xor_sync(0xffffffffu, sum1, 2);
        l0 = l0 * corr0 + sum0;
        l1 = l1 * corr1 + sum1;

        __syncwarp();   // P stripe is private to this warp

        // ---- O += P V  (1-pass tf32) ----
#pragma unroll 2
        for (int kk8 = 0; kk8 < 8; kk8++) {
            uint2 P0 = Pu[((kk8 << 6) + rbase + g) * 4 + tg];
            uint2 P1 = Pu[((kk8 << 6) + rbase + g + 8) * 4 + tg];
#pragma unroll
            for (int nf = 0; nf < 8; nf++) {
                uint2 Bv = Vu[((kk8 << 6) + nf * 8 + g) * 4 + tg];
                mma8(oacc[nf], P0.x, P1.x, P0.y, P1.y, Bv.x, Bv.y);
            }
        }
        __syncthreads();    // WAR on Kw/Vw before next iteration's stores
    }

    // ---- epilogue ----
    float inv0 = 1.f / l0, inv1 = 1.f / l1;
    float* Cg = g_C + ((size_t)bh * S_ + q0) * D_;
    const int rA = rbase + g, rB = rA + 8;
#pragma unroll
    for (int nf = 0; nf < 8; nf++) {
        int col = nf * 8 + 2 * tg;
        *(float2*)(Cg + (size_t)rA * D_ + col) =
            make_float2(oacc[nf][0] * inv0, oacc[nf][1] * inv0);
        *(float2*)(Cg + (size_t)rB * D_ + col) =
            make_float2(oacc[nf][2] * inv1, oacc[nf][3] * inv1);
    }
}

// ---------------------------------------------------------------------------
// Output projection (FFMA — round-5 known good: ~170us)
// ---------------------------------------------------------------------------
__global__ __launch_bounds__(256) void oproj_kernel(
    const float* __restrict__ Wo, const float* __restrict__ bo, float* __restrict__ out)
{
    __shared__ float As[16][132];
    __shared__ float Bs[16][64];

    const int m0 = blockIdx.x * 128;
    const int n0 = blockIdx.y * 64;
    const int tid = threadIdx.x;
    const int ng = tid & 15;
    const int mg = tid >> 4;
    const int b = m0 >> 11;
    const int sbase = m0 & (S_ - 1);

    float acc[8][4];
#pragma unroll
    for (int i = 0; i < 8; i++)
#pragma unroll
        for (int j = 0; j < 4; j++) acc[i][j] = 0.f;

    for (int k0 = 0; k0 < E_; k0 += 16) {
#pragma unroll
        for (int it = 0; it < 2; it++) {
            int i = tid + it * 256;
            int row = i >> 2;
            int c4 = (i & 3) * 4;
            int e = k0 + c4;
            int h = e >> 6;
            int dd = e & 63;
            float4 f = *(const float4*)(g_C +
                (((size_t)(b * H_ + h) * S_ + sbase + row) * D_ + dd));
            As[c4 + 0][row] = f.x; As[c4 + 1][row] = f.y;
            As[c4 + 2][row] = f.z; As[c4 + 3][row] = f.w;
        }
        {
            int r = tid >> 4, c4 = (tid & 15) * 4;
            *(float4*)&Bs[r][c4] = *(const float4*)(Wo + (size_t)(k0 + r) * E_ + n0 + c4);
        }
        __syncthreads();
#pragma unroll
        for (int kk = 0; kk < 16; kk++) {
            float4 a0 = *(float4*)&As[kk][mg * 8];
            float4 a1 = *(float4*)&As[kk][mg * 8 + 4];
            float4 b4 = *(float4*)&Bs[kk][ng * 4];
            float a[8] = {a0.x, a0.y, a0.z, a0.w, a1.x, a1.y, a1.z, a1.w};
            float bb[4] = {b4.x, b4.y, b4.z, b4.w};
#pragma unroll
            for (int i = 0; i < 8; i++)
#pragma unroll
                for (int j = 0; j < 4; j++) acc[i][j] += a[i] * bb[j];
        }
        __syncthreads();
    }

    float4 b4 = *(const float4*)(bo + n0 + ng * 4);
#pragma unroll
    for (int i = 0; i < 8; i++) {
        size_t row = (size_t)m0 + mg * 8 + i;
        float4 r;
        r.x = acc[i][0] + b4.x; r.y = acc[i][1] + b4.y;
        r.z = acc[i][2] + b4.z; r.w = acc[i][3] + b4.w;
        *(float4*)(out + row * E_ + n0 + ng * 4) = r;
    }
}

// ---------------------------------------------------------------------------
extern "C" void kernel_launch(void* const* d_in, const int* in_sizes, int n_in,
                              void* d_out, int out_size)
{
    const float* q  = (const float*)d_in[0];
    const float* k  = (const float*)d_in[1];
    const float* v  = (const float*)d_in[2];
    const float* Wq = (const float*)d_in[3];
    const float* Wk = (const float*)d_in[4];
    const float* Wv = (const float*)d_in[5];
    const float* bq = (const float*)d_in[6];
    const float* bk = (const float*)d_in[7];
    const float* bv = (const float*)d_in[8];
    const float* Wo = (const float*)d_in[9];
    const float* bo = (const float*)d_in[10];
    float* out = (float*)d_out;

    cudaFuncSetAttribute(attn_kernel, cudaFuncAttributeMaxDynamicSharedMemorySize, ATT_SMEM);

    proj_kernel<<<dim3(S_ / 128, BH_, 3), 256>>>(q, k, v, Wq, Wk, Wv, bq, bk, bv);
    attn_kernel<<<dim3(S_ / 64, BH_), 128, ATT_SMEM>>>();
    oproj_kernel<<<dim3((B_ * S_) / 128, E_ / 64), 256>>>(Wo, bo, out);
}

// round 9
// speedup vs baseline: 1.6637x; 1.4146x over previous
#include <cuda_runtime.h>
#include <cuda_fp16.h>
#include <stdint.h>
#include <math.h>

#define B_ 2
#define S_ 2048
#define E_ 1024
#define H_ 16
#define D_ 64
#define BH_ (B_*H_)

__device__ float g_Q[(size_t)BH_ * S_ * D_];
__device__ float g_K[(size_t)BH_ * S_ * D_];
__device__ float g_V[(size_t)BH_ * S_ * D_];
__device__ float g_C[(size_t)BH_ * S_ * D_];

// ---------------- f16 split helpers ----------------
__device__ __forceinline__ void split2h(float x0, float x1, uint32_t& hi, uint32_t& lo) {
    __half h0 = __float2half_rn(x0), h1 = __float2half_rn(x1);
    float r0 = x0 - __half2float(h0), r1 = x1 - __half2float(h1);
    __half l0 = __float2half_rn(r0), l1 = __float2half_rn(r1);
    hi = (uint32_t)__half_as_ushort(h0) | ((uint32_t)__half_as_ushort(h1) << 16);
    lo = (uint32_t)__half_as_ushort(l0) | ((uint32_t)__half_as_ushort(l1) << 16);
}
__device__ __forceinline__ uint16_t hbits(float x) {
    __half h = __float2half_rn(x);
    return __half_as_ushort(h);
}
// m16n8k16 f16 MMA, fp32 accum
__device__ __forceinline__ void mma16(float* c,
                                      uint32_t a0, uint32_t a1, uint32_t a2, uint32_t a3,
                                      uint32_t b0, uint32_t b1) {
    asm volatile(
        "mma.sync.aligned.m16n8k16.row.col.f32.f16.f16.f32 "
        "{%0,%1,%2,%3}, {%4,%5,%6,%7}, {%8,%9}, {%0,%1,%2,%3};\n"
        : "+f"(c[0]), "+f"(c[1]), "+f"(c[2]), "+f"(c[3])
        : "r"(a0), "r"(a1), "r"(a2), "r"(a3), "r"(b0), "r"(b1));
}

// fast exp on FMA pipe; args <= 0
__device__ __forceinline__ float fast_exp(float x) {
    float t = x * 1.44269504089f;
    t = fmaxf(t, -100.0f);
    float rm = t + 12582912.0f;
    int ib = __float_as_int(rm) - 0x4B400000;
    float f = t - (rm - 12582912.0f);
    float p = 0.0013333558f;
    p = fmaf(p, f, 0.0096181291f);
    p = fmaf(p, f, 0.0555041087f);
    p = fmaf(p, f, 0.2402265069f);
    p = fmaf(p, f, 0.6931471806f);
    p = fmaf(p, f, 1.0f);
    return __int_as_float(__float_as_int(p) + (ib << 23));
}

// ---------------------------------------------------------------------------
// QKV projection (FFMA — known good)
// ---------------------------------------------------------------------------
__global__ __launch_bounds__(256) void proj_kernel(
    const float* __restrict__ q, const float* __restrict__ k, const float* __restrict__ v,
    const float* __restrict__ Wq, const float* __restrict__ Wk, const float* __restrict__ Wv,
    const float* __restrict__ bq, const float* __restrict__ bk, const float* __restrict__ bv)
{
    __shared__ float As[16][132];
    __shared__ float Bs[16][64];

    const int z = blockIdx.z;
    const float* X    = (z == 0) ? q  : (z == 1) ? k  : v;
    const float* W    = (z == 0) ? Wq : (z == 1) ? Wk : Wv;
    const float* bias = (z == 0) ? bq : (z == 1) ? bk : bv;
    float* Out        = (z == 0) ? g_Q : (z == 1) ? g_K : g_V;

    const int bh = blockIdx.y;
    const int b = bh >> 4;
    const int h = bh & 15;
    const int s0 = blockIdx.x * 128;
    const int tid = threadIdx.x;
    const int ng = tid & 15;
    const int mg = tid >> 4;

    const float* Xb = X + ((size_t)b * S_ + s0) * E_;
    const float* Wh = W + (size_t)h * E_ * D_;

    float acc[8][4];
#pragma unroll
    for (int i = 0; i < 8; i++)
#pragma unroll
        for (int j = 0; j < 4; j++) acc[i][j] = 0.f;

    for (int k0 = 0; k0 < E_; k0 += 16) {
#pragma unroll
        for (int it = 0; it < 2; it++) {
            int i = tid + it * 256;
            int row = i >> 2;
            int c4 = (i & 3) * 4;
            float4 f = *(const float4*)(Xb + (size_t)row * E_ + k0 + c4);
            As[c4 + 0][row] = f.x; As[c4 + 1][row] = f.y;
            As[c4 + 2][row] = f.z; As[c4 + 3][row] = f.w;
        }
        {
            int r = tid >> 4, c4 = (tid & 15) * 4;
            *(float4*)&Bs[r][c4] = *(const float4*)(Wh + (size_t)(k0 + r) * D_ + c4);
        }
        __syncthreads();
#pragma unroll
        for (int kk = 0; kk < 16; kk++) {
            float4 a0 = *(float4*)&As[kk][mg * 8];
            float4 a1 = *(float4*)&As[kk][mg * 8 + 4];
            float4 b4 = *(float4*)&Bs[kk][ng * 4];
            float a[8] = {a0.x, a0.y, a0.z, a0.w, a1.x, a1.y, a1.z, a1.w};
            float bb[4] = {b4.x, b4.y, b4.z, b4.w};
#pragma unroll
            for (int i = 0; i < 8; i++)
#pragma unroll
                for (int j = 0; j < 4; j++) acc[i][j] += a[i] * bb[j];
        }
        __syncthreads();
    }

    float4 bias4 = *(const float4*)(bias + h * D_ + ng * 4);
    float* Ob = Out + ((size_t)bh * S_ + s0 + mg * 8) * D_ + ng * 4;
#pragma unroll
    for (int i = 0; i < 8; i++) {
        float4 r;
        r.x = acc[i][0] + bias4.x; r.y = acc[i][1] + bias4.y;
        r.z = acc[i][2] + bias4.z; r.w = acc[i][3] + bias4.w;
        *(float4*)(Ob + (size_t)i * D_) = r;
    }
}

// ---------------------------------------------------------------------------
// Flash attention: f16x3 QK + f16x2 PV on mma.sync.m16n8k16.
// BM=128, BN=64, 256 thr / 8 warps (warp = m16 x n64 stripe).
// SMEM 88KB: Q 32K @0 | K 16K @32768 | V 8K @49152 | P 32K @57344
//   Q/K: uint4 {hiPair(tg), hiPair(tg+4), loPair(tg), loPair(tg+4)} per
//        (k16-chunk, row, tg); pair = f16x2 of cols (chunk*16 + 2p, +1).
//   V  : uint2 {hiPair(tg), hiPair(tg+4)} per (keychunk, d, tg)  [V^T]
//   P  : uint2 {hiPair, loPair} per (keychunk, row, pidx 0..7)
// 2 CTAs/SM (regs capped via launch_bounds). grid = (S/128, BH)
// ---------------------------------------------------------------------------
#define ATT_SMEM 90112
#define F_KOFF 32768
#define F_VOFF 49152
#define F_POFF 57344

__global__ __launch_bounds__(256, 2) void attn_kernel()
{
    extern __shared__ char smc[];
    uint32_t* Qw = (uint32_t*)smc;
    uint32_t* Kw = (uint32_t*)(smc + F_KOFF);
    uint16_t* Vw = (uint16_t*)(smc + F_VOFF);
    uint2*    Pw = (uint2*)(smc + F_POFF);
    const uint4* Qu = (const uint4*)smc;
    const uint4* Ku = (const uint4*)(smc + F_KOFF);
    const uint2* Vu = (const uint2*)(smc + F_VOFF);
    const uint2* Pu = (const uint2*)(smc + F_POFF);

    const int tid = threadIdx.x;
    const int lane = tid & 31;
    const int warp = tid >> 5;
    const int g = lane >> 2;
    const int tg = lane & 3;
    const int rbase = warp * 16;
    const int bh = blockIdx.y;
    const int q0 = blockIdx.x * 128;

    const float* Qg = g_Q + ((size_t)bh * S_ + q0) * D_;
    const float* Kg = g_K + (size_t)bh * S_ * D_;
    const float* Vg = g_V + (size_t)bh * S_ * D_;

    // ---- Q load + scale(1/8) + split (once): 2048 float4 slots ----
#pragma unroll
    for (int it = 0; it < 8; it++) {
        int slot = tid + it * 256;
        int row = slot >> 4;
        int c4 = (slot & 15) * 4;
        float4 f = *(const float4*)(Qg + (size_t)row * D_ + c4);
        uint32_t hi01, lo01, hi23, lo23;
        split2h(f.x * 0.125f, f.y * 0.125f, hi01, lo01);
        split2h(f.z * 0.125f, f.w * 0.125f, hi23, lo23);
        int cc = c4 >> 4;
        int p0 = (c4 >> 1) & 7;           // even
        uint32_t* base = Qw + (((cc << 7) + row) << 4);
        int i0 = ((p0 & 3) << 2) + (p0 >> 2);
        int p1 = p0 + 1;
        int i1 = ((p1 & 3) << 2) + (p1 >> 2);
        base[i0] = hi01; base[i0 + 2] = lo01;
        base[i1] = hi23; base[i1 + 2] = lo23;
    }

    float m0 = -1e30f, m1 = -1e30f, l0 = 0.f, l1 = 0.f;
    float oacc[8][4];
#pragma unroll
    for (int nf = 0; nf < 8; nf++)
#pragma unroll
        for (int c = 0; c < 4; c++) oacc[nf][c] = 0.f;

    const int rA = rbase + g, rB = rA + 8;

    for (int kb = 0; kb < 32; kb++) {
        // ---- K split(hi/lo) + V(f16) tile: 1024 float4 slots ----
#pragma unroll
        for (int it = 0; it < 4; it++) {
            int slot = tid + it * 256;
            int key = slot >> 4;
            int c4 = (slot & 15) * 4;
            float4 kf = *(const float4*)(Kg + ((size_t)kb * 64 + key) * D_ + c4);
            float4 vf = *(const float4*)(Vg + ((size_t)kb * 64 + key) * D_ + c4);
            {
                uint32_t hi01, lo01, hi23, lo23;
                split2h(kf.x, kf.y, hi01, lo01);
                split2h(kf.z, kf.w, hi23, lo23);
                int cc = c4 >> 4;
                int p0 = (c4 >> 1) & 7;
                uint32_t* base = Kw + (((cc << 6) + key) << 4);
                int i0 = ((p0 & 3) << 2) + (p0 >> 2);
                int p1 = p0 + 1;
                int i1 = ((p1 & 3) << 2) + (p1 >> 2);
                base[i0] = hi01; base[i0 + 2] = lo01;
                base[i1] = hi23; base[i1 + 2] = lo23;
            }
            {
                int cc = key >> 4;
                int p = (key & 15) >> 1;
                int w = key & 1;
                int sl = p & 3, hf = p >> 2;
                const float* ve = (const float*)&vf;
#pragma unroll
                for (int j = 0; j < 4; j++) {
                    int d = c4 + j;
                    int uidx = (((cc << 6) + d) << 2) + sl;   // uint2 index
                    Vw[uidx * 4 + hf * 2 + w] = hbits(ve[j]);
                }
            }
        }
        __syncthreads();

        // ---- S = (Q/8) K^T  (f16 3-pass, k16 chunks) ----
        float sacc[8][4];
#pragma unroll
        for (int nf = 0; nf < 8; nf++)
#pragma unroll
            for (int c = 0; c < 4; c++) sacc[nf][c] = 0.f;

#pragma unroll 2
        for (int cc = 0; cc < 4; cc++) {
            uint4 qa = Qu[(((cc << 7) + rA) << 2) + tg];
            uint4 qb = Qu[(((cc << 7) + rB) << 2) + tg];
#pragma unroll
            for (int nf = 0; nf < 8; nf++) {
                uint4 kv = Ku[(((cc << 6) + nf * 8 + g) << 2) + tg];
                mma16(sacc[nf], qa.x, qb.x, qa.y, qb.y, kv.x, kv.y);   // hh
                mma16(sacc[nf], qa.z, qb.z, qa.w, qb.w, kv.x, kv.y);   // lh
                mma16(sacc[nf], qa.x, qb.x, qa.y, qb.y, kv.z, kv.w);   // hl
            }
        }

        // ---- online softmax (rows rA and rB) ----
        float mx0 = -1e30f, mx1 = -1e30f;
#pragma unroll
        for (int nf = 0; nf < 8; nf++) {
            mx0 = fmaxf(mx0, fmaxf(sacc[nf][0], sacc[nf][1]));
            mx1 = fmaxf(mx1, fmaxf(sacc[nf][2], sacc[nf][3]));
        }
        mx0 = fmaxf(mx0, __shfl_xor_sync(0xffffffffu, mx0, 1));
        mx0 = fmaxf(mx0, __shfl_xor_sync(0xffffffffu, mx0, 2));
        mx1 = fmaxf(mx1, __shfl_xor_sync(0xffffffffu, mx1, 1));
        mx1 = fmaxf(mx1, __shfl_xor_sync(0xffffffffu, mx1, 2));
        float mn0 = fmaxf(m0, mx0), mn1 = fmaxf(m1, mx1);
        float corr0 = fast_exp(m0 - mn0), corr1 = fast_exp(m1 - mn1);
        m0 = mn0; m1 = mn1;

        float sum0 = 0.f, sum1 = 0.f;
#pragma unroll
        for (int nf = 0; nf < 8; nf++) {
            float p0 = fast_exp(sacc[nf][0] - mn0);
            float p1 = fast_exp(sacc[nf][1] - mn0);
            float p2 = fast_exp(sacc[nf][2] - mn1);
            float p3 = fast_exp(sacc[nf][3] - mn1);
            sum0 += p0 + p1; sum1 += p2 + p3;
            uint32_t hiA, loA, hiB, loB;
            split2h(p0, p1, hiA, loA);
            split2h(p2, p3, hiB, loB);
            int ccp = nf >> 1;
            int pidx = ((nf & 1) << 2) + tg;
            Pw[(((ccp << 7) + rA) << 3) + pidx] = make_uint2(hiA, loA);
            Pw[(((ccp << 7) + rB) << 3) + pidx] = make_uint2(hiB, loB);
            oacc[nf][0] *= corr0; oacc[nf][1] *= corr0;
            oacc[nf][2] *= corr1; oacc[nf][3] *= corr1;
        }
        sum0 += __shfl_xor_sync(0xffffffffu, sum0, 1);
        sum0 += __shfl_xor_sync(0xffffffffu, sum0, 2);
        sum1 += __shfl_xor_sync(0xffffffffu, sum1, 1);
        sum1 += __shfl_xor_sync(0xffffffffu, sum1, 2);
        l0 = l0 * corr0 + sum0;
        l1 = l1 * corr1 + sum1;

        __syncwarp();   // P stripe is private to this warp

        // ---- O += P V  (f16 2-pass: P hi + P lo, V hi) ----
#pragma unroll 2
        for (int cc = 0; cc < 4; cc++) {
            uint2 pA  = Pu[(((cc << 7) + rA) << 3) + tg];
            uint2 pA4 = Pu[(((cc << 7) + rA) << 3) + tg + 4];
            uint2 pB  = Pu[(((cc << 7) + rB) << 3) + tg];
            uint2 pB4 = Pu[(((cc << 7) + rB) << 3) + tg + 4];
#pragma unroll
            for (int nf = 0; nf < 8; nf++) {
                uint2 vv = Vu[(((cc << 6) + nf * 8 + g) << 2) + tg];
                mma16(oacc[nf], pA.x, pB.x, pA4.x, pB4.x, vv.x, vv.y);
                mma16(oacc[nf], pA.y, pB.y, pA4.y, pB4.y, vv.x, vv.y);
            }
        }
        __syncthreads();    // WAR on Kw/Vw before next iteration's stores
    }

    // ---- epilogue ----
    float inv0 = 1.f / l0, inv1 = 1.f / l1;
    float* Cg = g_C + ((size_t)bh * S_ + q0) * D_;
#pragma unroll
    for (int nf = 0; nf < 8; nf++) {
        int col = nf * 8 + 2 * tg;
        *(float2*)(Cg + (size_t)rA * D_ + col) =
            make_float2(oacc[nf][0] * inv0, oacc[nf][1] * inv0);
        *(float2*)(Cg + (size_t)rB * D_ + col) =
            make_float2(oacc[nf][2] * inv1, oacc[nf][3] * inv1);
    }
}

// ---------------------------------------------------------------------------
// Output projection (FFMA — known good)
// ---------------------------------------------------------------------------
__global__ __launch_bounds__(256) void oproj_kernel(
    const float* __restrict__ Wo, const float* __restrict__ bo, float* __restrict__ out)
{
    __shared__ float As[16][132];
    __shared__ float Bs[16][64];

    const int m0 = blockIdx.x * 128;
    const int n0 = blockIdx.y * 64;
    const int tid = threadIdx.x;
    const int ng = tid & 15;
    const int mg = tid >> 4;
    const int b = m0 >> 11;
    const int sbase = m0 & (S_ - 1);

    float acc[8][4];
#pragma unroll
    for (int i = 0; i < 8; i++)
#pragma unroll
        for (int j = 0; j < 4; j++) acc[i][j] = 0.f;

    for (int k0 = 0; k0 < E_; k0 += 16) {
#pragma unroll
        for (int it = 0; it < 2; it++) {
            int i = tid + it * 256;
            int row = i >> 2;
            int c4 = (i & 3) * 4;
            int e = k0 + c4;
            int h = e >> 6;
            int dd = e & 63;
            float4 f = *(const float4*)(g_C +
                (((size_t)(b * H_ + h) * S_ + sbase + row) * D_ + dd));
            As[c4 + 0][row] = f.x; As[c4 + 1][row] = f.y;
            As[c4 + 2][row] = f.z; As[c4 + 3][row] = f.w;
        }
        {
            int r = tid >> 4, c4 = (tid & 15) * 4;
            *(float4*)&Bs[r][c4] = *(const float4*)(Wo + (size_t)(k0 + r) * E_ + n0 + c4);
        }
        __syncthreads();
#pragma unroll
        for (int kk = 0; kk < 16; kk++) {
            float4 a0 = *(float4*)&As[kk][mg * 8];
            float4 a1 = *(float4*)&As[kk][mg * 8 + 4];
            float4 b4 = *(float4*)&Bs[kk][ng * 4];
            float a[8] = {a0.x, a0.y, a0.z, a0.w, a1.x, a1.y, a1.z, a1.w};
            float bb[4] = {b4.x, b4.y, b4.z, b4.w};
#pragma unroll
            for (int i = 0; i < 8; i++)
#pragma unroll
                for (int j = 0; j < 4; j++) acc[i][j] += a[i] * bb[j];
        }
        __syncthreads();
    }

    float4 b4 = *(const float4*)(bo + n0 + ng * 4);
#pragma unroll
    for (int i = 0; i < 8; i++) {
        size_t row = (size_t)m0 + mg * 8 + i;
        float4 r;
        r.x = acc[i][0] + b4.x; r.y = acc[i][1] + b4.y;
        r.z = acc[i][2] + b4.z; r.w = acc[i][3] + b4.w;
        *(float4*)(out + row * E_ + n0 + ng * 4) = r;
    }
}

// ---------------------------------------------------------------------------
extern "C" void kernel_launch(void* const* d_in, const int* in_sizes, int n_in,
                              void* d_out, int out_size)
{
    const float* q  = (const float*)d_in[0];
    const float* k  = (const float*)d_in[1];
    const float* v  = (const float*)d_in[2];
    const float* Wq = (const float*)d_in[3];
    const float* Wk = (const float*)d_in[4];
    const float* Wv = (const float*)d_in[5];
    const float* bq = (const float*)d_in[6];
    const float* bk = (const float*)d_in[7];
    const float* bv = (const float*)d_in[8];
    const float* Wo = (const float*)d_in[9];
    const float* bo = (const float*)d_in[10];
    float* out = (float*)d_out;

    cudaFuncSetAttribute(attn_kernel, cudaFuncAttributeMaxDynamicSharedMemorySize, ATT_SMEM);

    proj_kernel<<<dim3(S_ / 128, BH_, 3), 256>>>(q, k, v, Wq, Wk, Wv, bq, bk, bv);
    attn_kernel<<<dim3(S_ / 128, BH_), 256, ATT_SMEM>>>();
    oproj_kernel<<<dim3((B_ * S_) / 128, E_ / 64), 256>>>(Wo, bo, out);
}

// round 10
// speedup vs baseline: 2.1940x; 1.3188x over previous
#include <cuda_runtime.h>
#include <cuda_fp16.h>
#include <stdint.h>
#include <math.h>

#define B_ 2
#define S_ 2048
#define E_ 1024
#define H_ 16
#define D_ 64
#define BH_ (B_*H_)

__device__ float g_Q[(size_t)BH_ * S_ * D_];
__device__ float g_K[(size_t)BH_ * S_ * D_];
__device__ float g_V[(size_t)BH_ * S_ * D_];
__device__ float g_C[(size_t)BH_ * S_ * D_];

// Pre-split operand images (interleaved f16 hi/lo, MMA smem layout):
// gXs[z][b][cc=64][s=2048][4xuint4]   (pairs along e within k16-chunk cc)
// gWs[z][h][cc=64][d=64][4xuint4]     (W transposed: pairs along e)
__device__ uint4 gXs[3u * 2 * 64 * 2048 * 4];
__device__ uint4 gWs[3u * 16 * 64 * 64 * 4];

// ---------------- f16 helpers ----------------
__device__ __forceinline__ void split2h(float x0, float x1, uint32_t& hi, uint32_t& lo) {
    __half h0 = __float2half_rn(x0), h1 = __float2half_rn(x1);
    float r0 = x0 - __half2float(h0), r1 = x1 - __half2float(h1);
    __half l0 = __float2half_rn(r0), l1 = __float2half_rn(r1);
    hi = (uint32_t)__half_as_ushort(h0) | ((uint32_t)__half_as_ushort(h1) << 16);
    lo = (uint32_t)__half_as_ushort(l0) | ((uint32_t)__half_as_ushort(l1) << 16);
}
__device__ __forceinline__ uint16_t hbits(float x) {
    __half h = __float2half_rn(x);
    return __half_as_ushort(h);
}
__device__ __forceinline__ void mma16(float* c,
                                      uint32_t a0, uint32_t a1, uint32_t a2, uint32_t a3,
                                      uint32_t b0, uint32_t b1) {
    asm volatile(
        "mma.sync.aligned.m16n8k16.row.col.f32.f16.f16.f32 "
        "{%0,%1,%2,%3}, {%4,%5,%6,%7}, {%8,%9}, {%0,%1,%2,%3};\n"
        : "+f"(c[0]), "+f"(c[1]), "+f"(c[2]), "+f"(c[3])
        : "r"(a0), "r"(a1), "r"(a2), "r"(a3), "r"(b0), "r"(b1));
}

// fast exp on FMA pipe; args <= 0
__device__ __forceinline__ float fast_exp(float x) {
    float t = x * 1.44269504089f;
    t = fmaxf(t, -100.0f);
    float rm = t + 12582912.0f;
    int ib = __float_as_int(rm) - 0x4B400000;
    float f = t - (rm - 12582912.0f);
    float p = 0.0013333558f;
    p = fmaf(p, f, 0.0096181291f);
    p = fmaf(p, f, 0.0555041087f);
    p = fmaf(p, f, 0.2402265069f);
    p = fmaf(p, f, 0.6931471806f);
    p = fmaf(p, f, 1.0f);
    return __int_as_float(__float_as_int(p) + (ib << 23));
}

// ---------------------------------------------------------------------------
// Pre-split X (q,k,v) into gXs. uint4 t: j=t&3, s=(t>>2)&2047, cc=(t>>13)&63,
// b=(t>>19)&1, z=t>>20. uint4 j = {hiPair p=j, hiPair p=j+4, loPair j, loPair j+4}
// pair p -> e-cols (16cc+2p, 16cc+2p+1).
// ---------------------------------------------------------------------------
__global__ __launch_bounds__(256) void splitX_kernel(
    const float* __restrict__ q, const float* __restrict__ k, const float* __restrict__ v)
{
    uint32_t t = blockIdx.x * 256 + threadIdx.x;
    int j = t & 3;
    int s = (t >> 2) & 2047;
    int cc = (t >> 13) & 63;
    int b = (t >> 19) & 1;
    int z = t >> 20;
    const float* X = (z == 0) ? q : (z == 1) ? k : v;
    const float* row = X + ((size_t)b * S_ + s) * E_ + cc * 16;
    float x0 = row[2 * j], x1 = row[2 * j + 1];
    float x2 = row[8 + 2 * j], x3 = row[8 + 2 * j + 1];
    uint32_t hiA, loA, hiB, loB;
    split2h(x0, x1, hiA, loA);
    split2h(x2, x3, hiB, loB);
    gXs[t] = make_uint4(hiA, hiB, loA, loB);
}

// ---------------------------------------------------------------------------
// Pre-split + transpose W (Wq,Wk,Wv [h][e][d]) into gWs.
// uint4 t: j=t&3, d=(t>>2)&63, cc=(t>>8)&63, h=(t>>14)&15, z=t>>18.
// ---------------------------------------------------------------------------
__global__ __launch_bounds__(256) void splitW_kernel(
    const float* __restrict__ Wq, const float* __restrict__ Wk, const float* __restrict__ Wv)
{
    uint32_t t = blockIdx.x * 256 + threadIdx.x;
    int j = t & 3;
    int d = (t >> 2) & 63;
    int cc = (t >> 8) & 63;
    int h = (t >> 14) & 15;
    int z = t >> 18;
    const float* W = (z == 0) ? Wq : (z == 1) ? Wk : Wv;
    const float* Wh = W + (size_t)h * E_ * D_;
    int e0 = cc * 16;
    float x0 = Wh[(size_t)(e0 + 2 * j) * D_ + d];
    float x1 = Wh[(size_t)(e0 + 2 * j + 1) * D_ + d];
    float x2 = Wh[(size_t)(e0 + 8 + 2 * j) * D_ + d];
    float x3 = Wh[(size_t)(e0 + 8 + 2 * j + 1) * D_ + d];
    uint32_t hiA, loA, hiB, loB;
    split2h(x0, x1, hiA, loA);
    split2h(x2, x3, hiB, loB);
    gWs[t] = make_uint4(hiA, hiB, loA, loB);
}

// ---------------------------------------------------------------------------
// f16 projection GEMM: Out[bh,s,d] = X[b,s,:]*W[h,:,d] + bias.
// PASSES=3: hh+lh+hl; PASSES=2: hh+lh. Operands pre-split (pure copy loaders).
// Tile 128x64, K32 chunks double-buffered, 8 warps m32 x n32, 48KB smem.
// grid = (S/128, BH). MODE selects g_Q/g_K/g_V (device-side).
// ---------------------------------------------------------------------------
#define PROJ_SMEM 49152

template<int PASSES, int MODE>
__global__ __launch_bounds__(256, 2) void proj_f16(
    const float* __restrict__ bias)
{
    extern __shared__ char smc[];
    uint4* Ab = (uint4*)smc;                    // [2][2][128][4]
    uint4* Bb = (uint4*)(smc + 32768);          // [2][2][64][4]

    const int tid = threadIdx.x;
    const int lane = tid & 31;
    const int warp = tid >> 5;
    const int g = lane >> 2;
    const int tg = lane & 3;
    const int wm = (warp >> 1) * 32;
    const int wn = (warp & 1) * 32;

    const int bh = blockIdx.y;
    const int b = bh >> 4;
    const int h = bh & 15;
    const int s0 = blockIdx.x * 128;

    const uint4* Xs = gXs + (((size_t)MODE * 2 + b) * 64) * 2048 * 4;
    const uint4* Ws = gWs + (((size_t)MODE * 16 + h) * 64) * 64 * 4;

    float acc[2][4][4];
#pragma unroll
    for (int mf = 0; mf < 2; mf++)
#pragma unroll
        for (int nf = 0; nf < 4; nf++)
#pragma unroll
            for (int c = 0; c < 4; c++) acc[mf][nf][c] = 0.f;

    uint4 ar[4], br[2];
    auto ldg = [&](int kc) {
        int cc0 = kc * 2;
#pragma unroll
        for (int it = 0; it < 4; it++) {
            int slot = tid + it * 256;          // 0..1023
            int cc = slot >> 9;
            int row = (slot >> 2) & 127;
            int j = slot & 3;
            ar[it] = Xs[(((size_t)(cc0 + cc) * 2048) + s0 + row) * 4 + j];
        }
#pragma unroll
        for (int it = 0; it < 2; it++) {
            int slot = tid + it * 256;          // 0..511
            int cc = slot >> 8;
            int d = (slot >> 2) & 63;
            int j = slot & 3;
            br[it] = Ws[(((size_t)(cc0 + cc) * 64) + d) * 4 + j];
        }
    };
    auto sts = [&](int buf) {
#pragma unroll
        for (int it = 0; it < 4; it++) {
            int slot = tid + it * 256;
            Ab[buf * 1024 + slot] = ar[it];
        }
#pragma unroll
        for (int it = 0; it < 2; it++) {
            int slot = tid + it * 256;
            Bb[buf * 512 + slot] = br[it];
        }
    };

    ldg(0);
    sts(0);
    __syncthreads();

    for (int kc = 0; kc < 32; kc++) {
        const int buf = kc & 1;
        if (kc < 31) ldg(kc + 1);

#pragma unroll
        for (int cc = 0; cc < 2; cc++) {
            const uint4* Ac = Ab + buf * 1024 + cc * 512;
            const uint4* Bc = Bb + buf * 512 + cc * 256;
            uint4 a0 = Ac[(wm + g) * 4 + tg];
            uint4 a1 = Ac[(wm + g + 8) * 4 + tg];
            uint4 a2 = Ac[(wm + 16 + g) * 4 + tg];
            uint4 a3 = Ac[(wm + 16 + g + 8) * 4 + tg];
            uint4 bv[4];
#pragma unroll
            for (int nf = 0; nf < 4; nf++)
                bv[nf] = Bc[(wn + nf * 8 + g) * 4 + tg];
#pragma unroll
            for (int nf = 0; nf < 4; nf++) {
                // hh
                mma16(acc[0][nf], a0.x, a1.x, a0.y, a1.y, bv[nf].x, bv[nf].y);
                mma16(acc[1][nf], a2.x, a3.x, a2.y, a3.y, bv[nf].x, bv[nf].y);
                // lh
                mma16(acc[0][nf], a0.z, a1.z, a0.w, a1.w, bv[nf].x, bv[nf].y);
                mma16(acc[1][nf], a2.z, a3.z, a2.w, a3.w, bv[nf].x, bv[nf].y);
                if (PASSES == 3) {
                    // hl
                    mma16(acc[0][nf], a0.x, a1.x, a0.y, a1.y, bv[nf].z, bv[nf].w);
                    mma16(acc[1][nf], a2.x, a3.x, a2.y, a3.y, bv[nf].z, bv[nf].w);
                }
            }
        }
        if (kc < 31) sts(buf ^ 1);
        __syncthreads();
    }

    float* G = (MODE == 0) ? g_Q : (MODE == 1) ? g_K : g_V;
    float* Ot = G + ((size_t)bh * S_ + s0) * D_;
    const float* bi = bias + h * D_;
#pragma unroll
    for (int mf = 0; mf < 2; mf++) {
#pragma unroll
        for (int nf = 0; nf < 4; nf++) {
            int col = wn + nf * 8 + 2 * tg;
            float bx = bi[col], by = bi[col + 1];
            int r0 = wm + mf * 16 + g;
            *(float2*)(Ot + (size_t)r0 * D_ + col) =
                make_float2(acc[mf][nf][0] + bx, acc[mf][nf][1] + by);
            *(float2*)(Ot + (size_t)(r0 + 8) * D_ + col) =
                make_float2(acc[mf][nf][2] + bx, acc[mf][nf][3] + by);
        }
    }
}

// ---------------------------------------------------------------------------
// Flash attention: f16x3 QK + f16x2 PV (round-9, unchanged / passing)
// ---------------------------------------------------------------------------
#define ATT_SMEM 90112
#define F_KOFF 32768
#define F_VOFF 49152
#define F_POFF 57344

__global__ __launch_bounds__(256, 2) void attn_kernel()
{
    extern __shared__ char smc[];
    uint32_t* Qw = (uint32_t*)smc;
    uint32_t* Kw = (uint32_t*)(smc + F_KOFF);
    uint16_t* Vw = (uint16_t*)(smc + F_VOFF);
    uint2*    Pw = (uint2*)(smc + F_POFF);
    const uint4* Qu = (const uint4*)smc;
    const uint4* Ku = (const uint4*)(smc + F_KOFF);
    const uint2* Vu = (const uint2*)(smc + F_VOFF);
    const uint2* Pu = (const uint2*)(smc + F_POFF);

    const int tid = threadIdx.x;
    const int lane = tid & 31;
    const int warp = tid >> 5;
    const int g = lane >> 2;
    const int tg = lane & 3;
    const int rbase = warp * 16;
    const int bh = blockIdx.y;
    const int q0 = blockIdx.x * 128;

    const float* Qg = g_Q + ((size_t)bh * S_ + q0) * D_;
    const float* Kg = g_K + (size_t)bh * S_ * D_;
    const float* Vg = g_V + (size_t)bh * S_ * D_;

#pragma unroll
    for (int it = 0; it < 8; it++) {
        int slot = tid + it * 256;
        int row = slot >> 4;
        int c4 = (slot & 15) * 4;
        float4 f = *(const float4*)(Qg + (size_t)row * D_ + c4);
        uint32_t hi01, lo01, hi23, lo23;
        split2h(f.x * 0.125f, f.y * 0.125f, hi01, lo01);
        split2h(f.z * 0.125f, f.w * 0.125f, hi23, lo23);
        int cc = c4 >> 4;
        int p0 = (c4 >> 1) & 7;
        uint32_t* base = Qw + (((cc << 7) + row) << 4);
        int i0 = ((p0 & 3) << 2) + (p0 >> 2);
        int p1 = p0 + 1;
        int i1 = ((p1 & 3) << 2) + (p1 >> 2);
        base[i0] = hi01; base[i0 + 2] = lo01;
        base[i1] = hi23; base[i1 + 2] = lo23;
    }

    float m0 = -1e30f, m1 = -1e30f, l0 = 0.f, l1 = 0.f;
    float oacc[8][4];
#pragma unroll
    for (int nf = 0; nf < 8; nf++)
#pragma unroll
        for (int c = 0; c < 4; c++) oacc[nf][c] = 0.f;

    const int rA = rbase + g, rB = rA + 8;

    for (int kb = 0; kb < 32; kb++) {
#pragma unroll
        for (int it = 0; it < 4; it++) {
            int slot = tid + it * 256;
            int key = slot >> 4;
            int c4 = (slot & 15) * 4;
            float4 kf = *(const float4*)(Kg + ((size_t)kb * 64 + key) * D_ + c4);
            float4 vf = *(const float4*)(Vg + ((size_t)kb * 64 + key) * D_ + c4);
            {
                uint32_t hi01, lo01, hi23, lo23;
                split2h(kf.x, kf.y, hi01, lo01);
                split2h(kf.z, kf.w, hi23, lo23);
                int cc = c4 >> 4;
                int p0 = (c4 >> 1) & 7;
                uint32_t* base = Kw + (((cc << 6) + key) << 4);
                int i0 = ((p0 & 3) << 2) + (p0 >> 2);
                int p1 = p0 + 1;
                int i1 = ((p1 & 3) << 2) + (p1 >> 2);
                base[i0] = hi01; base[i0 + 2] = lo01;
                base[i1] = hi23; base[i1 + 2] = lo23;
            }
            {
                int cc = key >> 4;
                int p = (key & 15) >> 1;
                int w = key & 1;
                int sl = p & 3, hf = p >> 2;
                const float* ve = (const float*)&vf;
#pragma unroll
                for (int j = 0; j < 4; j++) {
                    int d = c4 + j;
                    int uidx = (((cc << 6) + d) << 2) + sl;
                    Vw[uidx * 4 + hf * 2 + w] = hbits(ve[j]);
                }
            }
        }
        __syncthreads();

        float sacc[8][4];
#pragma unroll
        for (int nf = 0; nf < 8; nf++)
#pragma unroll
            for (int c = 0; c < 4; c++) sacc[nf][c] = 0.f;

#pragma unroll 2
        for (int cc = 0; cc < 4; cc++) {
            uint4 qa = Qu[(((cc << 7) + rA) << 2) + tg];
            uint4 qb = Qu[(((cc << 7) + rB) << 2) + tg];
#pragma unroll
            for (int nf = 0; nf < 8; nf++) {
                uint4 kv = Ku[(((cc << 6) + nf * 8 + g) << 2) + tg];
                mma16(sacc[nf], qa.x, qb.x, qa.y, qb.y, kv.x, kv.y);
                mma16(sacc[nf], qa.z, qb.z, qa.w, qb.w, kv.x, kv.y);
                mma16(sacc[nf], qa.x, qb.x, qa.y, qb.y, kv.z, kv.w);
            }
        }

        float mx0 = -1e30f, mx1 = -1e30f;
#pragma unroll
        for (int nf = 0; nf < 8; nf++) {
            mx0 = fmaxf(mx0, fmaxf(sacc[nf][0], sacc[nf][1]));
            mx1 = fmaxf(mx1, fmaxf(sacc[nf][2], sacc[nf][3]));
        }
        mx0 = fmaxf(mx0, __shfl_xor_sync(0xffffffffu, mx0, 1));
        mx0 = fmaxf(mx0, __shfl_xor_sync(0xffffffffu, mx0, 2));
        mx1 = fmaxf(mx1, __shfl_xor_sync(0xffffffffu, mx1, 1));
        mx1 = fmaxf(mx1, __shfl_xor_sync(0xffffffffu, mx1, 2));
        float mn0 = fmaxf(m0, mx0), mn1 = fmaxf(m1, mx1);
        float corr0 = fast_exp(m0 - mn0), corr1 = fast_exp(m1 - mn1);
        m0 = mn0; m1 = mn1;

        float sum0 = 0.f, sum1 = 0.f;
#pragma unroll
        for (int nf = 0; nf < 8; nf++) {
            float p0 = fast_exp(sacc[nf][0] - mn0);
            float p1 = fast_exp(sacc[nf][1] - mn0);
            float p2 = fast_exp(sacc[nf][2] - mn1);
            float p3 = fast_exp(sacc[nf][3] - mn1);
            sum0 += p0 + p1; sum1 += p2 + p3;
            uint32_t hiA, loA, hiB, loB;
            split2h(p0, p1, hiA, loA);
            split2h(p2, p3, hiB, loB);
            int ccp = nf >> 1;
            int pidx = ((nf & 1) << 2) + tg;
            Pw[(((ccp << 7) + rA) << 3) + pidx] = make_uint2(hiA, loA);
            Pw[(((ccp << 7) + rB) << 3) + pidx] = make_uint2(hiB, loB);
            oacc[nf][0] *= corr0; oacc[nf][1] *= corr0;
            oacc[nf][2] *= corr1; oacc[nf][3] *= corr1;
        }
        sum0 += __shfl_xor_sync(0xffffffffu, sum0, 1);
        sum0 += __shfl_xor_sync(0xffffffffu, sum0, 2);
        sum1 += __shfl_xor_sync(0xffffffffu, sum1, 1);
        sum1 += __shfl_xor_sync(0xffffffffu, sum1, 2);
        l0 = l0 * corr0 + sum0;
        l1 = l1 * corr1 + sum1;

        __syncwarp();

#pragma unroll 2
        for (int cc = 0; cc < 4; cc++) {
            uint2 pA  = Pu[(((cc << 7) + rA) << 3) + tg];
            uint2 pA4 = Pu[(((cc << 7) + rA) << 3) + tg + 4];
            uint2 pB  = Pu[(((cc << 7) + rB) << 3) + tg];
            uint2 pB4 = Pu[(((cc << 7) + rB) << 3) + tg + 4];
#pragma unroll
            for (int nf = 0; nf < 8; nf++) {
                uint2 vv = Vu[(((cc << 6) + nf * 8 + g) << 2) + tg];
                mma16(oacc[nf], pA.x, pB.x, pA4.x, pB4.x, vv.x, vv.y);
                mma16(oacc[nf], pA.y, pB.y, pA4.y, pB4.y, vv.x, vv.y);
            }
        }
        __syncthreads();
    }

    float inv0 = 1.f / l0, inv1 = 1.f / l1;
    float* Cg = g_C + ((size_t)bh * S_ + q0) * D_;
#pragma unroll
    for (int nf = 0; nf < 8; nf++) {
        int col = nf * 8 + 2 * tg;
        *(float2*)(Cg + (size_t)rA * D_ + col) =
            make_float2(oacc[nf][0] * inv0, oacc[nf][1] * inv0);
        *(float2*)(Cg + (size_t)rB * D_ + col) =
            make_float2(oacc[nf][2] * inv1, oacc[nf][3] * inv1);
    }
}

// ---------------------------------------------------------------------------
// Output projection (FFMA — known good)
// ---------------------------------------------------------------------------
__global__ __launch_bounds__(256) void oproj_kernel(
    const float* __restrict__ Wo, const float* __restrict__ bo, float* __restrict__ out)
{
    __shared__ float As[16][132];
    __shared__ float Bs[16][64];

    const int m0 = blockIdx.x * 128;
    const int n0 = blockIdx.y * 64;
    const int tid = threadIdx.x;
    const int ng = tid & 15;
    const int mg = tid >> 4;
    const int b = m0 >> 11;
    const int sbase = m0 & (S_ - 1);

    float acc[8][4];
#pragma unroll
    for (int i = 0; i < 8; i++)
#pragma unroll
        for (int j = 0; j < 4; j++) acc[i][j] = 0.f;

    for (int k0 = 0; k0 < E_; k0 += 16) {
#pragma unroll
        for (int it = 0; it < 2; it++) {
            int i = tid + it * 256;
            int row = i >> 2;
            int c4 = (i & 3) * 4;
            int e = k0 + c4;
            int h = e >> 6;
            int dd = e & 63;
            float4 f = *(const float4*)(g_C +
                (((size_t)(b * H_ + h) * S_ + sbase + row) * D_ + dd));
            As[c4 + 0][row] = f.x; As[c4 + 1][row] = f.y;
            As[c4 + 2][row] = f.z; As[c4 + 3][row] = f.w;
        }
        {
            int r = tid >> 4, c4 = (tid & 15) * 4;
            *(float4*)&Bs[r][c4] = *(const float4*)(Wo + (size_t)(k0 + r) * E_ + n0 + c4);
        }
        __syncthreads();
#pragma unroll
        for (int kk = 0; kk < 16; kk++) {
            float4 a0 = *(float4*)&As[kk][mg * 8];
            float4 a1 = *(float4*)&As[kk][mg * 8 + 4];
            float4 b4 = *(float4*)&Bs[kk][ng * 4];
            float a[8] = {a0.x, a0.y, a0.z, a0.w, a1.x, a1.y, a1.z, a1.w};
            float bb[4] = {b4.x, b4.y, b4.z, b4.w};
#pragma unroll
            for (int i = 0; i < 8; i++)
#pragma unroll
                for (int j = 0; j < 4; j++) acc[i][j] += a[i] * bb[j];
        }
        __syncthreads();
    }

    float4 b4 = *(const float4*)(bo + n0 + ng * 4);
#pragma unroll
    for (int i = 0; i < 8; i++) {
        size_t row = (size_t)m0 + mg * 8 + i;
        float4 r;
        r.x = acc[i][0] + b4.x; r.y = acc[i][1] + b4.y;
        r.z = acc[i][2] + b4.z; r.w = acc[i][3] + b4.w;
        *(float4*)(out + row * E_ + n0 + ng * 4) = r;
    }
}

// ---------------------------------------------------------------------------
extern "C" void kernel_launch(void* const* d_in, const int* in_sizes, int n_in,
                              void* d_out, int out_size)
{
    const float* q  = (const float*)d_in[0];
    const float* k  = (const float*)d_in[1];
    const float* v  = (const float*)d_in[2];
    const float* Wq = (const float*)d_in[3];
    const float* Wk = (const float*)d_in[4];
    const float* Wv = (const float*)d_in[5];
    const float* bq = (const float*)d_in[6];
    const float* bk = (const float*)d_in[7];
    const float* bv = (const float*)d_in[8];
    const float* Wo = (const float*)d_in[9];
    const float* bo = (const float*)d_in[10];
    float* out = (float*)d_out;

    cudaFuncSetAttribute(proj_f16<3, 0>, cudaFuncAttributeMaxDynamicSharedMemorySize, PROJ_SMEM);
    cudaFuncSetAttribute(proj_f16<3, 1>, cudaFuncAttributeMaxDynamicSharedMemorySize, PROJ_SMEM);
    cudaFuncSetAttribute(proj_f16<2, 2>, cudaFuncAttributeMaxDynamicSharedMemorySize, PROJ_SMEM);
    cudaFuncSetAttribute(attn_kernel, cudaFuncAttributeMaxDynamicSharedMemorySize, ATT_SMEM);

    splitX_kernel<<<12288, 256>>>(q, k, v);
    splitW_kernel<<<3072, 256>>>(Wq, Wk, Wv);
    proj_f16<3, 0><<<dim3(S_ / 128, BH_), 256, PROJ_SMEM>>>(bq);
    proj_f16<3, 1><<<dim3(S_ / 128, BH_), 256, PROJ_SMEM>>>(bk);
    proj_f16<2, 2><<<dim3(S_ / 128, BH_), 256, PROJ_SMEM>>>(bv);
    attn_kernel<<<dim3(S_ / 128, BH_), 256, ATT_SMEM>>>();
    oproj_kernel<<<dim3((B_ * S_) / 128, E_ / 64), 256>>>(Wo, bo, out);
}

// round 11
// speedup vs baseline: 3.0970x; 1.4116x over previous
#include <cuda_runtime.h>
#include <cuda_fp16.h>
#include <stdint.h>
#include <math.h>

#define B_ 2
#define S_ 2048
#define E_ 1024
#define H_ 16
#define D_ 64
#define BH_ (B_*H_)

// ---- pre-split operand images (f16 hi/lo interleaved, MMA smem layout) ----
__device__ uint4 gXs[(size_t)3 * 2 * 64 * 2048 * 4];   // proj A: [z][b][cc][s][j]
__device__ uint4 gWs[(size_t)3 * 16 * 64 * 64 * 4];    // proj B: [z][h][cc][d][j]
__device__ uint4 gQs[(size_t)BH_ * 4 * 2048 * 4];      // Q/8 split: [bh][cc][s][j]
__device__ uint4 gKs[(size_t)BH_ * 4 * 2048 * 4];      // K split:  [bh][cc][s][j]
__device__ uint2 gVs[(size_t)BH_ * 128 * 64 * 4];      // V^T f16:  [bh][kc][d][sl]
__device__ uint4 gCs[(size_t)64 * 4096 * 4];           // ctx split: [cc][m][j]
__device__ uint4 gWos[(size_t)64 * 1024 * 4];          // Wo split:  [cc][n][j]

// ---------------- f16 helpers ----------------
__device__ __forceinline__ void split2h(float x0, float x1, uint32_t& hi, uint32_t& lo) {
    __half h0 = __float2half_rn(x0), h1 = __float2half_rn(x1);
    float r0 = x0 - __half2float(h0), r1 = x1 - __half2float(h1);
    __half l0 = __float2half_rn(r0), l1 = __float2half_rn(r1);
    hi = (uint32_t)__half_as_ushort(h0) | ((uint32_t)__half_as_ushort(h1) << 16);
    lo = (uint32_t)__half_as_ushort(l0) | ((uint32_t)__half_as_ushort(l1) << 16);
}
__device__ __forceinline__ uint16_t hbits(float x) {
    __half h = __float2half_rn(x);
    return __half_as_ushort(h);
}
__device__ __forceinline__ void mma16(float* c,
                                      uint32_t a0, uint32_t a1, uint32_t a2, uint32_t a3,
                                      uint32_t b0, uint32_t b1) {
    asm volatile(
        "mma.sync.aligned.m16n8k16.row.col.f32.f16.f16.f32 "
        "{%0,%1,%2,%3}, {%4,%5,%6,%7}, {%8,%9}, {%0,%1,%2,%3};\n"
        : "+f"(c[0]), "+f"(c[1]), "+f"(c[2]), "+f"(c[3])
        : "r"(a0), "r"(a1), "r"(a2), "r"(a3), "r"(b0), "r"(b1));
}

// fast exp on FMA pipe; args <= 0
__device__ __forceinline__ float fast_exp(float x) {
    float t = x * 1.44269504089f;
    t = fmaxf(t, -100.0f);
    float rm = t + 12582912.0f;
    int ib = __float_as_int(rm) - 0x4B400000;
    float f = t - (rm - 12582912.0f);
    float p = 0.0013333558f;
    p = fmaf(p, f, 0.0096181291f);
    p = fmaf(p, f, 0.0555041087f);
    p = fmaf(p, f, 0.2402265069f);
    p = fmaf(p, f, 0.6931471806f);
    p = fmaf(p, f, 1.0f);
    return __int_as_float(__float_as_int(p) + (ib << 23));
}

// ---------------------------------------------------------------------------
// Pre-split X (q,k,v) into gXs  (round-10, passing)
// ---------------------------------------------------------------------------
__global__ __launch_bounds__(256) void splitX_kernel(
    const float* __restrict__ q, const float* __restrict__ k, const float* __restrict__ v)
{
    uint32_t t = blockIdx.x * 256 + threadIdx.x;
    int j = t & 3;
    int s = (t >> 2) & 2047;
    int cc = (t >> 13) & 63;
    int b = (t >> 19) & 1;
    int z = t >> 20;
    const float* X = (z == 0) ? q : (z == 1) ? k : v;
    const float* row = X + ((size_t)b * S_ + s) * E_ + cc * 16;
    float x0 = row[2 * j], x1 = row[2 * j + 1];
    float x2 = row[8 + 2 * j], x3 = row[8 + 2 * j + 1];
    uint32_t hiA, loA, hiB, loB;
    split2h(x0, x1, hiA, loA);
    split2h(x2, x3, hiB, loB);
    gXs[t] = make_uint4(hiA, hiB, loA, loB);
}

// ---------------------------------------------------------------------------
// Pre-split + transpose W (Wq,Wk,Wv) into gWs  (round-10, passing)
// ---------------------------------------------------------------------------
__global__ __launch_bounds__(256) void splitW_kernel(
    const float* __restrict__ Wq, const float* __restrict__ Wk, const float* __restrict__ Wv)
{
    uint32_t t = blockIdx.x * 256 + threadIdx.x;
    int j = t & 3;
    int d = (t >> 2) & 63;
    int cc = (t >> 8) & 63;
    int h = (t >> 14) & 15;
    int z = t >> 18;
    const float* W = (z == 0) ? Wq : (z == 1) ? Wk : Wv;
    const float* Wh = W + (size_t)h * E_ * D_;
    int e0 = cc * 16;
    float x0 = Wh[(size_t)(e0 + 2 * j) * D_ + d];
    float x1 = Wh[(size_t)(e0 + 2 * j + 1) * D_ + d];
    float x2 = Wh[(size_t)(e0 + 8 + 2 * j) * D_ + d];
    float x3 = Wh[(size_t)(e0 + 8 + 2 * j + 1) * D_ + d];
    uint32_t hiA, loA, hiB, loB;
    split2h(x0, x1, hiA, loA);
    split2h(x2, x3, hiB, loB);
    gWs[t] = make_uint4(hiA, hiB, loA, loB);
}

// ---------------------------------------------------------------------------
// Pre-split + transpose Wo into gWos: [cc=64][n=1024][j]
// ---------------------------------------------------------------------------
__global__ __launch_bounds__(256) void splitWo_kernel(const float* __restrict__ Wo)
{
    uint32_t t = blockIdx.x * 256 + threadIdx.x;
    int j = t & 3;
    int n = (t >> 2) & 1023;
    int cc = t >> 12;
    int e0 = cc * 16;
    float x0 = Wo[(size_t)(e0 + 2 * j) * E_ + n];
    float x1 = Wo[(size_t)(e0 + 2 * j + 1) * E_ + n];
    float x2 = Wo[(size_t)(e0 + 8 + 2 * j) * E_ + n];
    float x3 = Wo[(size_t)(e0 + 8 + 2 * j + 1) * E_ + n];
    uint32_t hiA, loA, hiB, loB;
    split2h(x0, x1, hiA, loA);
    split2h(x2, x3, hiB, loB);
    gWos[t] = make_uint4(hiA, hiB, loA, loB);
}

// ---------------------------------------------------------------------------
// f16 projection GEMM; epilogue writes pre-split images:
// MODE 0: Q -> gQs (scaled 1/8, split)   MODE 1: K -> gKs (split)
// MODE 2: V -> gVs (f16, transposed V^T image)
// ---------------------------------------------------------------------------
#define PROJ_SMEM 49152

template<int PASSES, int MODE>
__global__ __launch_bounds__(256, 2) void proj_f16(const float* __restrict__ bias)
{
    extern __shared__ char smc[];
    uint4* Ab = (uint4*)smc;
    uint4* Bb = (uint4*)(smc + 32768);

    const int tid = threadIdx.x;
    const int lane = tid & 31;
    const int warp = tid >> 5;
    const int g = lane >> 2;
    const int tg = lane & 3;
    const int wm = (warp >> 1) * 32;
    const int wn = (warp & 1) * 32;

    const int bh = blockIdx.y;
    const int b = bh >> 4;
    const int h = bh & 15;
    const int s0 = blockIdx.x * 128;

    const uint4* Xs = gXs + (((size_t)MODE * 2 + b) * 64) * 2048 * 4;
    const uint4* Ws = gWs + (((size_t)MODE * 16 + h) * 64) * 64 * 4;

    float acc[2][4][4];
#pragma unroll
    for (int mf = 0; mf < 2; mf++)
#pragma unroll
        for (int nf = 0; nf < 4; nf++)
#pragma unroll
            for (int c = 0; c < 4; c++) acc[mf][nf][c] = 0.f;

    uint4 ar[4], br[2];
    auto ldg = [&](int kc) {
        int cc0 = kc * 2;
#pragma unroll
        for (int it = 0; it < 4; it++) {
            int slot = tid + it * 256;
            int cc = slot >> 9;
            int row = (slot >> 2) & 127;
            int j = slot & 3;
            ar[it] = Xs[(((size_t)(cc0 + cc) * 2048) + s0 + row) * 4 + j];
        }
#pragma unroll
        for (int it = 0; it < 2; it++) {
            int slot = tid + it * 256;
            int cc = slot >> 8;
            int d = (slot >> 2) & 63;
            int j = slot & 3;
            br[it] = Ws[(((size_t)(cc0 + cc) * 64) + d) * 4 + j];
        }
    };
    auto sts = [&](int buf) {
#pragma unroll
        for (int it = 0; it < 4; it++) Ab[buf * 1024 + tid + it * 256] = ar[it];
#pragma unroll
        for (int it = 0; it < 2; it++) Bb[buf * 512 + tid + it * 256] = br[it];
    };

    ldg(0);
    sts(0);
    __syncthreads();

    for (int kc = 0; kc < 32; kc++) {
        const int buf = kc & 1;
        if (kc < 31) ldg(kc + 1);

#pragma unroll
        for (int cc = 0; cc < 2; cc++) {
            const uint4* Ac = Ab + buf * 1024 + cc * 512;
            const uint4* Bc = Bb + buf * 512 + cc * 256;
            uint4 a0 = Ac[(wm + g) * 4 + tg];
            uint4 a1 = Ac[(wm + g + 8) * 4 + tg];
            uint4 a2 = Ac[(wm + 16 + g) * 4 + tg];
            uint4 a3 = Ac[(wm + 16 + g + 8) * 4 + tg];
            uint4 bv[4];
#pragma unroll
            for (int nf = 0; nf < 4; nf++)
                bv[nf] = Bc[(wn + nf * 8 + g) * 4 + tg];
#pragma unroll
            for (int nf = 0; nf < 4; nf++) {
                mma16(acc[0][nf], a0.x, a1.x, a0.y, a1.y, bv[nf].x, bv[nf].y);
                mma16(acc[1][nf], a2.x, a3.x, a2.y, a3.y, bv[nf].x, bv[nf].y);
                mma16(acc[0][nf], a0.z, a1.z, a0.w, a1.w, bv[nf].x, bv[nf].y);
                mma16(acc[1][nf], a2.z, a3.z, a2.w, a3.w, bv[nf].x, bv[nf].y);
                if (PASSES == 3) {
                    mma16(acc[0][nf], a0.x, a1.x, a0.y, a1.y, bv[nf].z, bv[nf].w);
                    mma16(acc[1][nf], a2.x, a3.x, a2.y, a3.y, bv[nf].z, bv[nf].w);
                }
            }
        }
        if (kc < 31) sts(buf ^ 1);
        __syncthreads();
    }

    const float* bi = bias + h * D_;
    if (MODE == 2) {
        // V^T f16 image: gVs ushort idx = (((bh*128+kc)*64+d)*4+sl)*4 + hf*2 + w
        uint16_t* Vh = (uint16_t*)gVs;
#pragma unroll
        for (int mf = 0; mf < 2; mf++) {
#pragma unroll
            for (int nf = 0; nf < 4; nf++) {
                int col = wn + nf * 8 + 2 * tg;
                float bx = bi[col], by = bi[col + 1];
#pragma unroll
                for (int rr = 0; rr < 2; rr++) {
                    int key = s0 + wm + mf * 16 + g + rr * 8;
                    int kc = key >> 4;
                    int kl = key & 15;
                    int p = kl >> 1, sl = p & 3, hf = p >> 2, w = kl & 1;
                    size_t base = ((((size_t)bh * 128 + kc) * 64));
                    Vh[((base + col) * 4 + sl) * 4 + hf * 2 + w] =
                        hbits(acc[mf][nf][rr * 2] + bx);
                    Vh[((base + col + 1) * 4 + sl) * 4 + hf * 2 + w] =
                        hbits(acc[mf][nf][rr * 2 + 1] + by);
                }
            }
        }
    } else {
        const float scale = (MODE == 0) ? 0.125f : 1.0f;
        uint32_t* Gimg = (uint32_t*)((MODE == 0) ? gQs : gKs);
#pragma unroll
        for (int mf = 0; mf < 2; mf++) {
#pragma unroll
            for (int nf = 0; nf < 4; nf++) {
                int col = wn + nf * 8 + 2 * tg;
                float bx = bi[col], by = bi[col + 1];
                int cc = col >> 4;
                int p = (col & 15) >> 1;
                int ih = ((p & 3) << 2) + (p >> 2);
                int r0 = wm + mf * 16 + g;
                uint32_t hi, lo;
                size_t base0 = (((size_t)(bh * 4 + cc) * 2048) + s0 + r0) * 16;
                split2h((acc[mf][nf][0] + bx) * scale, (acc[mf][nf][1] + by) * scale, hi, lo);
                Gimg[base0 + ih] = hi; Gimg[base0 + ih + 2] = lo;
                split2h((acc[mf][nf][2] + bx) * scale, (acc[mf][nf][3] + by) * scale, hi, lo);
                Gimg[base0 + 128 + ih] = hi; Gimg[base0 + 128 + ih + 2] = lo;
            }
        }
    }
}

// ---------------------------------------------------------------------------
// Flash attention: f16x3 QK + f16x2 PV; ALL loaders are pure copies from
// pre-split images. Epilogue writes split ctx image gCs.
// BM=128, 256 thr / 8 warps, 88KB smem, 2 CTAs/SM. grid = (S/128, BH)
// ---------------------------------------------------------------------------
#define ATT_SMEM 90112
#define F_KOFF 32768
#define F_VOFF 49152
#define F_POFF 57344

__global__ __launch_bounds__(256, 2) void attn_kernel()
{
    extern __shared__ char smc[];
    uint4* Qsm = (uint4*)smc;
    uint4* Ksm = (uint4*)(smc + F_KOFF);
    uint2* Vsm = (uint2*)(smc + F_VOFF);
    uint2* Pw  = (uint2*)(smc + F_POFF);
    const uint4* Qu = (const uint4*)smc;
    const uint4* Ku = (const uint4*)(smc + F_KOFF);
    const uint2* Vu = (const uint2*)(smc + F_VOFF);
    const uint2* Pu = (const uint2*)(smc + F_POFF);

    const int tid = threadIdx.x;
    const int lane = tid & 31;
    const int warp = tid >> 5;
    const int g = lane >> 2;
    const int tg = lane & 3;
    const int rbase = warp * 16;
    const int bh = blockIdx.y;
    const int q0 = blockIdx.x * 128;

    // ---- Q tile: pure copy (2048 uint4) ----
#pragma unroll
    for (int it = 0; it < 8; it++) {
        int slot = tid + it * 256;
        int j = slot & 3;
        int row = (slot >> 2) & 127;
        int cc = slot >> 9;
        Qsm[slot] = gQs[(((size_t)(bh * 4 + cc) * 2048) + q0 + row) * 4 + j];
    }

    float m0 = -1e30f, m1 = -1e30f, l0 = 0.f, l1 = 0.f;
    float oacc[8][4];
#pragma unroll
    for (int nf = 0; nf < 8; nf++)
#pragma unroll
        for (int c = 0; c < 4; c++) oacc[nf][c] = 0.f;

    const int rA = rbase + g, rB = rA + 8;

    for (int kb = 0; kb < 32; kb++) {
        // ---- K tile copy (1024 uint4) + V tile copy (1024 uint2) ----
#pragma unroll
        for (int it = 0; it < 4; it++) {
            int slot = tid + it * 256;
            int j = slot & 3;
            int key = (slot >> 2) & 63;
            int cc = slot >> 8;
            Ksm[slot] = gKs[(((size_t)(bh * 4 + cc) * 2048) + kb * 64 + key) * 4 + j];
        }
        {
            size_t vbase = ((size_t)bh * 128 + kb * 4) * 256;
#pragma unroll
            for (int it = 0; it < 4; it++) {
                int slot = tid + it * 256;
                Vsm[slot] = gVs[vbase + slot];
            }
        }
        __syncthreads();

        // ---- S = (Q/8) K^T  (f16 3-pass) ----
        float sacc[8][4];
#pragma unroll
        for (int nf = 0; nf < 8; nf++)
#pragma unroll
            for (int c = 0; c < 4; c++) sacc[nf][c] = 0.f;

#pragma unroll 2
        for (int cc = 0; cc < 4; cc++) {
            uint4 qa = Qu[(((cc << 7) + rA) << 2) + tg];
            uint4 qb = Qu[(((cc << 7) + rB) << 2) + tg];
#pragma unroll
            for (int nf = 0; nf < 8; nf++) {
                uint4 kv = Ku[(((cc << 6) + nf * 8 + g) << 2) + tg];
                mma16(sacc[nf], qa.x, qb.x, qa.y, qb.y, kv.x, kv.y);
                mma16(sacc[nf], qa.z, qb.z, qa.w, qb.w, kv.x, kv.y);
                mma16(sacc[nf], qa.x, qb.x, qa.y, qb.y, kv.z, kv.w);
            }
        }

        // ---- online softmax ----
        float mx0 = -1e30f, mx1 = -1e30f;
#pragma unroll
        for (int nf = 0; nf < 8; nf++) {
            mx0 = fmaxf(mx0, fmaxf(sacc[nf][0], sacc[nf][1]));
            mx1 = fmaxf(mx1, fmaxf(sacc[nf][2], sacc[nf][3]));
        }
        mx0 = fmaxf(mx0, __shfl_xor_sync(0xffffffffu, mx0, 1));
        mx0 = fmaxf(mx0, __shfl_xor_sync(0xffffffffu, mx0, 2));
        mx1 = fmaxf(mx1, __shfl_xor_sync(0xffffffffu, mx1, 1));
        mx1 = fmaxf(mx1, __shfl_xor_sync(0xffffffffu, mx1, 2));
        float mn0 = fmaxf(m0, mx0), mn1 = fmaxf(m1, mx1);
        float corr0 = fast_exp(m0 - mn0), corr1 = fast_exp(m1 - mn1);
        m0 = mn0; m1 = mn1;

        float sum0 = 0.f, sum1 = 0.f;
#pragma unroll
        for (int nf = 0; nf < 8; nf++) {
            float p0 = fast_exp(sacc[nf][0] - mn0);
            float p1 = fast_exp(sacc[nf][1] - mn0);
            float p2 = fast_exp(sacc[nf][2] - mn1);
            float p3 = fast_exp(sacc[nf][3] - mn1);
            sum0 += p0 + p1; sum1 += p2 + p3;
            uint32_t hiA, loA, hiB, loB;
            split2h(p0, p1, hiA, loA);
            split2h(p2, p3, hiB, loB);
            int ccp = nf >> 1;
            int pidx = ((nf & 1) << 2) + tg;
            Pw[(((ccp << 7) + rA) << 3) + pidx] = make_uint2(hiA, loA);
            Pw[(((ccp << 7) + rB) << 3) + pidx] = make_uint2(hiB, loB);
            oacc[nf][0] *= corr0; oacc[nf][1] *= corr0;
            oacc[nf][2] *= corr1; oacc[nf][3] *= corr1;
        }
        sum0 += __shfl_xor_sync(0xffffffffu, sum0, 1);
        sum0 += __shfl_xor_sync(0xffffffffu, sum0, 2);
        sum1 += __shfl_xor_sync(0xffffffffu, sum1, 1);
        sum1 += __shfl_xor_sync(0xffffffffu, sum1, 2);
        l0 = l0 * corr0 + sum0;
        l1 = l1 * corr1 + sum1;

        __syncwarp();

        // ---- O += P V  (f16 2-pass) ----
#pragma unroll 2
        for (int cc = 0; cc < 4; cc++) {
            uint2 pA  = Pu[(((cc << 7) + rA) << 3) + tg];
            uint2 pA4 = Pu[(((cc << 7) + rA) << 3) + tg + 4];
            uint2 pB  = Pu[(((cc << 7) + rB) << 3) + tg];
            uint2 pB4 = Pu[(((cc << 7) + rB) << 3) + tg + 4];
#pragma unroll
            for (int nf = 0; nf < 8; nf++) {
                uint2 vv = Vu[(((cc << 6) + nf * 8 + g) << 2) + tg];
                mma16(oacc[nf], pA.x, pB.x, pA4.x, pB4.x, vv.x, vv.y);
                mma16(oacc[nf], pA.y, pB.y, pA4.y, pB4.y, vv.x, vv.y);
            }
        }
        __syncthreads();
    }

    // ---- epilogue: normalize + write split ctx image ----
    float inv0 = 1.f / l0, inv1 = 1.f / l1;
    uint32_t* Cimg = (uint32_t*)gCs;
    const int h = bh & 15, b = bh >> 4;
#pragma unroll
    for (int nf = 0; nf < 8; nf++) {
        int cc = h * 4 + (nf >> 1);
        int p = ((nf & 1) << 2) + tg;
        int ih = ((p & 3) << 2) + (p >> 2);
        uint32_t hi, lo;
        size_t baseA = ((size_t)cc * 4096 + b * 2048 + q0 + rA) * 16;
        split2h(oacc[nf][0] * inv0, oacc[nf][1] * inv0, hi, lo);
        Cimg[baseA + ih] = hi; Cimg[baseA + ih + 2] = lo;
        size_t baseB = ((size_t)cc * 4096 + b * 2048 + q0 + rB) * 16;
        split2h(oacc[nf][2] * inv1, oacc[nf][3] * inv1, hi, lo);
        Cimg[baseB + ih] = hi; Cimg[baseB + ih + 2] = lo;
    }
}

// ---------------------------------------------------------------------------
// Output projection: f16x2 GEMM from gCs x gWos. Tile 128x64, grid (32,16).
// ---------------------------------------------------------------------------
__global__ __launch_bounds__(256, 2) void oproj_f16(
    const float* __restrict__ bo, float* __restrict__ out)
{
    extern __shared__ char smc[];
    uint4* Ab = (uint4*)smc;
    uint4* Bb = (uint4*)(smc + 32768);

    const int tid = threadIdx.x;
    const int lane = tid & 31;
    const int warp = tid >> 5;
    const int g = lane >> 2;
    const int tg = lane & 3;
    const int wm = (warp >> 1) * 32;
    const int wn = (warp & 1) * 32;

    const int m0 = blockIdx.x * 128;
    const int n0 = blockIdx.y * 64;

    float acc[2][4][4];
#pragma unroll
    for (int mf = 0; mf < 2; mf++)
#pragma unroll
        for (int nf = 0; nf < 4; nf++)
#pragma unroll
            for (int c = 0; c < 4; c++) acc[mf][nf][c] = 0.f;

    uint4 ar[4], br[2];
    auto ldg = [&](int kc) {
        int cc0 = kc * 2;
#pragma unroll
        for (int it = 0; it < 4; it++) {
            int slot = tid + it * 256;
            int cc = slot >> 9;
            int row = (slot >> 2) & 127;
            int j = slot & 3;
            ar[it] = gCs[(((size_t)(cc0 + cc) * 4096) + m0 + row) * 4 + j];
        }
#pragma unroll
        for (int it = 0; it < 2; it++) {
            int slot = tid + it * 256;
            int cc = slot >> 8;
            int d = (slot >> 2) & 63;
            int j = slot & 3;
            br[it] = gWos[(((size_t)(cc0 + cc) * 1024) + n0 + d) * 4 + j];
        }
    };
    auto sts = [&](int buf) {
#pragma unroll
        for (int it = 0; it < 4; it++) Ab[buf * 1024 + tid + it * 256] = ar[it];
#pragma unroll
        for (int it = 0; it < 2; it++) Bb[buf * 512 + tid + it * 256] = br[it];
    };

    ldg(0);
    sts(0);
    __syncthreads();

    for (int kc = 0; kc < 32; kc++) {
        const int buf = kc & 1;
        if (kc < 31) ldg(kc + 1);

#pragma unroll
        for (int cc = 0; cc < 2; cc++) {
            const uint4* Ac = Ab + buf * 1024 + cc * 512;
            const uint4* Bc = Bb + buf * 512 + cc * 256;
            uint4 a0 = Ac[(wm + g) * 4 + tg];
            uint4 a1 = Ac[(wm + g + 8) * 4 + tg];
            uint4 a2 = Ac[(wm + 16 + g) * 4 + tg];
            uint4 a3 = Ac[(wm + 16 + g + 8) * 4 + tg];
            uint4 bv[4];
#pragma unroll
            for (int nf = 0; nf < 4; nf++)
                bv[nf] = Bc[(wn + nf * 8 + g) * 4 + tg];
#pragma unroll
            for (int nf = 0; nf < 4; nf++) {
                mma16(acc[0][nf], a0.x, a1.x, a0.y, a1.y, bv[nf].x, bv[nf].y);
                mma16(acc[1][nf], a2.x, a3.x, a2.y, a3.y, bv[nf].x, bv[nf].y);
                mma16(acc[0][nf], a0.z, a1.z, a0.w, a1.w, bv[nf].x, bv[nf].y);
                mma16(acc[1][nf], a2.z, a3.z, a2.w, a3.w, bv[nf].x, bv[nf].y);
            }
        }
        if (kc < 31) sts(buf ^ 1);
        __syncthreads();
    }

    const float* bi = bo + n0;
#pragma unroll
    for (int mf = 0; mf < 2; mf++) {
#pragma unroll
        for (int nf = 0; nf < 4; nf++) {
            int col = wn + nf * 8 + 2 * tg;
            float bx = bi[col], by = bi[col + 1];
            int r0 = wm + mf * 16 + g;
            *(float2*)(out + (size_t)(m0 + r0) * E_ + n0 + col) =
                make_float2(acc[0 * 2 + mf][nf][0] + bx, acc[mf][nf][1] + by);
            *(float2*)(out + (size_t)(m0 + r0 + 8) * E_ + n0 + col) =
                make_float2(acc[mf][nf][2] + bx, acc[mf][nf][3] + by);
        }
    }
}

// ---------------------------------------------------------------------------
extern "C" void kernel_launch(void* const* d_in, const int* in_sizes, int n_in,
                              void* d_out, int out_size)
{
    const float* q  = (const float*)d_in[0];
    const float* k  = (const float*)d_in[1];
    const float* v  = (const float*)d_in[2];
    const float* Wq = (const float*)d_in[3];
    const float* Wk = (const float*)d_in[4];
    const float* Wv = (const float*)d_in[5];
    const float* bq = (const float*)d_in[6];
    const float* bk = (const float*)d_in[7];
    const float* bv = (const float*)d_in[8];
    const float* Wo = (const float*)d_in[9];
    const float* bo = (const float*)d_in[10];
    float* out = (float*)d_out;

    cudaFuncSetAttribute(proj_f16<3, 0>, cudaFuncAttributeMaxDynamicSharedMemorySize, PROJ_SMEM);
    cudaFuncSetAttribute(proj_f16<3, 1>, cudaFuncAttributeMaxDynamicSharedMemorySize, PROJ_SMEM);
    cudaFuncSetAttribute(proj_f16<2, 2>, cudaFuncAttributeMaxDynamicSharedMemorySize, PROJ_SMEM);
    cudaFuncSetAttribute(oproj_f16, cudaFuncAttributeMaxDynamicSharedMemorySize, PROJ_SMEM);
    cudaFuncSetAttribute(attn_kernel, cudaFuncAttributeMaxDynamicSharedMemorySize, ATT_SMEM);

    splitX_kernel<<<12288, 256>>>(q, k, v);
    splitW_kernel<<<3072, 256>>>(Wq, Wk, Wv);
    splitWo_kernel<<<1024, 256>>>(Wo);
    proj_f16<3, 0><<<dim3(S_ / 128, BH_), 256, PROJ_SMEM>>>(bq);
    proj_f16<3, 1><<<dim3(S_ / 128, BH_), 256, PROJ_SMEM>>>(bk);
    proj_f16<2, 2><<<dim3(S_ / 128, BH_), 256, PROJ_SMEM>>>(bv);
    attn_kernel<<<dim3(S_ / 128, BH_), 256, ATT_SMEM>>>();
    oproj_f16<<<dim3((B_ * S_) / 128, E_ / 64), 256, PROJ_SMEM>>>(bo, out);
}

// round 13
// speedup vs baseline: 3.6164x; 1.1677x over previous
#include <cuda_runtime.h>
#include <cuda_fp16.h>
#include <stdint.h>
#include <math.h>

#define B_ 2
#define S_ 2048
#define E_ 1024
#define H_ 16
#define D_ 64
#define BH_ (B_*H_)

// ---- pre-split operand images (f16 hi/lo interleaved, MMA smem layout) ----
__device__ uint4 gXs[(size_t)3 * 2 * 64 * 2048 * 4];   // proj A: [z][b][cc][s][j]
__device__ uint4 gWs[(size_t)3 * 16 * 64 * 64 * 4];    // proj B: [z][h][cc][d][j]
__device__ uint4 gQs[(size_t)BH_ * 4 * 2048 * 4];      // Q/8 split: [bh][cc][s][j]
__device__ uint4 gKs[(size_t)BH_ * 4 * 2048 * 4];      // K split:  [bh][cc][s][j]
__device__ uint2 gVs[(size_t)BH_ * 128 * 64 * 4];      // V^T f16:  [bh][kc][d][sl]
__device__ uint4 gCs[(size_t)64 * 4096 * 4];           // ctx split: [cc][m][j]
__device__ uint4 gWos[(size_t)64 * 1024 * 4];          // Wo split:  [cc][n][j]

// ---------------- f16 helpers ----------------
__device__ __forceinline__ void split2h(float x0, float x1, uint32_t& hi, uint32_t& lo) {
    __half h0 = __float2half_rn(x0), h1 = __float2half_rn(x1);
    float r0 = x0 - __half2float(h0), r1 = x1 - __half2float(h1);
    __half l0 = __float2half_rn(r0), l1 = __float2half_rn(r1);
    hi = (uint32_t)__half_as_ushort(h0) | ((uint32_t)__half_as_ushort(h1) << 16);
    lo = (uint32_t)__half_as_ushort(l0) | ((uint32_t)__half_as_ushort(l1) << 16);
}
__device__ __forceinline__ uint16_t hbits(float x) {
    __half h = __float2half_rn(x);
    return __half_as_ushort(h);
}
__device__ __forceinline__ uint32_t packh(float x0, float x1) {
    return (uint32_t)hbits(x0) | ((uint32_t)hbits(x1) << 16);
}
__device__ __forceinline__ void mma16(float* c,
                                      uint32_t a0, uint32_t a1, uint32_t a2, uint32_t a3,
                                      uint32_t b0, uint32_t b1) {
    asm volatile(
        "mma.sync.aligned.m16n8k16.row.col.f32.f16.f16.f32 "
        "{%0,%1,%2,%3}, {%4,%5,%6,%7}, {%8,%9}, {%0,%1,%2,%3};\n"
        : "+f"(c[0]), "+f"(c[1]), "+f"(c[2]), "+f"(c[3])
        : "r"(a0), "r"(a1), "r"(a2), "r"(a3), "r"(b0), "r"(b1));
}

// ---------------------------------------------------------------------------
// Pre-split X (q,k,v) into gXs
// ---------------------------------------------------------------------------
__global__ __launch_bounds__(256) void splitX_kernel(
    const float* __restrict__ q, const float* __restrict__ k, const float* __restrict__ v)
{
    uint32_t t = blockIdx.x * 256 + threadIdx.x;
    int j = t & 3;
    int s = (t >> 2) & 2047;
    int cc = (t >> 13) & 63;
    int b = (t >> 19) & 1;
    int z = t >> 20;
    const float* X = (z == 0) ? q : (z == 1) ? k : v;
    const float* row = X + ((size_t)b * S_ + s) * E_ + cc * 16;
    float x0 = row[2 * j], x1 = row[2 * j + 1];
    float x2 = row[8 + 2 * j], x3 = row[8 + 2 * j + 1];
    uint32_t hiA, loA, hiB, loB;
    split2h(x0, x1, hiA, loA);
    split2h(x2, x3, hiB, loB);
    gXs[t] = make_uint4(hiA, hiB, loA, loB);
}

// ---------------------------------------------------------------------------
// Pre-split + transpose W (Wq,Wk,Wv) into gWs
// ---------------------------------------------------------------------------
__global__ __launch_bounds__(256) void splitW_kernel(
    const float* __restrict__ Wq, const float* __restrict__ Wk, const float* __restrict__ Wv)
{
    uint32_t t = blockIdx.x * 256 + threadIdx.x;
    int j = t & 3;
    int d = (t >> 2) & 63;
    int cc = (t >> 8) & 63;
    int h = (t >> 14) & 15;
    int z = t >> 18;
    const float* W = (z == 0) ? Wq : (z == 1) ? Wk : Wv;
    const float* Wh = W + (size_t)h * E_ * D_;
    int e0 = cc * 16;
    float x0 = Wh[(size_t)(e0 + 2 * j) * D_ + d];
    float x1 = Wh[(size_t)(e0 + 2 * j + 1) * D_ + d];
    float x2 = Wh[(size_t)(e0 + 8 + 2 * j) * D_ + d];
    float x3 = Wh[(size_t)(e0 + 8 + 2 * j + 1) * D_ + d];
    uint32_t hiA, loA, hiB, loB;
    split2h(x0, x1, hiA, loA);
    split2h(x2, x3, hiB, loB);
    gWs[t] = make_uint4(hiA, hiB, loA, loB);
}

// ---------------------------------------------------------------------------
// Pre-split + transpose Wo into gWos
// ---------------------------------------------------------------------------
__global__ __launch_bounds__(256) void splitWo_kernel(const float* __restrict__ Wo)
{
    uint32_t t = blockIdx.x * 256 + threadIdx.x;
    int j = t & 3;
    int n = (t >> 2) & 1023;
    int cc = t >> 12;
    int e0 = cc * 16;
    float x0 = Wo[(size_t)(e0 + 2 * j) * E_ + n];
    float x1 = Wo[(size_t)(e0 + 2 * j + 1) * E_ + n];
    float x2 = Wo[(size_t)(e0 + 8 + 2 * j) * E_ + n];
    float x3 = Wo[(size_t)(e0 + 8 + 2 * j + 1) * E_ + n];
    uint32_t hiA, loA, hiB, loB;
    split2h(x0, x1, hiA, loA);
    split2h(x2, x3, hiB, loB);
    gWos[t] = make_uint4(hiA, hiB, loA, loB);
}

// ---------------------------------------------------------------------------
// f16 projection GEMM; epilogue writes pre-split images.
// MODE 0: Q -> gQs (x1/8, split)  MODE 1: K -> gKs  MODE 2: V -> gVs (V^T f16)
// ---------------------------------------------------------------------------
#define PROJ_SMEM 49152

template<int PASSES, int MODE>
__global__ __launch_bounds__(256, 2) void proj_f16(const float* __restrict__ bias)
{
    extern __shared__ char smc[];
    uint4* Ab = (uint4*)smc;
    uint4* Bb = (uint4*)(smc + 32768);

    const int tid = threadIdx.x;
    const int lane = tid & 31;
    const int warp = tid >> 5;
    const int g = lane >> 2;
    const int tg = lane & 3;
    const int wm = (warp >> 1) * 32;
    const int wn = (warp & 1) * 32;

    const int bh = blockIdx.y;
    const int b = bh >> 4;
    const int h = bh & 15;
    const int s0 = blockIdx.x * 128;

    const uint4* Xs = gXs + (((size_t)MODE * 2 + b) * 64) * 2048 * 4;
    const uint4* Ws = gWs + (((size_t)MODE * 16 + h) * 64) * 64 * 4;

    float acc[2][4][4];
#pragma unroll
    for (int mf = 0; mf < 2; mf++)
#pragma unroll
        for (int nf = 0; nf < 4; nf++)
#pragma unroll
            for (int c = 0; c < 4; c++) acc[mf][nf][c] = 0.f;

    uint4 ar[4], br[2];
    auto ldg = [&](int kc) {
        int cc0 = kc * 2;
#pragma unroll
        for (int it = 0; it < 4; it++) {
            int slot = tid + it * 256;
            int cc = slot >> 9;
            int row = (slot >> 2) & 127;
            int j = slot & 3;
            ar[it] = Xs[(((size_t)(cc0 + cc) * 2048) + s0 + row) * 4 + j];
        }
#pragma unroll
        for (int it = 0; it < 2; it++) {
            int slot = tid + it * 256;
            int cc = slot >> 8;
            int d = (slot >> 2) & 63;
            int j = slot & 3;
            br[it] = Ws[(((size_t)(cc0 + cc) * 64) + d) * 4 + j];
        }
    };
    auto sts = [&](int buf) {
#pragma unroll
        for (int it = 0; it < 4; it++) Ab[buf * 1024 + tid + it * 256] = ar[it];
#pragma unroll
        for (int it = 0; it < 2; it++) Bb[buf * 512 + tid + it * 256] = br[it];
    };

    ldg(0);
    sts(0);
    __syncthreads();

    for (int kc = 0; kc < 32; kc++) {
        const int buf = kc & 1;
        if (kc < 31) ldg(kc + 1);

#pragma unroll
        for (int cc = 0; cc < 2; cc++) {
            const uint4* Ac = Ab + buf * 1024 + cc * 512;
            const uint4* Bc = Bb + buf * 512 + cc * 256;
            uint4 a0 = Ac[(wm + g) * 4 + tg];
            uint4 a1 = Ac[(wm + g + 8) * 4 + tg];
            uint4 a2 = Ac[(wm + 16 + g) * 4 + tg];
            uint4 a3 = Ac[(wm + 16 + g + 8) * 4 + tg];
            uint4 bv[4];
#pragma unroll
            for (int nf = 0; nf < 4; nf++)
                bv[nf] = Bc[(wn + nf * 8 + g) * 4 + tg];
#pragma unroll
            for (int nf = 0; nf < 4; nf++) {
                mma16(acc[0][nf], a0.x, a1.x, a0.y, a1.y, bv[nf].x, bv[nf].y);
                mma16(acc[1][nf], a2.x, a3.x, a2.y, a3.y, bv[nf].x, bv[nf].y);
                mma16(acc[0][nf], a0.z, a1.z, a0.w, a1.w, bv[nf].x, bv[nf].y);
                mma16(acc[1][nf], a2.z, a3.z, a2.w, a3.w, bv[nf].x, bv[nf].y);
                if (PASSES == 3) {
                    mma16(acc[0][nf], a0.x, a1.x, a0.y, a1.y, bv[nf].z, bv[nf].w);
                    mma16(acc[1][nf], a2.x, a3.x, a2.y, a3.y, bv[nf].z, bv[nf].w);
                }
            }
        }
        if (kc < 31) sts(buf ^ 1);
        __syncthreads();
    }

    const float* bi = bias + h * D_;
    if (MODE == 2) {
        uint16_t* Vh = (uint16_t*)gVs;
#pragma unroll
        for (int mf = 0; mf < 2; mf++) {
#pragma unroll
            for (int nf = 0; nf < 4; nf++) {
                int col = wn + nf * 8 + 2 * tg;
                float bx = bi[col], by = bi[col + 1];
#pragma unroll
                for (int rr = 0; rr < 2; rr++) {
                    int key = s0 + wm + mf * 16 + g + rr * 8;
                    int kc = key >> 4;
                    int kl = key & 15;
                    int p = kl >> 1, sl = p & 3, hf = p >> 2, w = kl & 1;
                    size_t base = ((((size_t)bh * 128 + kc) * 64));
                    Vh[((base + col) * 4 + sl) * 4 + hf * 2 + w] =
                        hbits(acc[mf][nf][rr * 2] + bx);
                    Vh[((base + col + 1) * 4 + sl) * 4 + hf * 2 + w] =
                        hbits(acc[mf][nf][rr * 2 + 1] + by);
                }
            }
        }
    } else {
        const float scale = (MODE == 0) ? 0.125f : 1.0f;
        uint32_t* Gimg = (uint32_t*)((MODE == 0) ? gQs : gKs);
#pragma unroll
        for (int mf = 0; mf < 2; mf++) {
#pragma unroll
            for (int nf = 0; nf < 4; nf++) {
                int col = wn + nf * 8 + 2 * tg;
                float bx = bi[col], by = bi[col + 1];
                int cc = col >> 4;
                int p = (col & 15) >> 1;
                int ih = ((p & 3) << 2) + (p >> 2);
                int r0 = wm + mf * 16 + g;
                uint32_t hi, lo;
                size_t base0 = (((size_t)(bh * 4 + cc) * 2048) + s0 + r0) * 16;
                split2h((acc[mf][nf][0] + bx) * scale, (acc[mf][nf][1] + by) * scale, hi, lo);
                Gimg[base0 + ih] = hi; Gimg[base0 + ih + 2] = lo;
                split2h((acc[mf][nf][2] + bx) * scale, (acc[mf][nf][3] + by) * scale, hi, lo);
                Gimg[base0 + 128 + ih] = hi; Gimg[base0 + 128 + ih + 2] = lo;
            }
        }
    }
}

// ---------------------------------------------------------------------------
// Flash attention: f16x3 QK + f16x1 PV (P hi only); __expf softmax.
// Pure-copy loaders from pre-split images. 256 thr / 8 warps, 2 CTAs/SM.
// SMEM 72KB: Q 32K @0 | K 16K @32768 | V 8K @49152 | P(hi) 16K @57344
// grid = (S/128, BH)
// ---------------------------------------------------------------------------
#define ATT_SMEM 73728
#define F_KOFF 32768
#define F_VOFF 49152
#define F_POFF 57344

__global__ __launch_bounds__(256, 2) void attn_kernel()
{
    extern __shared__ char smc[];
    uint4* Qsm = (uint4*)smc;
    uint4* Ksm = (uint4*)(smc + F_KOFF);
    uint2* Vsm = (uint2*)(smc + F_VOFF);
    uint32_t* Pw = (uint32_t*)(smc + F_POFF);
    const uint4* Qu = (const uint4*)smc;
    const uint4* Ku = (const uint4*)(smc + F_KOFF);
    const uint2* Vu = (const uint2*)(smc + F_VOFF);
    const uint32_t* Pu = (const uint32_t*)(smc + F_POFF);

    const int tid = threadIdx.x;
    const int lane = tid & 31;
    const int warp = tid >> 5;
    const int g = lane >> 2;
    const int tg = lane & 3;
    const int rbase = warp * 16;
    const int bh = blockIdx.y;
    const int q0 = blockIdx.x * 128;

    // ---- Q tile: pure copy ----
#pragma unroll
    for (int it = 0; it < 8; it++) {
        int slot = tid + it * 256;
        int j = slot & 3;
        int row = (slot >> 2) & 127;
        int cc = slot >> 9;
        Qsm[slot] = gQs[(((size_t)(bh * 4 + cc) * 2048) + q0 + row) * 4 + j];
    }

    float m0 = -1e30f, m1 = -1e30f, l0 = 0.f, l1 = 0.f;
    float oacc[8][4];
#pragma unroll
    for (int nf = 0; nf < 8; nf++)
#pragma unroll
        for (int c = 0; c < 4; c++) oacc[nf][c] = 0.f;

    const int rA = rbase + g, rB = rA + 8;

    for (int kb = 0; kb < 32; kb++) {
        // ---- K + V tile pure copies ----
#pragma unroll
        for (int it = 0; it < 4; it++) {
            int slot = tid + it * 256;
            int j = slot & 3;
            int key = (slot >> 2) & 63;
            int cc = slot >> 8;
            Ksm[slot] = gKs[(((size_t)(bh * 4 + cc) * 2048) + kb * 64 + key) * 4 + j];
        }
        {
            size_t vbase = ((size_t)bh * 128 + kb * 4) * 256;
#pragma unroll
            for (int it = 0; it < 4; it++) {
                int slot = tid + it * 256;
                Vsm[slot] = gVs[vbase + slot];
            }
        }
        __syncthreads();

        // ---- S = (Q/8) K^T  (f16 3-pass) ----
        float sacc[8][4];
#pragma unroll
        for (int nf = 0; nf < 8; nf++)
#pragma unroll
            for (int c = 0; c < 4; c++) sacc[nf][c] = 0.f;

#pragma unroll 2
        for (int cc = 0; cc < 4; cc++) {
            uint4 qa = Qu[(((cc << 7) + rA) << 2) + tg];
            uint4 qb = Qu[(((cc << 7) + rB) << 2) + tg];
#pragma unroll
            for (int nf = 0; nf < 8; nf++) {
                uint4 kv = Ku[(((cc << 6) + nf * 8 + g) << 2) + tg];
                mma16(sacc[nf], qa.x, qb.x, qa.y, qb.y, kv.x, kv.y);
                mma16(sacc[nf], qa.z, qb.z, qa.w, qb.w, kv.x, kv.y);
                mma16(sacc[nf], qa.x, qb.x, qa.y, qb.y, kv.z, kv.w);
            }
        }

        // ---- online softmax (MUFU exp) ----
        float mx0 = -1e30f, mx1 = -1e30f;
#pragma unroll
        for (int nf = 0; nf < 8; nf++) {
            mx0 = fmaxf(mx0, fmaxf(sacc[nf][0], sacc[nf][1]));
            mx1 = fmaxf(mx1, fmaxf(sacc[nf][2], sacc[nf][3]));
        }
        mx0 = fmaxf(mx0, __shfl_xor_sync(0xffffffffu, mx0, 1));
        mx0 = fmaxf(mx0, __shfl_xor_sync(0xffffffffu, mx0, 2));
        mx1 = fmaxf(mx1, __shfl_xor_sync(0xffffffffu, mx1, 1));
        mx1 = fmaxf(mx1, __shfl_xor_sync(0xffffffffu, mx1, 2));
        float mn0 = fmaxf(m0, mx0), mn1 = fmaxf(m1, mx1);
        float corr0 = __expf(m0 - mn0), corr1 = __expf(m1 - mn1);
        m0 = mn0; m1 = mn1;

        float sum0 = 0.f, sum1 = 0.f;
#pragma unroll
        for (int nf = 0; nf < 8; nf++) {
            float p0 = __expf(sacc[nf][0] - mn0);
            float p1 = __expf(sacc[nf][1] - mn0);
            float p2 = __expf(sacc[nf][2] - mn1);
            float p3 = __expf(sacc[nf][3] - mn1);
            sum0 += p0 + p1; sum1 += p2 + p3;
            int ccp = nf >> 1;
            int pidx = ((nf & 1) << 2) + tg;
            Pw[(((ccp << 7) + rA) << 3) + pidx] = packh(p0, p1);
            Pw[(((ccp << 7) + rB) << 3) + pidx] = packh(p2, p3);
            oacc[nf][0] *= corr0; oacc[nf][1] *= corr0;
            oacc[nf][2] *= corr1; oacc[nf][3] *= corr1;
        }
        sum0 += __shfl_xor_sync(0xffffffffu, sum0, 1);
        sum0 += __shfl_xor_sync(0xffffffffu, sum0, 2);
        sum1 += __shfl_xor_sync(0xffffffffu, sum1, 1);
        sum1 += __shfl_xor_sync(0xffffffffu, sum1, 2);
        l0 = l0 * corr0 + sum0;
        l1 = l1 * corr1 + sum1;

        __syncwarp();

        // ---- O += P V  (f16 1-pass) ----
#pragma unroll 2
        for (int cc = 0; cc < 4; cc++) {
            uint32_t pA  = Pu[(((cc << 7) + rA) << 3) + tg];
            uint32_t pA4 = Pu[(((cc << 7) + rA) << 3) + tg + 4];
            uint32_t pB  = Pu[(((cc << 7) + rB) << 3) + tg];
            uint32_t pB4 = Pu[(((cc << 7) + rB) << 3) + tg + 4];
#pragma unroll
            for (int nf = 0; nf < 8; nf++) {
                uint2 vv = Vu[(((cc << 6) + nf * 8 + g) << 2) + tg];
                mma16(oacc[nf], pA, pB, pA4, pB4, vv.x, vv.y);
            }
        }
        __syncthreads();
    }

    // ---- epilogue: normalize + write split ctx image ----
    float inv0 = 1.f / l0, inv1 = 1.f / l1;
    uint32_t* Cimg = (uint32_t*)gCs;
    const int h = bh & 15, b = bh >> 4;
#pragma unroll
    for (int nf = 0; nf < 8; nf++) {
        int cc = h * 4 + (nf >> 1);
        int p = ((nf & 1) << 2) + tg;
        int ih = ((p & 3) << 2) + (p >> 2);
        uint32_t hi, lo;
        size_t baseA = ((size_t)cc * 4096 + b * 2048 + q0 + rA) * 16;
        split2h(oacc[nf][0] * inv0, oacc[nf][1] * inv0, hi, lo);
        Cimg[baseA + ih] = hi; Cimg[baseA + ih + 2] = lo;
        size_t baseB = ((size_t)cc * 4096 + b * 2048 + q0 + rB) * 16;
        split2h(oacc[nf][2] * inv1, oacc[nf][3] * inv1, hi, lo);
        Cimg[baseB + ih] = hi; Cimg[baseB + ih + 2] = lo;
    }
}

// ---------------------------------------------------------------------------
// Output projection: f16x2 GEMM from gCs x gWos
// ---------------------------------------------------------------------------
__global__ __launch_bounds__(256, 2) void oproj_f16(
    const float* __restrict__ bo, float* __restrict__ out)
{
    extern __shared__ char smc[];
    uint4* Ab = (uint4*)smc;
    uint4* Bb = (uint4*)(smc + 32768);

    const int tid = threadIdx.x;
    const int lane = tid & 31;
    const int warp = tid >> 5;
    const int g = lane >> 2;
    const int tg = lane & 3;
    const int wm = (warp >> 1) * 32;
    const int wn = (warp & 1) * 32;

    const int m0 = blockIdx.x * 128;
    const int n0 = blockIdx.y * 64;

    float acc[2][4][4];
#pragma unroll
    for (int mf = 0; mf < 2; mf++)
#pragma unroll
        for (int nf = 0; nf < 4; nf++)
#pragma unroll
            for (int c = 0; c < 4; c++) acc[mf][nf][c] = 0.f;

    uint4 ar[4], br[2];
    auto ldg = [&](int kc) {
        int cc0 = kc * 2;
#pragma unroll
        for (int it = 0; it < 4; it++) {
            int slot = tid + it * 256;
            int cc = slot >> 9;
            int row = (slot >> 2) & 127;
            int j = slot & 3;
            ar[it] = gCs[(((size_t)(cc0 + cc) * 4096) + m0 + row) * 4 + j];
        }
#pragma unroll
        for (int it = 0; it < 2; it++) {
            int slot = tid + it * 256;
            int cc = slot >> 8;
            int d = (slot >> 2) & 63;
            int j = slot & 3;
            br[it] = gWos[(((size_t)(cc0 + cc) * 1024) + n0 + d) * 4 + j];
        }
    };
    auto sts = [&](int buf) {
#pragma unroll
        for (int it = 0; it < 4; it++) Ab[buf * 1024 + tid + it * 256] = ar[it];
#pragma unroll
        for (int it = 0; it < 2; it++) Bb[buf * 512 + tid + it * 256] = br[it];
    };

    ldg(0);
    sts(0);
    __syncthreads();

    for (int kc = 0; kc < 32; kc++) {
        const int buf = kc & 1;
        if (kc < 31) ldg(kc + 1);

#pragma unroll
        for (int cc = 0; cc < 2; cc++) {
            const uint4* Ac = Ab + buf * 1024 + cc * 512;
            const uint4* Bc = Bb + buf * 512 + cc * 256;
            uint4 a0 = Ac[(wm + g) * 4 + tg];
            uint4 a1 = Ac[(wm + g + 8) * 4 + tg];
            uint4 a2 = Ac[(wm + 16 + g) * 4 + tg];
            uint4 a3 = Ac[(wm + 16 + g + 8) * 4 + tg];
            uint4 bv[4];
#pragma unroll
            for (int nf = 0; nf < 4; nf++)
                bv[nf] = Bc[(wn + nf * 8 + g) * 4 + tg];
#pragma unroll
            for (int nf = 0; nf < 4; nf++) {
                mma16(acc[0][nf], a0.x, a1.x, a0.y, a1.y, bv[nf].x, bv[nf].y);
                mma16(acc[1][nf], a2.x, a3.x, a2.y, a3.y, bv[nf].x, bv[nf].y);
                mma16(acc[0][nf], a0.z, a1.z, a0.w, a1.w, bv[nf].x, bv[nf].y);
                mma16(acc[1][nf], a2.z, a3.z, a2.w, a3.w, bv[nf].x, bv[nf].y);
            }
        }
        if (kc < 31) sts(buf ^ 1);
        __syncthreads();
    }

    const float* bi = bo + n0;
#pragma unroll
    for (int mf = 0; mf < 2; mf++) {
#pragma unroll
        for (int nf = 0; nf < 4; nf++) {
            int col = wn + nf * 8 + 2 * tg;
            float bx = bi[col], by = bi[col + 1];
            int r0 = wm + mf * 16 + g;
            *(float2*)(out + (size_t)(m0 + r0) * E_ + n0 + col) =
                make_float2(acc[mf][nf][0] + bx, acc[mf][nf][1] + by);
            *(float2*)(out + (size_t)(m0 + r0 + 8) * E_ + n0 + col) =
                make_float2(acc[mf][nf][2] + bx, acc[mf][nf][3] + by);
        }
    }
}

// ---------------------------------------------------------------------------
extern "C" void kernel_launch(void* const* d_in, const int* in_sizes, int n_in,
                              void* d_out, int out_size)
{
    const float* q  = (const float*)d_in[0];
    const float* k  = (const float*)d_in[1];
    const float* v  = (const float*)d_in[2];
    const float* Wq = (const float*)d_in[3];
    const float* Wk = (const float*)d_in[4];
    const float* Wv = (const float*)d_in[5];
    const float* bq = (const float*)d_in[6];
    const float* bk = (const float*)d_in[7];
    const float* bv = (const float*)d_in[8];
    const float* Wo = (const float*)d_in[9];
    const float* bo = (const float*)d_in[10];
    float* out = (float*)d_out;

    cudaFuncSetAttribute(proj_f16<3, 0>, cudaFuncAttributeMaxDynamicSharedMemorySize, PROJ_SMEM);
    cudaFuncSetAttribute(proj_f16<3, 1>, cudaFuncAttributeMaxDynamicSharedMemorySize, PROJ_SMEM);
    cudaFuncSetAttribute(proj_f16<2, 2>, cudaFuncAttributeMaxDynamicSharedMemorySize, PROJ_SMEM);
    cudaFuncSetAttribute(oproj_f16, cudaFuncAttributeMaxDynamicSharedMemorySize, PROJ_SMEM);
    cudaFuncSetAttribute(attn_kernel, cudaFuncAttributeMaxDynamicSharedMemorySize, ATT_SMEM);

    splitX_kernel<<<12288, 256>>>(q, k, v);
    splitW_kernel<<<3072, 256>>>(Wq, Wk, Wv);
    splitWo_kernel<<<1024, 256>>>(Wo);
    proj_f16<3, 0><<<dim3(S_ / 128, BH_), 256, PROJ_SMEM>>>(bq);
    proj_f16<3, 1><<<dim3(S_ / 128, BH_), 256, PROJ_SMEM>>>(bk);
    proj_f16<2, 2><<<dim3(S_ / 128, BH_), 256, PROJ_SMEM>>>(bv);
    attn_kernel<<<dim3(S_ / 128, BH_), 256, ATT_SMEM>>>();
    oproj_f16<<<dim3((B_ * S_) / 128, E_ / 64), 256, PROJ_SMEM>>>(bo, out);
}

// round 14
// speedup vs baseline: 3.8325x; 1.0598x over previous
#include <cuda_runtime.h>
#include <cuda_fp16.h>
#include <stdint.h>
#include <math.h>

#define B_ 2
#define S_ 2048
#define E_ 1024
#define H_ 16
#define D_ 64
#define BH_ (B_*H_)

// ---- pre-split operand images (f16 hi/lo interleaved, MMA smem layout) ----
__device__ uint4 gXs[(size_t)3 * 2 * 64 * 2048 * 4];   // proj A: [z][b][cc][s][j]
__device__ uint4 gWs[(size_t)3 * 16 * 64 * 64 * 4];    // proj B: [z][h][cc][d][j]
__device__ uint4 gQs[(size_t)BH_ * 4 * 2048 * 4];      // Q/8 split: [bh][cc][s][j]
__device__ uint4 gKs[(size_t)BH_ * 4 * 2048 * 4];      // K split:  [bh][cc][s][j]
__device__ uint2 gVs[(size_t)BH_ * 128 * 64 * 4];      // V^T f16:  [bh][kc][d][sl]
__device__ uint4 gCs[(size_t)64 * 4096 * 4];           // ctx split: [cc][m][j]
__device__ uint4 gWos[(size_t)64 * 1024 * 4];          // Wo split:  [cc][n][j]

// ---------------- f16 helpers ----------------
__device__ __forceinline__ void split2h(float x0, float x1, uint32_t& hi, uint32_t& lo) {
    __half h0 = __float2half_rn(x0), h1 = __float2half_rn(x1);
    float r0 = x0 - __half2float(h0), r1 = x1 - __half2float(h1);
    __half l0 = __float2half_rn(r0), l1 = __float2half_rn(r1);
    hi = (uint32_t)__half_as_ushort(h0) | ((uint32_t)__half_as_ushort(h1) << 16);
    lo = (uint32_t)__half_as_ushort(l0) | ((uint32_t)__half_as_ushort(l1) << 16);
}
__device__ __forceinline__ uint16_t hbits(float x) {
    __half h = __float2half_rn(x);
    return __half_as_ushort(h);
}
__device__ __forceinline__ uint32_t packh(float x0, float x1) {
    return (uint32_t)hbits(x0) | ((uint32_t)hbits(x1) << 16);
}
__device__ __forceinline__ void mma16(float* c,
                                      uint32_t a0, uint32_t a1, uint32_t a2, uint32_t a3,
                                      uint32_t b0, uint32_t b1) {
    asm volatile(
        "mma.sync.aligned.m16n8k16.row.col.f32.f16.f16.f32 "
        "{%0,%1,%2,%3}, {%4,%5,%6,%7}, {%8,%9}, {%0,%1,%2,%3};\n"
        : "+f"(c[0]), "+f"(c[1]), "+f"(c[2]), "+f"(c[3])
        : "r"(a0), "r"(a1), "r"(a2), "r"(a3), "r"(b0), "r"(b1));
}

// ---------------------------------------------------------------------------
// Merged pre-split kernel: X (12288 blks) | W (3072) | Wo (1024)
// ---------------------------------------------------------------------------
__global__ __launch_bounds__(256) void split_all(
    const float* __restrict__ q, const float* __restrict__ k, const float* __restrict__ v,
    const float* __restrict__ Wq, const float* __restrict__ Wk, const float* __restrict__ Wv,
    const float* __restrict__ Wo)
{
    uint32_t bid = blockIdx.x;
    if (bid < 12288) {
        uint32_t t = bid * 256 + threadIdx.x;
        int j = t & 3;
        int s = (t >> 2) & 2047;
        int cc = (t >> 13) & 63;
        int b = (t >> 19) & 1;
        int z = t >> 20;
        const float* X = (z == 0) ? q : (z == 1) ? k : v;
        const float* row = X + ((size_t)b * S_ + s) * E_ + cc * 16;
        float x0 = row[2 * j], x1 = row[2 * j + 1];
        float x2 = row[8 + 2 * j], x3 = row[8 + 2 * j + 1];
        uint32_t hiA, loA, hiB, loB;
        split2h(x0, x1, hiA, loA);
        split2h(x2, x3, hiB, loB);
        gXs[t] = make_uint4(hiA, hiB, loA, loB);
    } else if (bid < 15360) {
        uint32_t t = (bid - 12288) * 256 + threadIdx.x;
        int j = t & 3;
        int d = (t >> 2) & 63;
        int cc = (t >> 8) & 63;
        int h = (t >> 14) & 15;
        int z = t >> 18;
        const float* W = (z == 0) ? Wq : (z == 1) ? Wk : Wv;
        const float* Wh = W + (size_t)h * E_ * D_;
        int e0 = cc * 16;
        float x0 = Wh[(size_t)(e0 + 2 * j) * D_ + d];
        float x1 = Wh[(size_t)(e0 + 2 * j + 1) * D_ + d];
        float x2 = Wh[(size_t)(e0 + 8 + 2 * j) * D_ + d];
        float x3 = Wh[(size_t)(e0 + 8 + 2 * j + 1) * D_ + d];
        uint32_t hiA, loA, hiB, loB;
        split2h(x0, x1, hiA, loA);
        split2h(x2, x3, hiB, loB);
        gWs[t] = make_uint4(hiA, hiB, loA, loB);
    } else {
        uint32_t t = (bid - 15360) * 256 + threadIdx.x;
        int j = t & 3;
        int n = (t >> 2) & 1023;
        int cc = t >> 12;
        int e0 = cc * 16;
        float x0 = Wo[(size_t)(e0 + 2 * j) * E_ + n];
        float x1 = Wo[(size_t)(e0 + 2 * j + 1) * E_ + n];
        float x2 = Wo[(size_t)(e0 + 8 + 2 * j) * E_ + n];
        float x3 = Wo[(size_t)(e0 + 8 + 2 * j + 1) * E_ + n];
        uint32_t hiA, loA, hiB, loB;
        split2h(x0, x1, hiA, loA);
        split2h(x2, x3, hiB, loB);
        gWos[t] = make_uint4(hiA, hiB, loA, loB);
    }
}

// ---------------------------------------------------------------------------
// Merged f16 projection GEMM: blockIdx.z = mode (0:Q 1:K 2:V).
// z<2: 3-pass, epilogue writes split images; z=2: 2-pass, writes V^T f16.
// grid (16, BH, 3), 256 thr, 48KB smem, 2 CTAs/SM.
// ---------------------------------------------------------------------------
#define PROJ_SMEM 49152

__global__ __launch_bounds__(256, 2) void proj_all(
    const float* __restrict__ bq, const float* __restrict__ bk, const float* __restrict__ bv)
{
    extern __shared__ char smc[];
    uint4* Ab = (uint4*)smc;
    uint4* Bb = (uint4*)(smc + 32768);

    const int tid = threadIdx.x;
    const int lane = tid & 31;
    const int warp = tid >> 5;
    const int g = lane >> 2;
    const int tg = lane & 3;
    const int wm = (warp >> 1) * 32;
    const int wn = (warp & 1) * 32;

    const int z = blockIdx.z;
    const int bh = blockIdx.y;
    const int b = bh >> 4;
    const int h = bh & 15;
    const int s0 = blockIdx.x * 128;
    const float* bias = (z == 0) ? bq : (z == 1) ? bk : bv;

    const uint4* Xs = gXs + (((size_t)z * 2 + b) * 64) * 2048 * 4;
    const uint4* Ws = gWs + (((size_t)z * 16 + h) * 64) * 64 * 4;

    float acc[2][4][4];
#pragma unroll
    for (int mf = 0; mf < 2; mf++)
#pragma unroll
        for (int nf = 0; nf < 4; nf++)
#pragma unroll
            for (int c = 0; c < 4; c++) acc[mf][nf][c] = 0.f;

    uint4 ar[4], br[2];
    auto ldg = [&](int kc) {
        int cc0 = kc * 2;
#pragma unroll
        for (int it = 0; it < 4; it++) {
            int slot = tid + it * 256;
            int cc = slot >> 9;
            int row = (slot >> 2) & 127;
            int j = slot & 3;
            ar[it] = Xs[(((size_t)(cc0 + cc) * 2048) + s0 + row) * 4 + j];
        }
#pragma unroll
        for (int it = 0; it < 2; it++) {
            int slot = tid + it * 256;
            int cc = slot >> 8;
            int d = (slot >> 2) & 63;
            int j = slot & 3;
            br[it] = Ws[(((size_t)(cc0 + cc) * 64) + d) * 4 + j];
        }
    };
    auto sts = [&](int buf) {
#pragma unroll
        for (int it = 0; it < 4; it++) Ab[buf * 1024 + tid + it * 256] = ar[it];
#pragma unroll
        for (int it = 0; it < 2; it++) Bb[buf * 512 + tid + it * 256] = br[it];
    };

    ldg(0);
    sts(0);
    __syncthreads();

    const bool p3 = (z < 2);
    for (int kc = 0; kc < 32; kc++) {
        const int buf = kc & 1;
        if (kc < 31) ldg(kc + 1);

#pragma unroll
        for (int cc = 0; cc < 2; cc++) {
            const uint4* Ac = Ab + buf * 1024 + cc * 512;
            const uint4* Bc = Bb + buf * 512 + cc * 256;
            uint4 a0 = Ac[(wm + g) * 4 + tg];
            uint4 a1 = Ac[(wm + g + 8) * 4 + tg];
            uint4 a2 = Ac[(wm + 16 + g) * 4 + tg];
            uint4 a3 = Ac[(wm + 16 + g + 8) * 4 + tg];
            uint4 bv4[4];
#pragma unroll
            for (int nf = 0; nf < 4; nf++)
                bv4[nf] = Bc[(wn + nf * 8 + g) * 4 + tg];
#pragma unroll
            for (int nf = 0; nf < 4; nf++) {
                mma16(acc[0][nf], a0.x, a1.x, a0.y, a1.y, bv4[nf].x, bv4[nf].y);
                mma16(acc[1][nf], a2.x, a3.x, a2.y, a3.y, bv4[nf].x, bv4[nf].y);
                mma16(acc[0][nf], a0.z, a1.z, a0.w, a1.w, bv4[nf].x, bv4[nf].y);
                mma16(acc[1][nf], a2.z, a3.z, a2.w, a3.w, bv4[nf].x, bv4[nf].y);
            }
            if (p3) {
#pragma unroll
                for (int nf = 0; nf < 4; nf++) {
                    mma16(acc[0][nf], a0.x, a1.x, a0.y, a1.y, bv4[nf].z, bv4[nf].w);
                    mma16(acc[1][nf], a2.x, a3.x, a2.y, a3.y, bv4[nf].z, bv4[nf].w);
                }
            }
        }
        if (kc < 31) sts(buf ^ 1);
        __syncthreads();
    }

    const float* bi = bias + h * D_;
    if (z == 2) {
        uint16_t* Vh = (uint16_t*)gVs;
#pragma unroll
        for (int mf = 0; mf < 2; mf++) {
#pragma unroll
            for (int nf = 0; nf < 4; nf++) {
                int col = wn + nf * 8 + 2 * tg;
                float bx = bi[col], by = bi[col + 1];
#pragma unroll
                for (int rr = 0; rr < 2; rr++) {
                    int key = s0 + wm + mf * 16 + g + rr * 8;
                    int kc = key >> 4;
                    int kl = key & 15;
                    int p = kl >> 1, sl = p & 3, hf = p >> 2, w = kl & 1;
                    size_t base = ((((size_t)bh * 128 + kc) * 64));
                    Vh[((base + col) * 4 + sl) * 4 + hf * 2 + w] =
                        hbits(acc[mf][nf][rr * 2] + bx);
                    Vh[((base + col + 1) * 4 + sl) * 4 + hf * 2 + w] =
                        hbits(acc[mf][nf][rr * 2 + 1] + by);
                }
            }
        }
    } else {
        const float scale = (z == 0) ? 0.125f : 1.0f;
        uint32_t* Gimg = (uint32_t*)((z == 0) ? gQs : gKs);
#pragma unroll
        for (int mf = 0; mf < 2; mf++) {
#pragma unroll
            for (int nf = 0; nf < 4; nf++) {
                int col = wn + nf * 8 + 2 * tg;
                float bx = bi[col], by = bi[col + 1];
                int cc = col >> 4;
                int p = (col & 15) >> 1;
                int ih = ((p & 3) << 2) + (p >> 2);
                int r0 = wm + mf * 16 + g;
                uint32_t hi, lo;
                size_t base0 = (((size_t)(bh * 4 + cc) * 2048) + s0 + r0) * 16;
                split2h((acc[mf][nf][0] + bx) * scale, (acc[mf][nf][1] + by) * scale, hi, lo);
                Gimg[base0 + ih] = hi; Gimg[base0 + ih + 2] = lo;
                split2h((acc[mf][nf][2] + bx) * scale, (acc[mf][nf][3] + by) * scale, hi, lo);
                Gimg[base0 + 128 + ih] = hi; Gimg[base0 + 128 + ih + 2] = lo;
            }
        }
    }
}

// ---------------------------------------------------------------------------
// Flash attention: f16x3 QK + f16x1 PV with REGISTER-RESIDENT P
// (S-accumulator fragments repacked as PV A-operands — no P smem, no syncwarp).
// Double-buffered K/V + register prefetch -> ONE __syncthreads per iter.
// SMEM 80KB: Q 32K @0 | K[2] 2x16K @32768 | V[2] 2x8K @65536. 2 CTAs/SM.
// grid = (S/128, BH)
// ---------------------------------------------------------------------------
#define ATT_SMEM 81920

__global__ __launch_bounds__(256, 2) void attn_kernel()
{
    extern __shared__ char smc[];
    uint4* Qsm = (uint4*)smc;
    uint4* Ksm = (uint4*)(smc + 32768);     // 2 x 1024 uint4
    uint2* Vsm = (uint2*)(smc + 65536);     // 2 x 1024 uint2

    const int tid = threadIdx.x;
    const int lane = tid & 31;
    const int warp = tid >> 5;
    const int g = lane >> 2;
    const int tg = lane & 3;
    const int rbase = warp * 16;
    const int bh = blockIdx.y;
    const int q0 = blockIdx.x * 128;
    const int rA = rbase + g, rB = rA + 8;

    // ---- Q tile: pure copy ----
#pragma unroll
    for (int it = 0; it < 8; it++) {
        int slot = tid + it * 256;
        int j = slot & 3;
        int row = (slot >> 2) & 127;
        int cc = slot >> 9;
        Qsm[slot] = gQs[(((size_t)(bh * 4 + cc) * 2048) + q0 + row) * 4 + j];
    }
    // ---- preload K/V tile 0 into buffer 0 ----
#pragma unroll
    for (int it = 0; it < 4; it++) {
        int slot = tid + it * 256;
        int j = slot & 3;
        int key = (slot >> 2) & 63;
        int cc = slot >> 8;
        Ksm[slot] = gKs[(((size_t)(bh * 4 + cc) * 2048) + key) * 4 + j];
        Vsm[slot] = gVs[((size_t)bh * 128) * 256 + slot];
    }
    __syncthreads();

    float m0 = -1e30f, m1 = -1e30f, l0 = 0.f, l1 = 0.f;
    float oacc[8][4];
#pragma unroll
    for (int nf = 0; nf < 8; nf++)
#pragma unroll
        for (int c = 0; c < 4; c++) oacc[nf][c] = 0.f;

    for (int kb = 0; kb < 32; kb++) {
        const int buf = kb & 1;
        const uint4* Kb = Ksm + buf * 1024;
        const uint2* Vb = Vsm + buf * 1024;

        // prefetch next tile into registers (hidden under MMAs)
        uint4 kreg[4];
        uint2 vreg[4];
        if (kb < 31) {
#pragma unroll
            for (int it = 0; it < 4; it++) {
                int slot = tid + it * 256;
                int j = slot & 3;
                int key = (slot >> 2) & 63;
                int cc = slot >> 8;
                kreg[it] = gKs[(((size_t)(bh * 4 + cc) * 2048) + (kb + 1) * 64 + key) * 4 + j];
                vreg[it] = gVs[((size_t)bh * 128 + (kb + 1) * 4) * 256 + slot];
            }
        }

        // ---- S = (Q/8) K^T  (f16 3-pass) ----
        float sacc[8][4];
#pragma unroll
        for (int nf = 0; nf < 8; nf++)
#pragma unroll
            for (int c = 0; c < 4; c++) sacc[nf][c] = 0.f;

#pragma unroll 2
        for (int cc = 0; cc < 4; cc++) {
            uint4 qa = Qsm[(((cc << 7) + rA) << 2) + tg];
            uint4 qb = Qsm[(((cc << 7) + rB) << 2) + tg];
#pragma unroll
            for (int nf = 0; nf < 8; nf++) {
                uint4 kv = Kb[(((cc << 6) + nf * 8 + g) << 2) + tg];
                mma16(sacc[nf], qa.x, qb.x, qa.y, qb.y, kv.x, kv.y);
                mma16(sacc[nf], qa.z, qb.z, qa.w, qb.w, kv.x, kv.y);
                mma16(sacc[nf], qa.x, qb.x, qa.y, qb.y, kv.z, kv.w);
            }
        }

        // ---- online softmax (MUFU exp), pack P into registers ----
        float mx0 = -1e30f, mx1 = -1e30f;
#pragma unroll
        for (int nf = 0; nf < 8; nf++) {
            mx0 = fmaxf(mx0, fmaxf(sacc[nf][0], sacc[nf][1]));
            mx1 = fmaxf(mx1, fmaxf(sacc[nf][2], sacc[nf][3]));
        }
        mx0 = fmaxf(mx0, __shfl_xor_sync(0xffffffffu, mx0, 1));
        mx0 = fmaxf(mx0, __shfl_xor_sync(0xffffffffu, mx0, 2));
        mx1 = fmaxf(mx1, __shfl_xor_sync(0xffffffffu, mx1, 1));
        mx1 = fmaxf(mx1, __shfl_xor_sync(0xffffffffu, mx1, 2));
        float mn0 = fmaxf(m0, mx0), mn1 = fmaxf(m1, mx1);
        float corr0 = __expf(m0 - mn0), corr1 = __expf(m1 - mn1);
        m0 = mn0; m1 = mn1;

        uint32_t pk[8][2];
        float sum0 = 0.f, sum1 = 0.f;
#pragma unroll
        for (int nf = 0; nf < 8; nf++) {
            float p0 = __expf(sacc[nf][0] - mn0);
            float p1 = __expf(sacc[nf][1] - mn0);
            float p2 = __expf(sacc[nf][2] - mn1);
            float p3 = __expf(sacc[nf][3] - mn1);
            sum0 += p0 + p1; sum1 += p2 + p3;
            pk[nf][0] = packh(p0, p1);   // row rA, keys nf*8+2tg,+1
            pk[nf][1] = packh(p2, p3);   // row rB
            oacc[nf][0] *= corr0; oacc[nf][1] *= corr0;
            oacc[nf][2] *= corr1; oacc[nf][3] *= corr1;
        }
        sum0 += __shfl_xor_sync(0xffffffffu, sum0, 1);
        sum0 += __shfl_xor_sync(0xffffffffu, sum0, 2);
        sum1 += __shfl_xor_sync(0xffffffffu, sum1, 1);
        sum1 += __shfl_xor_sync(0xffffffffu, sum1, 2);
        l0 = l0 * corr0 + sum0;
        l1 = l1 * corr1 + sum1;

        // ---- O += P V  (P from registers: acc-fragment == A-fragment) ----
#pragma unroll
        for (int cc = 0; cc < 4; cc++) {
            uint32_t a0 = pk[2 * cc][0];       // rA, k-lo
            uint32_t a1 = pk[2 * cc][1];       // rB, k-lo
            uint32_t a2 = pk[2 * cc + 1][0];   // rA, k-hi
            uint32_t a3 = pk[2 * cc + 1][1];   // rB, k-hi
#pragma unroll
            for (int nf = 0; nf < 8; nf++) {
                uint2 vv = Vb[(((cc << 6) + nf * 8 + g) << 2) + tg];
                mma16(oacc[nf], a0, a1, a2, a3, vv.x, vv.y);
            }
        }

        // ---- store prefetched tile into the other buffer, single barrier ----
        if (kb < 31) {
#pragma unroll
            for (int it = 0; it < 4; it++) {
                int slot = tid + it * 256;
                Ksm[(buf ^ 1) * 1024 + slot] = kreg[it];
                Vsm[(buf ^ 1) * 1024 + slot] = vreg[it];
            }
        }
        __syncthreads();
    }

    // ---- epilogue: normalize + write split ctx image ----
    float inv0 = 1.f / l0, inv1 = 1.f / l1;
    uint32_t* Cimg = (uint32_t*)gCs;
    const int h = bh & 15, b = bh >> 4;
#pragma unroll
    for (int nf = 0; nf < 8; nf++) {
        int cc = h * 4 + (nf >> 1);
        int p = ((nf & 1) << 2) + tg;
        int ih = ((p & 3) << 2) + (p >> 2);
        uint32_t hi, lo;
        size_t baseA = ((size_t)cc * 4096 + b * 2048 + q0 + rA) * 16;
        split2h(oacc[nf][0] * inv0, oacc[nf][1] * inv0, hi, lo);
        Cimg[baseA + ih] = hi; Cimg[baseA + ih + 2] = lo;
        size_t baseB = ((size_t)cc * 4096 + b * 2048 + q0 + rB) * 16;
        split2h(oacc[nf][2] * inv1, oacc[nf][3] * inv1, hi, lo);
        Cimg[baseB + ih] = hi; Cimg[baseB + ih + 2] = lo;
    }
}

// ---------------------------------------------------------------------------
// Output projection: f16x2 GEMM from gCs x gWos
// ---------------------------------------------------------------------------
__global__ __launch_bounds__(256, 2) void oproj_f16(
    const float* __restrict__ bo, float* __restrict__ out)
{
    extern __shared__ char smc[];
    uint4* Ab = (uint4*)smc;
    uint4* Bb = (uint4*)(smc + 32768);

    const int tid = threadIdx.x;
    const int lane = tid & 31;
    const int warp = tid >> 5;
    const int g = lane >> 2;
    const int tg = lane & 3;
    const int wm = (warp >> 1) * 32;
    const int wn = (warp & 1) * 32;

    const int m0 = blockIdx.x * 128;
    const int n0 = blockIdx.y * 64;

    float acc[2][4][4];
#pragma unroll
    for (int mf = 0; mf < 2; mf++)
#pragma unroll
        for (int nf = 0; nf < 4; nf++)
#pragma unroll
            for (int c = 0; c < 4; c++) acc[mf][nf][c] = 0.f;

    uint4 ar[4], br[2];
    auto ldg = [&](int kc) {
        int cc0 = kc * 2;
#pragma unroll
        for (int it = 0; it < 4; it++) {
            int slot = tid + it * 256;
            int cc = slot >> 9;
            int row = (slot >> 2) & 127;
            int j = slot & 3;
            ar[it] = gCs[(((size_t)(cc0 + cc) * 4096) + m0 + row) * 4 + j];
        }
#pragma unroll
        for (int it = 0; it < 2; it++) {
            int slot = tid + it * 256;
            int cc = slot >> 8;
            int d = (slot >> 2) & 63;
            int j = slot & 3;
            br[it] = gWos[(((size_t)(cc0 + cc) * 1024) + n0 + d) * 4 + j];
        }
    };
    auto sts = [&](int buf) {
#pragma unroll
        for (int it = 0; it < 4; it++) Ab[buf * 1024 + tid + it * 256] = ar[it];
#pragma unroll
        for (int it = 0; it < 2; it++) Bb[buf * 512 + tid + it * 256] = br[it];
    };

    ldg(0);
    sts(0);
    __syncthreads();

    for (int kc = 0; kc < 32; kc++) {
        const int buf = kc & 1;
        if (kc < 31) ldg(kc + 1);

#pragma unroll
        for (int cc = 0; cc < 2; cc++) {
            const uint4* Ac = Ab + buf * 1024 + cc * 512;
            const uint4* Bc = Bb + buf * 512 + cc * 256;
            uint4 a0 = Ac[(wm + g) * 4 + tg];
            uint4 a1 = Ac[(wm + g + 8) * 4 + tg];
            uint4 a2 = Ac[(wm + 16 + g) * 4 + tg];
            uint4 a3 = Ac[(wm + 16 + g + 8) * 4 + tg];
            uint4 bv4[4];
#pragma unroll
            for (int nf = 0; nf < 4; nf++)
                bv4[nf] = Bc[(wn + nf * 8 + g) * 4 + tg];
#pragma unroll
            for (int nf = 0; nf < 4; nf++) {
                mma16(acc[0][nf], a0.x, a1.x, a0.y, a1.y, bv4[nf].x, bv4[nf].y);
                mma16(acc[1][nf], a2.x, a3.x, a2.y, a3.y, bv4[nf].x, bv4[nf].y);
                mma16(acc[0][nf], a0.z, a1.z, a0.w, a1.w, bv4[nf].x, bv4[nf].y);
                mma16(acc[1][nf], a2.z, a3.z, a2.w, a3.w, bv4[nf].x, bv4[nf].y);
            }
        }
        if (kc < 31) sts(buf ^ 1);
        __syncthreads();
    }

    const float* bi = bo + n0;
#pragma unroll
    for (int mf = 0; mf < 2; mf++) {
#pragma unroll
        for (int nf = 0; nf < 4; nf++) {
            int col = wn + nf * 8 + 2 * tg;
            float bx = bi[col], by = bi[col + 1];
            int r0 = wm + mf * 16 + g;
            *(float2*)(out + (size_t)(m0 + r0) * E_ + n0 + col) =
                make_float2(acc[mf][nf][0] + bx, acc[mf][nf][1] + by);
            *(float2*)(out + (size_t)(m0 + r0 + 8) * E_ + n0 + col) =
                make_float2(acc[mf][nf][2] + bx, acc[mf][nf][3] + by);
        }
    }
}

// ---------------------------------------------------------------------------
extern "C" void kernel_launch(void* const* d_in, const int* in_sizes, int n_in,
                              void* d_out, int out_size)
{
    const float* q  = (const float*)d_in[0];
    const float* k  = (const float*)d_in[1];
    const float* v  = (const float*)d_in[2];
    const float* Wq = (const float*)d_in[3];
    const float* Wk = (const float*)d_in[4];
    const float* Wv = (const float*)d_in[5];
    const float* bq = (const float*)d_in[6];
    const float* bk = (const float*)d_in[7];
    const float* bv = (const float*)d_in[8];
    const float* Wo = (const float*)d_in[9];
    const float* bo = (const float*)d_in[10];
    float* out = (float*)d_out;

    cudaFuncSetAttribute(proj_all, cudaFuncAttributeMaxDynamicSharedMemorySize, PROJ_SMEM);
    cudaFuncSetAttribute(oproj_f16, cudaFuncAttributeMaxDynamicSharedMemorySize, PROJ_SMEM);
    cudaFuncSetAttribute(attn_kernel, cudaFuncAttributeMaxDynamicSharedMemorySize, ATT_SMEM);

    split_all<<<16384, 256>>>(q, k, v, Wq, Wk, Wv, Wo);
    proj_all<<<dim3(S_ / 128, BH_, 3), 256, PROJ_SMEM>>>(bq, bk, bv);
    attn_kernel<<<dim3(S_ / 128, BH_), 256, ATT_SMEM>>>();
    oproj_f16<<<dim3((B_ * S_) / 128, E_ / 64), 256, PROJ_SMEM>>>(bo, out);
}

// round 15
// speedup vs baseline: 4.0788x; 1.0643x over previous
#include <cuda_runtime.h>
#include <cuda_fp16.h>
#include <stdint.h>
#include <math.h>

#define B_ 2
#define S_ 2048
#define E_ 1024
#define H_ 16
#define D_ 64
#define BH_ (B_*H_)

// ---- pre-split operand images ----
__device__ uint4 gXs[(size_t)3 * 2 * 64 * 2048 * 4];   // proj A: [z][b][cc][s][j]
__device__ uint4 gWs[(size_t)3 * 16 * 64 * 64 * 4];    // proj B: [z][h][cc][d][j]
__device__ uint4 gQs[(size_t)BH_ * 4 * 2048 * 4];      // Q*log2e/8 split: [bh][cc][s][j]
__device__ uint4 gKs[(size_t)BH_ * 4 * 2048 * 4];      // K split:  [bh][cc][s][j]
__device__ uint2 gVs[(size_t)BH_ * 128 * 64 * 4];      // V^T f16:  [bh][kc][d][sl]
__device__ uint2 gCs[(size_t)64 * 4096 * 4];           // ctx hi-only: [cc][m][j]
__device__ uint2 gWos[(size_t)64 * 1024 * 4];          // Wo hi-only:  [cc][n][j]

// ---------------- f16 helpers ----------------
__device__ __forceinline__ void split2h(float x0, float x1, uint32_t& hi, uint32_t& lo) {
    __half h0 = __float2half_rn(x0), h1 = __float2half_rn(x1);
    float r0 = x0 - __half2float(h0), r1 = x1 - __half2float(h1);
    __half l0 = __float2half_rn(r0), l1 = __float2half_rn(r1);
    hi = (uint32_t)__half_as_ushort(h0) | ((uint32_t)__half_as_ushort(h1) << 16);
    lo = (uint32_t)__half_as_ushort(l0) | ((uint32_t)__half_as_ushort(l1) << 16);
}
__device__ __forceinline__ uint16_t hbits(float x) {
    __half h = __float2half_rn(x);
    return __half_as_ushort(h);
}
__device__ __forceinline__ uint32_t packh(float x0, float x1) {
    return (uint32_t)hbits(x0) | ((uint32_t)hbits(x1) << 16);
}
__device__ __forceinline__ float ex2(float x) {
    float r;
    asm("ex2.approx.ftz.f32 %0, %1;" : "=f"(r) : "f"(x));
    return r;
}
__device__ __forceinline__ void mma16(float* c,
                                      uint32_t a0, uint32_t a1, uint32_t a2, uint32_t a3,
                                      uint32_t b0, uint32_t b1) {
    asm volatile(
        "mma.sync.aligned.m16n8k16.row.col.f32.f16.f16.f32 "
        "{%0,%1,%2,%3}, {%4,%5,%6,%7}, {%8,%9}, {%0,%1,%2,%3};\n"
        : "+f"(c[0]), "+f"(c[1]), "+f"(c[2]), "+f"(c[3])
        : "r"(a0), "r"(a1), "r"(a2), "r"(a3), "r"(b0), "r"(b1));
}

// ---------------------------------------------------------------------------
// Merged pre-split kernel: X (12288 blks) | W (3072) | Wo (1024, hi-only)
// ---------------------------------------------------------------------------
__global__ __launch_bounds__(256) void split_all(
    const float* __restrict__ q, const float* __restrict__ k, const float* __restrict__ v,
    const float* __restrict__ Wq, const float* __restrict__ Wk, const float* __restrict__ Wv,
    const float* __restrict__ Wo)
{
    uint32_t bid = blockIdx.x;
    if (bid < 12288) {
        uint32_t t = bid * 256 + threadIdx.x;
        int j = t & 3;
        int s = (t >> 2) & 2047;
        int cc = (t >> 13) & 63;
        int b = (t >> 19) & 1;
        int z = t >> 20;
        const float* X = (z == 0) ? q : (z == 1) ? k : v;
        const float* row = X + ((size_t)b * S_ + s) * E_ + cc * 16;
        float x0 = row[2 * j], x1 = row[2 * j + 1];
        float x2 = row[8 + 2 * j], x3 = row[8 + 2 * j + 1];
        uint32_t hiA, loA, hiB, loB;
        split2h(x0, x1, hiA, loA);
        split2h(x2, x3, hiB, loB);
        gXs[t] = make_uint4(hiA, hiB, loA, loB);
    } else if (bid < 15360) {
        uint32_t t = (bid - 12288) * 256 + threadIdx.x;
        int j = t & 3;
        int d = (t >> 2) & 63;
        int cc = (t >> 8) & 63;
        int h = (t >> 14) & 15;
        int z = t >> 18;
        const float* W = (z == 0) ? Wq : (z == 1) ? Wk : Wv;
        const float* Wh = W + (size_t)h * E_ * D_;
        int e0 = cc * 16;
        float x0 = Wh[(size_t)(e0 + 2 * j) * D_ + d];
        float x1 = Wh[(size_t)(e0 + 2 * j + 1) * D_ + d];
        float x2 = Wh[(size_t)(e0 + 8 + 2 * j) * D_ + d];
        float x3 = Wh[(size_t)(e0 + 8 + 2 * j + 1) * D_ + d];
        uint32_t hiA, loA, hiB, loB;
        split2h(x0, x1, hiA, loA);
        split2h(x2, x3, hiB, loB);
        gWs[t] = make_uint4(hiA, hiB, loA, loB);
    } else {
        uint32_t t = (bid - 15360) * 256 + threadIdx.x;
        int j = t & 3;
        int n = (t >> 2) & 1023;
        int cc = t >> 12;
        int e0 = cc * 16;
        float x0 = Wo[(size_t)(e0 + 2 * j) * E_ + n];
        float x1 = Wo[(size_t)(e0 + 2 * j + 1) * E_ + n];
        float x2 = Wo[(size_t)(e0 + 8 + 2 * j) * E_ + n];
        float x3 = Wo[(size_t)(e0 + 8 + 2 * j + 1) * E_ + n];
        gWos[t] = make_uint2(packh(x0, x1), packh(x2, x3));
    }
}

// ---------------------------------------------------------------------------
// Merged f16 projection GEMM: blockIdx.z = mode (0:Q 1:K 2:V).
// z<2: 3-pass -> split images (Q pre-scaled by log2e/8); z=2: 2-pass -> V^T f16.
// ---------------------------------------------------------------------------
#define PROJ_SMEM 49152

__global__ __launch_bounds__(256, 2) void proj_all(
    const float* __restrict__ bq, const float* __restrict__ bk, const float* __restrict__ bv)
{
    extern __shared__ char smc[];
    uint4* Ab = (uint4*)smc;
    uint4* Bb = (uint4*)(smc + 32768);

    const int tid = threadIdx.x;
    const int lane = tid & 31;
    const int warp = tid >> 5;
    const int g = lane >> 2;
    const int tg = lane & 3;
    const int wm = (warp >> 1) * 32;
    const int wn = (warp & 1) * 32;

    const int z = blockIdx.z;
    const int bh = blockIdx.y;
    const int b = bh >> 4;
    const int h = bh & 15;
    const int s0 = blockIdx.x * 128;
    const float* bias = (z == 0) ? bq : (z == 1) ? bk : bv;

    const uint4* Xs = gXs + (((size_t)z * 2 + b) * 64) * 2048 * 4;
    const uint4* Ws = gWs + (((size_t)z * 16 + h) * 64) * 64 * 4;

    float acc[2][4][4];
#pragma unroll
    for (int mf = 0; mf < 2; mf++)
#pragma unroll
        for (int nf = 0; nf < 4; nf++)
#pragma unroll
            for (int c = 0; c < 4; c++) acc[mf][nf][c] = 0.f;

    uint4 ar[4], br[2];
    auto ldg = [&](int kc) {
        int cc0 = kc * 2;
#pragma unroll
        for (int it = 0; it < 4; it++) {
            int slot = tid + it * 256;
            int cc = slot >> 9;
            int row = (slot >> 2) & 127;
            int j = slot & 3;
            ar[it] = Xs[(((size_t)(cc0 + cc) * 2048) + s0 + row) * 4 + j];
        }
#pragma unroll
        for (int it = 0; it < 2; it++) {
            int slot = tid + it * 256;
            int cc = slot >> 8;
            int d = (slot >> 2) & 63;
            int j = slot & 3;
            br[it] = Ws[(((size_t)(cc0 + cc) * 64) + d) * 4 + j];
        }
    };
    auto sts = [&](int buf) {
#pragma unroll
        for (int it = 0; it < 4; it++) Ab[buf * 1024 + tid + it * 256] = ar[it];
#pragma unroll
        for (int it = 0; it < 2; it++) Bb[buf * 512 + tid + it * 256] = br[it];
    };

    ldg(0);
    sts(0);
    __syncthreads();

    const bool p3 = (z < 2);
    for (int kc = 0; kc < 32; kc++) {
        const int buf = kc & 1;
        if (kc < 31) ldg(kc + 1);

#pragma unroll
        for (int cc = 0; cc < 2; cc++) {
            const uint4* Ac = Ab + buf * 1024 + cc * 512;
            const uint4* Bc = Bb + buf * 512 + cc * 256;
            uint4 a0 = Ac[(wm + g) * 4 + tg];
            uint4 a1 = Ac[(wm + g + 8) * 4 + tg];
            uint4 a2 = Ac[(wm + 16 + g) * 4 + tg];
            uint4 a3 = Ac[(wm + 16 + g + 8) * 4 + tg];
            uint4 bv4[4];
#pragma unroll
            for (int nf = 0; nf < 4; nf++)
                bv4[nf] = Bc[(wn + nf * 8 + g) * 4 + tg];
#pragma unroll
            for (int nf = 0; nf < 4; nf++) {
                mma16(acc[0][nf], a0.x, a1.x, a0.y, a1.y, bv4[nf].x, bv4[nf].y);
                mma16(acc[1][nf], a2.x, a3.x, a2.y, a3.y, bv4[nf].x, bv4[nf].y);
                mma16(acc[0][nf], a0.z, a1.z, a0.w, a1.w, bv4[nf].x, bv4[nf].y);
                mma16(acc[1][nf], a2.z, a3.z, a2.w, a3.w, bv4[nf].x, bv4[nf].y);
            }
            if (p3) {
#pragma unroll
                for (int nf = 0; nf < 4; nf++) {
                    mma16(acc[0][nf], a0.x, a1.x, a0.y, a1.y, bv4[nf].z, bv4[nf].w);
                    mma16(acc[1][nf], a2.x, a3.x, a2.y, a3.y, bv4[nf].z, bv4[nf].w);
                }
            }
        }
        if (kc < 31) sts(buf ^ 1);
        __syncthreads();
    }

    const float* bi = bias + h * D_;
    if (z == 2) {
        uint16_t* Vh = (uint16_t*)gVs;
#pragma unroll
        for (int mf = 0; mf < 2; mf++) {
#pragma unroll
            for (int nf = 0; nf < 4; nf++) {
                int col = wn + nf * 8 + 2 * tg;
                float bx = bi[col], by = bi[col + 1];
#pragma unroll
                for (int rr = 0; rr < 2; rr++) {
                    int key = s0 + wm + mf * 16 + g + rr * 8;
                    int kc = key >> 4;
                    int kl = key & 15;
                    int p = kl >> 1, sl = p & 3, hf = p >> 2, w = kl & 1;
                    size_t base = ((((size_t)bh * 128 + kc) * 64));
                    Vh[((base + col) * 4 + sl) * 4 + hf * 2 + w] =
                        hbits(acc[mf][nf][rr * 2] + bx);
                    Vh[((base + col + 1) * 4 + sl) * 4 + hf * 2 + w] =
                        hbits(acc[mf][nf][rr * 2 + 1] + by);
                }
            }
        }
    } else {
        // Q is pre-scaled by log2e/8 so attention works in log2 domain.
        const float scale = (z == 0) ? 0.1803368801f : 1.0f;
        uint32_t* Gimg = (uint32_t*)((z == 0) ? gQs : gKs);
#pragma unroll
        for (int mf = 0; mf < 2; mf++) {
#pragma unroll
            for (int nf = 0; nf < 4; nf++) {
                int col = wn + nf * 8 + 2 * tg;
                float bx = bi[col], by = bi[col + 1];
                int cc = col >> 4;
                int p = (col & 15) >> 1;
                int ih = ((p & 3) << 2) + (p >> 2);
                int r0 = wm + mf * 16 + g;
                uint32_t hi, lo;
                size_t base0 = (((size_t)(bh * 4 + cc) * 2048) + s0 + r0) * 16;
                split2h((acc[mf][nf][0] + bx) * scale, (acc[mf][nf][1] + by) * scale, hi, lo);
                Gimg[base0 + ih] = hi; Gimg[base0 + ih + 2] = lo;
                split2h((acc[mf][nf][2] + bx) * scale, (acc[mf][nf][3] + by) * scale, hi, lo);
                Gimg[base0 + 128 + ih] = hi; Gimg[base0 + 128 + ih + 2] = lo;
            }
        }
    }
}

// ---------------------------------------------------------------------------
// Flash attention: f16x3 QK + f16x1 PV, register-resident P, log2-domain
// softmax (single EX2 per prob). Double-buffered K/V, one barrier/iter.
// SMEM 80KB. 2 CTAs/SM. grid = (S/128, BH)
// ---------------------------------------------------------------------------
#define ATT_SMEM 81920

__global__ __launch_bounds__(256, 2) void attn_kernel()
{
    extern __shared__ char smc[];
    uint4* Qsm = (uint4*)smc;
    uint4* Ksm = (uint4*)(smc + 32768);     // 2 x 1024 uint4
    uint2* Vsm = (uint2*)(smc + 65536);     // 2 x 1024 uint2

    const int tid = threadIdx.x;
    const int lane = tid & 31;
    const int warp = tid >> 5;
    const int g = lane >> 2;
    const int tg = lane & 3;
    const int bh = blockIdx.y;
    const int q0 = blockIdx.x * 128;
    const int rA = warp * 16 + g, rB = rA + 8;

    // ---- Q tile: pure copy ----
#pragma unroll
    for (int it = 0; it < 8; it++) {
        int slot = tid + it * 256;
        int j = slot & 3;
        int row = (slot >> 2) & 127;
        int cc = slot >> 9;
        Qsm[slot] = gQs[(((size_t)(bh * 4 + cc) * 2048) + q0 + row) * 4 + j];
    }
    // ---- preload K/V tile 0 ----
#pragma unroll
    for (int it = 0; it < 4; it++) {
        int slot = tid + it * 256;
        int j = slot & 3;
        int key = (slot >> 2) & 63;
        int cc = slot >> 8;
        Ksm[slot] = gKs[(((size_t)(bh * 4 + cc) * 2048) + key) * 4 + j];
        Vsm[slot] = gVs[((size_t)bh * 128) * 256 + slot];
    }
    __syncthreads();

    float m0 = -1e30f, m1 = -1e30f, l0 = 0.f, l1 = 0.f;
    float oacc[8][4];
#pragma unroll
    for (int nf = 0; nf < 8; nf++)
#pragma unroll
        for (int c = 0; c < 4; c++) oacc[nf][c] = 0.f;

    for (int kb = 0; kb < 32; kb++) {
        const int buf = kb & 1;
        const uint4* Kb = Ksm + buf * 1024;
        const uint2* Vb = Vsm + buf * 1024;

        uint4 kreg[4];
        uint2 vreg[4];
        if (kb < 31) {
#pragma unroll
            for (int it = 0; it < 4; it++) {
                int slot = tid + it * 256;
                int j = slot & 3;
                int key = (slot >> 2) & 63;
                int cc = slot >> 8;
                kreg[it] = gKs[(((size_t)(bh * 4 + cc) * 2048) + (kb + 1) * 64 + key) * 4 + j];
                vreg[it] = gVs[((size_t)bh * 128 + (kb + 1) * 4) * 256 + slot];
            }
        }

        // ---- S = Q K^T (log2-domain logits), f16 3-pass ----
        float sacc[8][4];
#pragma unroll
        for (int nf = 0; nf < 8; nf++)
#pragma unroll
            for (int c = 0; c < 4; c++) sacc[nf][c] = 0.f;

#pragma unroll 2
        for (int cc = 0; cc < 4; cc++) {
            uint4 qa = Qsm[(((cc << 7) + rA) << 2) + tg];
            uint4 qb = Qsm[(((cc << 7) + rB) << 2) + tg];
#pragma unroll
            for (int nf = 0; nf < 8; nf++) {
                uint4 kv = Kb[(((cc << 6) + nf * 8 + g) << 2) + tg];
                mma16(sacc[nf], qa.x, qb.x, qa.y, qb.y, kv.x, kv.y);
                mma16(sacc[nf], qa.z, qb.z, qa.w, qb.w, kv.x, kv.y);
                mma16(sacc[nf], qa.x, qb.x, qa.y, qb.y, kv.z, kv.w);
            }
        }

        // ---- online softmax (log2 domain, single EX2 per prob) ----
        float mx0 = -1e30f, mx1 = -1e30f;
#pragma unroll
        for (int nf = 0; nf < 8; nf++) {
            mx0 = fmaxf(mx0, fmaxf(sacc[nf][0], sacc[nf][1]));
            mx1 = fmaxf(mx1, fmaxf(sacc[nf][2], sacc[nf][3]));
        }
        mx0 = fmaxf(mx0, __shfl_xor_sync(0xffffffffu, mx0, 1));
        mx0 = fmaxf(mx0, __shfl_xor_sync(0xffffffffu, mx0, 2));
        mx1 = fmaxf(mx1, __shfl_xor_sync(0xffffffffu, mx1, 1));
        mx1 = fmaxf(mx1, __shfl_xor_sync(0xffffffffu, mx1, 2));
        float mn0 = fmaxf(m0, mx0), mn1 = fmaxf(m1, mx1);
        float corr0 = ex2(m0 - mn0), corr1 = ex2(m1 - mn1);
        m0 = mn0; m1 = mn1;

        uint32_t pk[8][2];
        float sum0 = 0.f, sum1 = 0.f;
#pragma unroll
        for (int nf = 0; nf < 8; nf++) {
            float p0 = ex2(sacc[nf][0] - mn0);
            float p1 = ex2(sacc[nf][1] - mn0);
            float p2 = ex2(sacc[nf][2] - mn1);
            float p3 = ex2(sacc[nf][3] - mn1);
            sum0 += p0 + p1; sum1 += p2 + p3;
            pk[nf][0] = packh(p0, p1);
            pk[nf][1] = packh(p2, p3);
            oacc[nf][0] *= corr0; oacc[nf][1] *= corr0;
            oacc[nf][2] *= corr1; oacc[nf][3] *= corr1;
        }
        sum0 += __shfl_xor_sync(0xffffffffu, sum0, 1);
        sum0 += __shfl_xor_sync(0xffffffffu, sum0, 2);
        sum1 += __shfl_xor_sync(0xffffffffu, sum1, 1);
        sum1 += __shfl_xor_sync(0xffffffffu, sum1, 2);
        l0 = l0 * corr0 + sum0;
        l1 = l1 * corr1 + sum1;

        // ---- O += P V  (P from registers) ----
#pragma unroll
        for (int cc = 0; cc < 4; cc++) {
            uint32_t a0 = pk[2 * cc][0];
            uint32_t a1 = pk[2 * cc][1];
            uint32_t a2 = pk[2 * cc + 1][0];
            uint32_t a3 = pk[2 * cc + 1][1];
#pragma unroll
            for (int nf = 0; nf < 8; nf++) {
                uint2 vv = Vb[(((cc << 6) + nf * 8 + g) << 2) + tg];
                mma16(oacc[nf], a0, a1, a2, a3, vv.x, vv.y);
            }
        }

        if (kb < 31) {
#pragma unroll
            for (int it = 0; it < 4; it++) {
                int slot = tid + it * 256;
                Ksm[(buf ^ 1) * 1024 + slot] = kreg[it];
                Vsm[(buf ^ 1) * 1024 + slot] = vreg[it];
            }
        }
        __syncthreads();
    }

    // ---- epilogue: normalize + write hi-only ctx image ----
    float inv0 = 1.f / l0, inv1 = 1.f / l1;
    uint32_t* Cimg = (uint32_t*)gCs;
    const int h = bh & 15, b = bh >> 4;
#pragma unroll
    for (int nf = 0; nf < 8; nf++) {
        int cc = h * 4 + (nf >> 1);
        int p = ((nf & 1) << 2) + tg;
        int ih = ((p & 3) << 1) + (p >> 2);
        size_t baseA = ((size_t)cc * 4096 + b * 2048 + q0 + rA) * 8;
        Cimg[baseA + ih] = packh(oacc[nf][0] * inv0, oacc[nf][1] * inv0);
        size_t baseB = ((size_t)cc * 4096 + b * 2048 + q0 + rB) * 8;
        Cimg[baseB + ih] = packh(oacc[nf][2] * inv1, oacc[nf][3] * inv1);
    }
}

// ---------------------------------------------------------------------------
// Output projection: f16 1-pass GEMM from hi-only gCs x gWos.
// SMEM 24KB (A 2x8KB + B 2x4KB), 3 CTAs/SM target.
// ---------------------------------------------------------------------------
#define OPROJ_SMEM 24576

__global__ __launch_bounds__(256, 3) void oproj_f16(
    const float* __restrict__ bo, float* __restrict__ out)
{
    extern __shared__ char smc[];
    uint2* Ab = (uint2*)smc;                 // [2][1024]
    uint2* Bb = (uint2*)(smc + 16384);       // [2][512]

    const int tid = threadIdx.x;
    const int lane = tid & 31;
    const int warp = tid >> 5;
    const int g = lane >> 2;
    const int tg = lane & 3;
    const int wm = (warp >> 1) * 32;
    const int wn = (warp & 1) * 32;

    const int m0 = blockIdx.x * 128;
    const int n0 = blockIdx.y * 64;

    float acc[2][4][4];
#pragma unroll
    for (int mf = 0; mf < 2; mf++)
#pragma unroll
        for (int nf = 0; nf < 4; nf++)
#pragma unroll
            for (int c = 0; c < 4; c++) acc[mf][nf][c] = 0.f;

    uint2 ar[4], br[2];
    auto ldg = [&](int kc) {
        int cc0 = kc * 2;
#pragma unroll
        for (int it = 0; it < 4; it++) {
            int slot = tid + it * 256;
            int cc = slot >> 9;
            int row = (slot >> 2) & 127;
            int j = slot & 3;
            ar[it] = gCs[(((size_t)(cc0 + cc) * 4096) + m0 + row) * 4 + j];
        }
#pragma unroll
        for (int it = 0; it < 2; it++) {
            int slot = tid + it * 256;
            int cc = slot >> 8;
            int d = (slot >> 2) & 63;
            int j = slot & 3;
            br[it] = gWos[(((size_t)(cc0 + cc) * 1024) + n0 + d) * 4 + j];
        }
    };
    auto sts = [&](int buf) {
#pragma unroll
        for (int it = 0; it < 4; it++) Ab[buf * 1024 + tid + it * 256] = ar[it];
#pragma unroll
        for (int it = 0; it < 2; it++) Bb[buf * 512 + tid + it * 256] = br[it];
    };

    ldg(0);
    sts(0);
    __syncthreads();

    for (int kc = 0; kc < 32; kc++) {
        const int buf = kc & 1;
        if (kc < 31) ldg(kc + 1);

#pragma unroll
        for (int cc = 0; cc < 2; cc++) {
            const uint2* Ac = Ab + buf * 1024 + cc * 512;
            const uint2* Bc = Bb + buf * 512 + cc * 256;
            uint2 au0 = Ac[(wm + g) * 4 + tg];
            uint2 av0 = Ac[(wm + g + 8) * 4 + tg];
            uint2 au1 = Ac[(wm + 16 + g) * 4 + tg];
            uint2 av1 = Ac[(wm + 16 + g + 8) * 4 + tg];
            uint2 bv2[4];
#pragma unroll
            for (int nf = 0; nf < 4; nf++)
                bv2[nf] = Bc[(wn + nf * 8 + g) * 4 + tg];
#pragma unroll
            for (int nf = 0; nf < 4; nf++) {
                mma16(acc[0][nf], au0.x, av0.x, au0.y, av0.y, bv2[nf].x, bv2[nf].y);
                mma16(acc[1][nf], au1.x, av1.x, au1.y, av1.y, bv2[nf].x, bv2[nf].y);
            }
        }
        if (kc < 31) sts(buf ^ 1);
        __syncthreads();
    }

    const float* bi = bo + n0;
#pragma unroll
    for (int mf = 0; mf < 2; mf++) {
#pragma unroll
        for (int nf = 0; nf < 4; nf++) {
            int col = wn + nf * 8 + 2 * tg;
            float bx = bi[col], by = bi[col + 1];
            int r0 = wm + mf * 16 + g;
            *(float2*)(out + (size_t)(m0 + r0) * E_ + n0 + col) =
                make_float2(acc[mf][nf][0] + bx, acc[mf][nf][1] + by);
            *(float2*)(out + (size_t)(m0 + r0 + 8) * E_ + n0 + col) =
                make_float2(acc[mf][nf][2] + bx, acc[mf][nf][3] + by);
        }
    }
}

// ---------------------------------------------------------------------------
extern "C" void kernel_launch(void* const* d_in, const int* in_sizes, int n_in,
                              void* d_out, int out_size)
{
    const float* q  = (const float*)d_in[0];
    const float* k  = (const float*)d_in[1];
    const float* v  = (const float*)d_in[2];
    const float* Wq = (const float*)d_in[3];
    const float* Wk = (const float*)d_in[4];
    const float* Wv = (const float*)d_in[5];
    const float* bq = (const float*)d_in[6];
    const float* bk = (const float*)d_in[7];
    const float* bv = (const float*)d_in[8];
    const float* Wo = (const float*)d_in[9];
    const float* bo = (const float*)d_in[10];
    float* out = (float*)d_out;

    cudaFuncSetAttribute(proj_all, cudaFuncAttributeMaxDynamicSharedMemorySize, PROJ_SMEM);
    cudaFuncSetAttribute(oproj_f16, cudaFuncAttributeMaxDynamicSharedMemorySize, OPROJ_SMEM);
    cudaFuncSetAttribute(attn_kernel, cudaFuncAttributeMaxDynamicSharedMemorySize, ATT_SMEM);

    split_all<<<16384, 256>>>(q, k, v, Wq, Wk, Wv, Wo);
    proj_all<<<dim3(S_ / 128, BH_, 3), 256, PROJ_SMEM>>>(bq, bk, bv);
    attn_kernel<<<dim3(S_ / 128, BH_), 256, ATT_SMEM>>>();
    oproj_f16<<<dim3((B_ * S_) / 128, E_ / 64), 256, OPROJ_SMEM>>>(bo, out);
}

// round 16
// speedup vs baseline: 4.1970x; 1.0290x over previous
#include <cuda_runtime.h>
#include <cuda_fp16.h>
#include <stdint.h>
#include <math.h>

#define B_ 2
#define S_ 2048
#define E_ 1024
#define H_ 16
#define D_ 64
#define BH_ (B_*H_)

// ---- pre-split operand images ----
__device__ uint4 gXs[(size_t)3 * 2 * 64 * 2048 * 4];   // proj A: [z][b][cc][s][j]
__device__ uint4 gWs[(size_t)3 * 16 * 64 * 64 * 4];    // proj B: [z][h][cc][d][j]
__device__ uint4 gQs[(size_t)BH_ * 4 * 2048 * 4];      // Q*log2e/8 split: [bh][cc][s][j]
__device__ uint4 gKs[(size_t)BH_ * 4 * 2048 * 4];      // K split:  [bh][cc][s][j]
__device__ uint2 gVs[(size_t)BH_ * 128 * 64 * 4];      // V^T f16:  [bh][kc][d][sl]
__device__ uint2 gCs[(size_t)64 * 4096 * 4];           // ctx hi-only: [cc][m][j]
__device__ uint2 gWos[(size_t)64 * 1024 * 4];          // Wo hi-only:  [cc][n][j]

// ---------------- f16 helpers ----------------
__device__ __forceinline__ void split2h(float x0, float x1, uint32_t& hi, uint32_t& lo) {
    __half h0 = __float2half_rn(x0), h1 = __float2half_rn(x1);
    float r0 = x0 - __half2float(h0), r1 = x1 - __half2float(h1);
    __half l0 = __float2half_rn(r0), l1 = __float2half_rn(r1);
    hi = (uint32_t)__half_as_ushort(h0) | ((uint32_t)__half_as_ushort(h1) << 16);
    lo = (uint32_t)__half_as_ushort(l0) | ((uint32_t)__half_as_ushort(l1) << 16);
}
__device__ __forceinline__ uint16_t hbits(float x) {
    __half h = __float2half_rn(x);
    return __half_as_ushort(h);
}
__device__ __forceinline__ uint32_t packh(float x0, float x1) {
    return (uint32_t)hbits(x0) | ((uint32_t)hbits(x1) << 16);
}
__device__ __forceinline__ float ex2(float x) {
    float r;
    asm("ex2.approx.ftz.f32 %0, %1;" : "=f"(r) : "f"(x));
    return r;
}
__device__ __forceinline__ void mma16(float* c,
                                      uint32_t a0, uint32_t a1, uint32_t a2, uint32_t a3,
                                      uint32_t b0, uint32_t b1) {
    asm volatile(
        "mma.sync.aligned.m16n8k16.row.col.f32.f16.f16.f32 "
        "{%0,%1,%2,%3}, {%4,%5,%6,%7}, {%8,%9}, {%0,%1,%2,%3};\n"
        : "+f"(c[0]), "+f"(c[1]), "+f"(c[2]), "+f"(c[3])
        : "r"(a0), "r"(a1), "r"(a2), "r"(a3), "r"(b0), "r"(b1));
}

// ---------------------------------------------------------------------------
// Merged pre-split kernel: X (12288 blks) | W (3072) | Wo (1024, hi-only)
// ---------------------------------------------------------------------------
__global__ __launch_bounds__(256) void split_all(
    const float* __restrict__ q, const float* __restrict__ k, const float* __restrict__ v,
    const float* __restrict__ Wq, const float* __restrict__ Wk, const float* __restrict__ Wv,
    const float* __restrict__ Wo)
{
    uint32_t bid = blockIdx.x;
    if (bid < 12288) {
        uint32_t t = bid * 256 + threadIdx.x;
        int j = t & 3;
        int s = (t >> 2) & 2047;
        int cc = (t >> 13) & 63;
        int b = (t >> 19) & 1;
        int z = t >> 20;
        const float* X = (z == 0) ? q : (z == 1) ? k : v;
        const float* row = X + ((size_t)b * S_ + s) * E_ + cc * 16;
        float x0 = row[2 * j], x1 = row[2 * j + 1];
        float x2 = row[8 + 2 * j], x3 = row[8 + 2 * j + 1];
        uint32_t hiA, loA, hiB, loB;
        split2h(x0, x1, hiA, loA);
        split2h(x2, x3, hiB, loB);
        gXs[t] = make_uint4(hiA, hiB, loA, loB);
    } else if (bid < 15360) {
        uint32_t t = (bid - 12288) * 256 + threadIdx.x;
        int j = t & 3;
        int d = (t >> 2) & 63;
        int cc = (t >> 8) & 63;
        int h = (t >> 14) & 15;
        int z = t >> 18;
        const float* W = (z == 0) ? Wq : (z == 1) ? Wk : Wv;
        const float* Wh = W + (size_t)h * E_ * D_;
        int e0 = cc * 16;
        float x0 = Wh[(size_t)(e0 + 2 * j) * D_ + d];
        float x1 = Wh[(size_t)(e0 + 2 * j + 1) * D_ + d];
        float x2 = Wh[(size_t)(e0 + 8 + 2 * j) * D_ + d];
        float x3 = Wh[(size_t)(e0 + 8 + 2 * j + 1) * D_ + d];
        uint32_t hiA, loA, hiB, loB;
        split2h(x0, x1, hiA, loA);
        split2h(x2, x3, hiB, loB);
        gWs[t] = make_uint4(hiA, hiB, loA, loB);
    } else {
        uint32_t t = (bid - 15360) * 256 + threadIdx.x;
        int j = t & 3;
        int n = (t >> 2) & 1023;
        int cc = t >> 12;
        int e0 = cc * 16;
        float x0 = Wo[(size_t)(e0 + 2 * j) * E_ + n];
        float x1 = Wo[(size_t)(e0 + 2 * j + 1) * E_ + n];
        float x2 = Wo[(size_t)(e0 + 8 + 2 * j) * E_ + n];
        float x3 = Wo[(size_t)(e0 + 8 + 2 * j + 1) * E_ + n];
        gWos[t] = make_uint2(packh(x0, x1), packh(x2, x3));
    }
}

// ---------------------------------------------------------------------------
// Merged f16 projection GEMM: blockIdx.z = mode (0:Q 1:K 2:V).
// z<2: 3-pass -> split images (Q pre-scaled by log2e/8); z=2: 1-PASS -> V^T f16
// (V stored f16 anyway; 2nd pass refines below storage quantization noise).
// ---------------------------------------------------------------------------
#define PROJ_SMEM 49152

__global__ __launch_bounds__(256, 2) void proj_all(
    const float* __restrict__ bq, const float* __restrict__ bk, const float* __restrict__ bv)
{
    extern __shared__ char smc[];
    uint4* Ab = (uint4*)smc;
    uint4* Bb = (uint4*)(smc + 32768);

    const int tid = threadIdx.x;
    const int lane = tid & 31;
    const int warp = tid >> 5;
    const int g = lane >> 2;
    const int tg = lane & 3;
    const int wm = (warp >> 1) * 32;
    const int wn = (warp & 1) * 32;

    const int z = blockIdx.z;
    const int bh = blockIdx.y;
    const int b = bh >> 4;
    const int h = bh & 15;
    const int s0 = blockIdx.x * 128;
    const float* bias = (z == 0) ? bq : (z == 1) ? bk : bv;

    const uint4* Xs = gXs + (((size_t)z * 2 + b) * 64) * 2048 * 4;
    const uint4* Ws = gWs + (((size_t)z * 16 + h) * 64) * 64 * 4;

    float acc[2][4][4];
#pragma unroll
    for (int mf = 0; mf < 2; mf++)
#pragma unroll
        for (int nf = 0; nf < 4; nf++)
#pragma unroll
            for (int c = 0; c < 4; c++) acc[mf][nf][c] = 0.f;

    uint4 ar[4], br[2];
    auto ldg = [&](int kc) {
        int cc0 = kc * 2;
#pragma unroll
        for (int it = 0; it < 4; it++) {
            int slot = tid + it * 256;
            int cc = slot >> 9;
            int row = (slot >> 2) & 127;
            int j = slot & 3;
            ar[it] = Xs[(((size_t)(cc0 + cc) * 2048) + s0 + row) * 4 + j];
        }
#pragma unroll
        for (int it = 0; it < 2; it++) {
            int slot = tid + it * 256;
            int cc = slot >> 8;
            int d = (slot >> 2) & 63;
            int j = slot & 3;
            br[it] = Ws[(((size_t)(cc0 + cc) * 64) + d) * 4 + j];
        }
    };
    auto sts = [&](int buf) {
#pragma unroll
        for (int it = 0; it < 4; it++) Ab[buf * 1024 + tid + it * 256] = ar[it];
#pragma unroll
        for (int it = 0; it < 2; it++) Bb[buf * 512 + tid + it * 256] = br[it];
    };

    ldg(0);
    sts(0);
    __syncthreads();

    const bool p3 = (z < 2);
    for (int kc = 0; kc < 32; kc++) {
        const int buf = kc & 1;
        if (kc < 31) ldg(kc + 1);

#pragma unroll
        for (int cc = 0; cc < 2; cc++) {
            const uint4* Ac = Ab + buf * 1024 + cc * 512;
            const uint4* Bc = Bb + buf * 512 + cc * 256;
            uint4 a0 = Ac[(wm + g) * 4 + tg];
            uint4 a1 = Ac[(wm + g + 8) * 4 + tg];
            uint4 a2 = Ac[(wm + 16 + g) * 4 + tg];
            uint4 a3 = Ac[(wm + 16 + g + 8) * 4 + tg];
            uint4 bv4[4];
#pragma unroll
            for (int nf = 0; nf < 4; nf++)
                bv4[nf] = Bc[(wn + nf * 8 + g) * 4 + tg];
#pragma unroll
            for (int nf = 0; nf < 4; nf++) {
                mma16(acc[0][nf], a0.x, a1.x, a0.y, a1.y, bv4[nf].x, bv4[nf].y);
                mma16(acc[1][nf], a2.x, a3.x, a2.y, a3.y, bv4[nf].x, bv4[nf].y);
            }
            if (p3) {
#pragma unroll
                for (int nf = 0; nf < 4; nf++) {
                    mma16(acc[0][nf], a0.z, a1.z, a0.w, a1.w, bv4[nf].x, bv4[nf].y);
                    mma16(acc[1][nf], a2.z, a3.z, a2.w, a3.w, bv4[nf].x, bv4[nf].y);
                    mma16(acc[0][nf], a0.x, a1.x, a0.y, a1.y, bv4[nf].z, bv4[nf].w);
                    mma16(acc[1][nf], a2.x, a3.x, a2.y, a3.y, bv4[nf].z, bv4[nf].w);
                }
            }
        }
        if (kc < 31) sts(buf ^ 1);
        __syncthreads();
    }

    const float* bi = bias + h * D_;
    if (z == 2) {
        uint16_t* Vh = (uint16_t*)gVs;
#pragma unroll
        for (int mf = 0; mf < 2; mf++) {
#pragma unroll
            for (int nf = 0; nf < 4; nf++) {
                int col = wn + nf * 8 + 2 * tg;
                float bx = bi[col], by = bi[col + 1];
#pragma unroll
                for (int rr = 0; rr < 2; rr++) {
                    int key = s0 + wm + mf * 16 + g + rr * 8;
                    int kc = key >> 4;
                    int kl = key & 15;
                    int p = kl >> 1, sl = p & 3, hf = p >> 2, w = kl & 1;
                    size_t base = ((((size_t)bh * 128 + kc) * 64));
                    Vh[((base + col) * 4 + sl) * 4 + hf * 2 + w] =
                        hbits(acc[mf][nf][rr * 2] + bx);
                    Vh[((base + col + 1) * 4 + sl) * 4 + hf * 2 + w] =
                        hbits(acc[mf][nf][rr * 2 + 1] + by);
                }
            }
        }
    } else {
        // Q pre-scaled by log2e/8 so attention works in log2 domain.
        const float scale = (z == 0) ? 0.1803368801f : 1.0f;
        uint32_t* Gimg = (uint32_t*)((z == 0) ? gQs : gKs);
#pragma unroll
        for (int mf = 0; mf < 2; mf++) {
#pragma unroll
            for (int nf = 0; nf < 4; nf++) {
                int col = wn + nf * 8 + 2 * tg;
                float bx = bi[col], by = bi[col + 1];
                int cc = col >> 4;
                int p = (col & 15) >> 1;
                int ih = ((p & 3) << 2) + (p >> 2);
                int r0 = wm + mf * 16 + g;
                uint32_t hi, lo;
                size_t base0 = (((size_t)(bh * 4 + cc) * 2048) + s0 + r0) * 16;
                split2h((acc[mf][nf][0] + bx) * scale, (acc[mf][nf][1] + by) * scale, hi, lo);
                Gimg[base0 + ih] = hi; Gimg[base0 + ih + 2] = lo;
                split2h((acc[mf][nf][2] + bx) * scale, (acc[mf][nf][3] + by) * scale, hi, lo);
                Gimg[base0 + 128 + ih] = hi; Gimg[base0 + 128 + ih + 2] = lo;
            }
        }
    }
}

// ---------------------------------------------------------------------------
// Flash attention: f16x3 QK + f16x1 PV, register-resident P, log2-domain
// softmax. Double-buffered K/V, one barrier/iter. (round-15, passing)
// ---------------------------------------------------------------------------
#define ATT_SMEM 81920

__global__ __launch_bounds__(256, 2) void attn_kernel()
{
    extern __shared__ char smc[];
    uint4* Qsm = (uint4*)smc;
    uint4* Ksm = (uint4*)(smc + 32768);
    uint2* Vsm = (uint2*)(smc + 65536);

    const int tid = threadIdx.x;
    const int lane = tid & 31;
    const int warp = tid >> 5;
    const int g = lane >> 2;
    const int tg = lane & 3;
    const int bh = blockIdx.y;
    const int q0 = blockIdx.x * 128;
    const int rA = warp * 16 + g, rB = rA + 8;

#pragma unroll
    for (int it = 0; it < 8; it++) {
        int slot = tid + it * 256;
        int j = slot & 3;
        int row = (slot >> 2) & 127;
        int cc = slot >> 9;
        Qsm[slot] = gQs[(((size_t)(bh * 4 + cc) * 2048) + q0 + row) * 4 + j];
    }
#pragma unroll
    for (int it = 0; it < 4; it++) {
        int slot = tid + it * 256;
        int j = slot & 3;
        int key = (slot >> 2) & 63;
        int cc = slot >> 8;
        Ksm[slot] = gKs[(((size_t)(bh * 4 + cc) * 2048) + key) * 4 + j];
        Vsm[slot] = gVs[((size_t)bh * 128) * 256 + slot];
    }
    __syncthreads();

    float m0 = -1e30f, m1 = -1e30f, l0 = 0.f, l1 = 0.f;
    float oacc[8][4];
#pragma unroll
    for (int nf = 0; nf < 8; nf++)
#pragma unroll
        for (int c = 0; c < 4; c++) oacc[nf][c] = 0.f;

    for (int kb = 0; kb < 32; kb++) {
        const int buf = kb & 1;
        const uint4* Kb = Ksm + buf * 1024;
        const uint2* Vb = Vsm + buf * 1024;

        uint4 kreg[4];
        uint2 vreg[4];
        if (kb < 31) {
#pragma unroll
            for (int it = 0; it < 4; it++) {
                int slot = tid + it * 256;
                int j = slot & 3;
                int key = (slot >> 2) & 63;
                int cc = slot >> 8;
                kreg[it] = gKs[(((size_t)(bh * 4 + cc) * 2048) + (kb + 1) * 64 + key) * 4 + j];
                vreg[it] = gVs[((size_t)bh * 128 + (kb + 1) * 4) * 256 + slot];
            }
        }

        float sacc[8][4];
#pragma unroll
        for (int nf = 0; nf < 8; nf++)
#pragma unroll
            for (int c = 0; c < 4; c++) sacc[nf][c] = 0.f;

#pragma unroll 2
        for (int cc = 0; cc < 4; cc++) {
            uint4 qa = Qsm[(((cc << 7) + rA) << 2) + tg];
            uint4 qb = Qsm[(((cc << 7) + rB) << 2) + tg];
#pragma unroll
            for (int nf = 0; nf < 8; nf++) {
                uint4 kv = Kb[(((cc << 6) + nf * 8 + g) << 2) + tg];
                mma16(sacc[nf], qa.x, qb.x, qa.y, qb.y, kv.x, kv.y);
                mma16(sacc[nf], qa.z, qb.z, qa.w, qb.w, kv.x, kv.y);
                mma16(sacc[nf], qa.x, qb.x, qa.y, qb.y, kv.z, kv.w);
            }
        }

        float mx0 = -1e30f, mx1 = -1e30f;
#pragma unroll
        for (int nf = 0; nf < 8; nf++) {
            mx0 = fmaxf(mx0, fmaxf(sacc[nf][0], sacc[nf][1]));
            mx1 = fmaxf(mx1, fmaxf(sacc[nf][2], sacc[nf][3]));
        }
        mx0 = fmaxf(mx0, __shfl_xor_sync(0xffffffffu, mx0, 1));
        mx0 = fmaxf(mx0, __shfl_xor_sync(0xffffffffu, mx0, 2));
        mx1 = fmaxf(mx1, __shfl_xor_sync(0xffffffffu, mx1, 1));
        mx1 = fmaxf(mx1, __shfl_xor_sync(0xffffffffu, mx1, 2));
        float mn0 = fmaxf(m0, mx0), mn1 = fmaxf(m1, mx1);
        float corr0 = ex2(m0 - mn0), corr1 = ex2(m1 - mn1);
        m0 = mn0; m1 = mn1;

        uint32_t pk[8][2];
        float sum0 = 0.f, sum1 = 0.f;
#pragma unroll
        for (int nf = 0; nf < 8; nf++) {
            float p0 = ex2(sacc[nf][0] - mn0);
            float p1 = ex2(sacc[nf][1] - mn0);
            float p2 = ex2(sacc[nf][2] - mn1);
            float p3 = ex2(sacc[nf][3] - mn1);
            sum0 += p0 + p1; sum1 += p2 + p3;
            pk[nf][0] = packh(p0, p1);
            pk[nf][1] = packh(p2, p3);
            oacc[nf][0] *= corr0; oacc[nf][1] *= corr0;
            oacc[nf][2] *= corr1; oacc[nf][3] *= corr1;
        }
        sum0 += __shfl_xor_sync(0xffffffffu, sum0, 1);
        sum0 += __shfl_xor_sync(0xffffffffu, sum0, 2);
        sum1 += __shfl_xor_sync(0xffffffffu, sum1, 1);
        sum1 += __shfl_xor_sync(0xffffffffu, sum1, 2);
        l0 = l0 * corr0 + sum0;
        l1 = l1 * corr1 + sum1;

#pragma unroll
        for (int cc = 0; cc < 4; cc++) {
            uint32_t a0 = pk[2 * cc][0];
            uint32_t a1 = pk[2 * cc][1];
            uint32_t a2 = pk[2 * cc + 1][0];
            uint32_t a3 = pk[2 * cc + 1][1];
#pragma unroll
            for (int nf = 0; nf < 8; nf++) {
                uint2 vv = Vb[(((cc << 6) + nf * 8 + g) << 2) + tg];
                mma16(oacc[nf], a0, a1, a2, a3, vv.x, vv.y);
            }
        }

        if (kb < 31) {
#pragma unroll
            for (int it = 0; it < 4; it++) {
                int slot = tid + it * 256;
                Ksm[(buf ^ 1) * 1024 + slot] = kreg[it];
                Vsm[(buf ^ 1) * 1024 + slot] = vreg[it];
            }
        }
        __syncthreads();
    }

    float inv0 = 1.f / l0, inv1 = 1.f / l1;
    uint32_t* Cimg = (uint32_t*)gCs;
    const int h = bh & 15, b = bh >> 4;
#pragma unroll
    for (int nf = 0; nf < 8; nf++) {
        int cc = h * 4 + (nf >> 1);
        int p = ((nf & 1) << 2) + tg;
        int ih = ((p & 3) << 1) + (p >> 2);
        size_t baseA = ((size_t)cc * 4096 + b * 2048 + q0 + rA) * 8;
        Cimg[baseA + ih] = packh(oacc[nf][0] * inv0, oacc[nf][1] * inv0);
        size_t baseB = ((size_t)cc * 4096 + b * 2048 + q0 + rB) * 8;
        Cimg[baseB + ih] = packh(oacc[nf][2] * inv1, oacc[nf][3] * inv1);
    }
}

// ---------------------------------------------------------------------------
// Output projection: f16 1-pass GEMM, tile 128x128 (grid 32x8 = 256 CTAs,
// 0.86 waves). SMEM 32KB (A 2x8K + B 2x8K), 2 CTAs/SM.
// ---------------------------------------------------------------------------
#define OPROJ_SMEM 32768

__global__ __launch_bounds__(256, 2) void oproj_f16(
    const float* __restrict__ bo, float* __restrict__ out)
{
    extern __shared__ char smc[];
    uint2* Ab = (uint2*)smc;                 // [2][1024]
    uint2* Bb = (uint2*)(smc + 16384);       // [2][1024]

    const int tid = threadIdx.x;
    const int lane = tid & 31;
    const int warp = tid >> 5;
    const int g = lane >> 2;
    const int tg = lane & 3;
    const int wm = (warp >> 1) * 32;
    const int wn = (warp & 1) * 64;

    const int m0 = blockIdx.x * 128;
    const int n0 = blockIdx.y * 128;

    float acc[2][8][4];
#pragma unroll
    for (int mf = 0; mf < 2; mf++)
#pragma unroll
        for (int nf = 0; nf < 8; nf++)
#pragma unroll
            for (int c = 0; c < 4; c++) acc[mf][nf][c] = 0.f;

    uint2 ar[4], br[4];
    auto ldg = [&](int kc) {
        int cc0 = kc * 2;
#pragma unroll
        for (int it = 0; it < 4; it++) {
            int slot = tid + it * 256;
            int cc = slot >> 9;
            int row = (slot >> 2) & 127;
            int j = slot & 3;
            ar[it] = gCs[(((size_t)(cc0 + cc) * 4096) + m0 + row) * 4 + j];
            br[it] = gWos[(((size_t)(cc0 + cc) * 1024) + n0 + row) * 4 + j];
        }
    };
    auto sts = [&](int buf) {
#pragma unroll
        for (int it = 0; it < 4; it++) {
            int slot = tid + it * 256;
            Ab[buf * 1024 + slot] = ar[it];
            Bb[buf * 1024 + slot] = br[it];
        }
    };

    ldg(0);
    sts(0);
    __syncthreads();

    for (int kc = 0; kc < 32; kc++) {
        const int buf = kc & 1;
        if (kc < 31) ldg(kc + 1);

#pragma unroll
        for (int cc = 0; cc < 2; cc++) {
            const uint2* Ac = Ab + buf * 1024 + cc * 512;
            const uint2* Bc = Bb + buf * 1024 + cc * 512;
            uint2 au0 = Ac[(wm + g) * 4 + tg];
            uint2 av0 = Ac[(wm + g + 8) * 4 + tg];
            uint2 au1 = Ac[(wm + 16 + g) * 4 + tg];
            uint2 av1 = Ac[(wm + 16 + g + 8) * 4 + tg];
            uint2 bv2[8];
#pragma unroll
            for (int nf = 0; nf < 8; nf++)
                bv2[nf] = Bc[(wn + nf * 8 + g) * 4 + tg];
#pragma unroll
            for (int nf = 0; nf < 8; nf++) {
                mma16(acc[0][nf], au0.x, av0.x, au0.y, av0.y, bv2[nf].x, bv2[nf].y);
                mma16(acc[1][nf], au1.x, av1.x, au1.y, av1.y, bv2[nf].x, bv2[nf].y);
            }
        }
        if (kc < 31) sts(buf ^ 1);
        __syncthreads();
    }

    const float* bi = bo + n0;
#pragma unroll
    for (int mf = 0; mf < 2; mf++) {
#pragma unroll
        for (int nf = 0; nf < 8; nf++) {
            int col = wn + nf * 8 + 2 * tg;
            float bx = bi[col], by = bi[col + 1];
            int r0 = wm + mf * 16 + g;
            *(float2*)(out + (size_t)(m0 + r0) * E_ + n0 + col) =
                make_float2(acc[mf][nf][0] + bx, acc[mf][nf][1] + by);
            *(float2*)(out + (size_t)(m0 + r0 + 8) * E_ + n0 + col) =
                make_float2(acc[mf][nf][2] + bx, acc[mf][nf][3] + by);
        }
    }
}

// ---------------------------------------------------------------------------
extern "C" void kernel_launch(void* const* d_in, const int* in_sizes, int n_in,
                              void* d_out, int out_size)
{
    const float* q  = (const float*)d_in[0];
    const float* k  = (const float*)d_in[1];
    const float* v  = (const float*)d_in[2];
    const float* Wq = (const float*)d_in[3];
    const float* Wk = (const float*)d_in[4];
    const float* Wv = (const float*)d_in[5];
    const float* bq = (const float*)d_in[6];
    const float* bk = (const float*)d_in[7];
    const float* bv = (const float*)d_in[8];
    const float* Wo = (const float*)d_in[9];
    const float* bo = (const float*)d_in[10];
    float* out = (float*)d_out;

    cudaFuncSetAttribute(proj_all, cudaFuncAttributeMaxDynamicSharedMemorySize, PROJ_SMEM);
    cudaFuncSetAttribute(oproj_f16, cudaFuncAttributeMaxDynamicSharedMemorySize, OPROJ_SMEM);
    cudaFuncSetAttribute(attn_kernel, cudaFuncAttributeMaxDynamicSharedMemorySize, ATT_SMEM);

    split_all<<<16384, 256>>>(q, k, v, Wq, Wk, Wv, Wo);
    proj_all<<<dim3(S_ / 128, BH_, 3), 256, PROJ_SMEM>>>(bq, bk, bv);
    attn_kernel<<<dim3(S_ / 128, BH_), 256, ATT_SMEM>>>();
    oproj_f16<<<dim3((B_ * S_) / 128, E_ / 128), 256, OPROJ_SMEM>>>(bo, out);
}